// round 12
// baseline (speedup 1.0000x reference)
#include <cuda_runtime.h>
#include <cuda_bf16.h>
#include <math.h>
#include <stdint.h>
#include <float.h>

#define BATCH 8
#define S0    2048
#define DMODEL 512
#define NH    8
#define HD    64
#define DFF   2048
#define ELAY  3
#define NCOUT 7
#define UMAX  24
#define QS    1536   // packed qkv row stride
#define ASPL  4      // attention KV splits (round-9 proven)

// ------------------------- scratch (device globals) --------------------------
__device__ float g_x  [BATCH*S0*DMODEL];
__device__ float g_t2 [BATCH*S0*DMODEL];
__device__ float g_qkv[BATCH*S0*QS];
__device__ float g_M  [BATCH*NH*S0];
__device__ int   g_top[BATCH*NH*UMAX];
__device__ float g_vme[BATCH*NH*HD];
__device__ float g_upd[BATCH*NH*UMAX*HD];
__device__ float g_updp[BATCH*NH*ASPL*UMAX*HD];
__device__ float g_mlp [BATCH*NH*ASPL*2*UMAX];
__device__ float g_vsp [BATCH*NH*ASPL*HD];
__device__ float g_bnp[64*DMODEL*2];
__device__ float g_bns[DMODEL*2];
__device__ float g_bqkv[QS];
__device__ __nv_bfloat16 g_xh [BATCH*S0*DMODEL];
__device__ __nv_bfloat16 g_xl [BATCH*S0*DMODEL];
__device__ __nv_bfloat16 g_ch [BATCH*S0*DMODEL];
__device__ __nv_bfloat16 g_cl [BATCH*S0*DMODEL];
__device__ __nv_bfloat16 g_ffh[BATCH*S0*DFF];
__device__ __nv_bfloat16 g_ffl[BATCH*S0*DFF];
__device__ __nv_bfloat16 g_wh [DFF*DMODEL];
__device__ __nv_bfloat16 g_wl [DFF*DMODEL];

// ------------------------- threefry2x32 --------------------------------------
__host__ __device__ __forceinline__ void tf_round(uint32_t& x0, uint32_t& x1, int r) {
    x0 += x1; x1 = (x1 << r) | (x1 >> (32 - r)); x1 ^= x0;
}
__host__ __device__ inline void threefry2x32(uint32_t k0, uint32_t k1,
                                             uint32_t c0, uint32_t c1,
                                             uint32_t& o0, uint32_t& o1) {
    uint32_t ks2 = k0 ^ k1 ^ 0x1BD11BDAu;
    uint32_t x0 = c0 + k0, x1 = c1 + k1;
    tf_round(x0,x1,13); tf_round(x0,x1,15); tf_round(x0,x1,26); tf_round(x0,x1,6);
    x0 += k1;  x1 += ks2 + 1u;
    tf_round(x0,x1,17); tf_round(x0,x1,29); tf_round(x0,x1,16); tf_round(x0,x1,24);
    x0 += ks2; x1 += k0 + 2u;
    tf_round(x0,x1,13); tf_round(x0,x1,15); tf_round(x0,x1,26); tf_round(x0,x1,6);
    x0 += k0;  x1 += k1 + 3u;
    tf_round(x0,x1,17); tf_round(x0,x1,29); tf_round(x0,x1,16); tf_round(x0,x1,24);
    x0 += k1;  x1 += ks2 + 4u;
    tf_round(x0,x1,13); tf_round(x0,x1,15); tf_round(x0,x1,26); tf_round(x0,x1,6);
    x0 += ks2; x1 += k0 + 5u;
    o0 = x0; o1 = x1;
}

// ------------------------- split helpers -------------------------------------
__device__ __forceinline__ void split_bf16(float v, __nv_bfloat16& h, __nv_bfloat16& l) {
    h = __float2bfloat16(v);
    l = __float2bfloat16(v - __bfloat162float(h));
}
__global__ void cvt_split(const float* __restrict__ x, __nv_bfloat16* __restrict__ h,
                          __nv_bfloat16* __restrict__ l, int n) {
    int i = blockIdx.x * 256 + threadIdx.x;
    if (i >= n) return;
    split_bf16(x[i], h[i], l[i]);
}
// fused: QKV weight split + bias concat
__global__ void cvt_qkv(const float* __restrict__ Wq, const float* __restrict__ Wk,
                        const float* __restrict__ Wv, __nv_bfloat16* __restrict__ h,
                        __nv_bfloat16* __restrict__ l,
                        const float* __restrict__ bq, const float* __restrict__ bk,
                        const float* __restrict__ bv, float* __restrict__ bdst) {
    int i = blockIdx.x * 256 + threadIdx.x;
    if (i < QS)
        bdst[i] = (i < DMODEL) ? bq[i] : (i < 2 * DMODEL) ? bk[i - DMODEL] : bv[i - 2 * DMODEL];
    if (i >= 3 * DMODEL * DMODEL) return;
    int r = i / DMODEL, c = i - r * DMODEL;
    const float* W = (r < DMODEL) ? Wq : (r < 2 * DMODEL) ? Wk : Wv;
    int rr = r & (DMODEL - 1);
    split_bf16(W[rr * DMODEL + c], h[i], l[i]);
}
__global__ void cvt_dconv(const float* __restrict__ w, __nv_bfloat16* __restrict__ h,
                          __nv_bfloat16* __restrict__ l) {
    int i = blockIdx.x * 256 + threadIdx.x;
    if (i >= 3 * DMODEL * DMODEL) return;
    int tap = i / (DMODEL * DMODEL);
    int r = i - tap * DMODEL * DMODEL;
    split_bf16(w[(size_t)r * 3 + tap], h[i], l[i]);
}

// ------------------------- mma.sync GEMM (frozen round-9 config) -------------
#define GF_GELU   1
#define GF_RES    2
#define GF_CIRC   8
#define GF_WRF    32
#define GF_SPLIT  64

#define BM 128
#define BN 128
#define BK 32
#define SSTRIDE 40
#define TSZ (128 * SSTRIDE * 2)
#define STAGE_BYTES (4 * TSZ)
#define GSMEM (2 * STAGE_BYTES)

__device__ __forceinline__ void load_chunk2(
    const __nv_bfloat16* __restrict__ Ah, const __nv_bfloat16* __restrict__ Al,
    const __nv_bfloat16* __restrict__ Bh, const __nv_bfloat16* __restrict__ Bl,
    char* dynsm, int buf, int c, int nkc, int K, int N,
    int m0, int n0, int flags, int Lb, int tid)
{
    int tap = c / nkc;
    int kc = c - tap * nkc;
    int k0 = kc * BK;
    int shift = (flags & GF_CIRC) ? (tap - 1) : 0;
    char* st = dynsm + buf * STAGE_BYTES;
    const __nv_bfloat16* Bht = Bh + (size_t)tap * N * K;
    const __nv_bfloat16* Blt = Bl + (size_t)tap * N * K;
    #pragma unroll 2
    for (int i = tid; i < 512; i += 256) {
        int row = i >> 2, seg = i & 3;
        int gm = m0 + row, arow = gm;
        if (flags & GF_CIRC) {
            int b = gm / Lb, t = gm - b * Lb + shift;
            if (t < 0) t += Lb; else if (t >= Lb) t -= Lb;
            arow = b * Lb + t;
        }
        size_t so = (size_t)arow * K + k0 + seg * 8;
        uint32_t d = (uint32_t)__cvta_generic_to_shared(st + row * (SSTRIDE * 2) + seg * 16);
        asm volatile("cp.async.cg.shared.global [%0], [%1], 16;" :: "r"(d), "l"(Ah + so));
        asm volatile("cp.async.cg.shared.global [%0], [%1], 16;" :: "r"(d + TSZ), "l"(Al + so));
    }
    #pragma unroll 2
    for (int i = tid; i < 512; i += 256) {
        int row = i >> 2, seg = i & 3;
        size_t so = (size_t)(n0 + row) * K + k0 + seg * 8;
        uint32_t d = (uint32_t)__cvta_generic_to_shared(st + 2 * TSZ + row * (SSTRIDE * 2) + seg * 16);
        asm volatile("cp.async.cg.shared.global [%0], [%1], 16;" :: "r"(d), "l"(Bht + so));
        asm volatile("cp.async.cg.shared.global [%0], [%1], 16;" :: "r"(d + TSZ), "l"(Blt + so));
    }
    asm volatile("cp.async.commit_group;");
}

__global__ __launch_bounds__(256)
void mma_gemm(const __nv_bfloat16* __restrict__ Ah, const __nv_bfloat16* __restrict__ Al,
              const __nv_bfloat16* __restrict__ Bh, const __nv_bfloat16* __restrict__ Bl,
              const float* __restrict__ bias, const float* __restrict__ R,
              float* __restrict__ C, __nv_bfloat16* __restrict__ Ch, __nv_bfloat16* __restrict__ Cl,
              int M, int N, int K, int flags, int ntaps, int Lb)
{
    extern __shared__ __align__(16) char dynsm[];
    int tid = threadIdx.x, lane = tid & 31, wid = tid >> 5;
    int warp_m = wid & 1, warp_n = wid >> 1;
    int m0 = blockIdx.y * BM, n0 = blockIdx.x * BN;

    float acc[4][4][4];
    #pragma unroll
    for (int mi = 0; mi < 4; mi++)
        #pragma unroll
        for (int ni = 0; ni < 4; ni++)
            #pragma unroll
            for (int e = 0; e < 4; e++) acc[mi][ni][e] = 0.f;

    const int nkc = K / BK;
    const int nch = nkc * ntaps;

    load_chunk2(Ah, Al, Bh, Bl, dynsm, 0, 0, nkc, K, N, m0, n0, flags, Lb, tid);

    uint32_t smb = (uint32_t)__cvta_generic_to_shared(dynsm);
    int a_row = warp_m * 64 + (lane & 15);
    int a_col = (lane >> 4) * 8;
    int b_row = warp_n * 32 + (lane & 7) + ((lane >> 4) * 8);
    int b_col = ((lane >> 3) & 1) * 8;

    for (int c = 0; c < nch; c++) {
        if (c + 1 < nch) {
            load_chunk2(Ah, Al, Bh, Bl, dynsm, (c + 1) & 1, c + 1, nkc, K, N, m0, n0, flags, Lb, tid);
            asm volatile("cp.async.wait_group 1;");
        } else {
            asm volatile("cp.async.wait_group 0;");
        }
        __syncthreads();
        uint32_t ab = smb + (c & 1) * STAGE_BYTES;
        #pragma unroll
        for (int ks = 0; ks < 2; ks++) {
            uint32_t ah[4][4], al[4][4];
            #pragma unroll
            for (int mi = 0; mi < 4; mi++) {
                uint32_t addr = ab + ((a_row + mi * 16) * SSTRIDE + ks * 16 + a_col) * 2;
                asm volatile("ldmatrix.sync.aligned.m8n8.x4.shared.b16 {%0,%1,%2,%3}, [%4];"
                    : "=r"(ah[mi][0]), "=r"(ah[mi][1]), "=r"(ah[mi][2]), "=r"(ah[mi][3]) : "r"(addr));
                asm volatile("ldmatrix.sync.aligned.m8n8.x4.shared.b16 {%0,%1,%2,%3}, [%4];"
                    : "=r"(al[mi][0]), "=r"(al[mi][1]), "=r"(al[mi][2]), "=r"(al[mi][3]) : "r"(addr + TSZ));
            }
            uint32_t bh[4][2], bl[4][2];
            #pragma unroll
            for (int nf2 = 0; nf2 < 2; nf2++) {
                uint32_t r0, r1, r2, r3;
                uint32_t addr = ab + 2 * TSZ + ((b_row + nf2 * 16) * SSTRIDE + ks * 16 + b_col) * 2;
                asm volatile("ldmatrix.sync.aligned.m8n8.x4.shared.b16 {%0,%1,%2,%3}, [%4];"
                    : "=r"(r0), "=r"(r1), "=r"(r2), "=r"(r3) : "r"(addr));
                bh[nf2 * 2][0] = r0;     bh[nf2 * 2][1] = r1;
                bh[nf2 * 2 + 1][0] = r2; bh[nf2 * 2 + 1][1] = r3;
                asm volatile("ldmatrix.sync.aligned.m8n8.x4.shared.b16 {%0,%1,%2,%3}, [%4];"
                    : "=r"(r0), "=r"(r1), "=r"(r2), "=r"(r3) : "r"(addr + TSZ));
                bl[nf2 * 2][0] = r0;     bl[nf2 * 2][1] = r1;
                bl[nf2 * 2 + 1][0] = r2; bl[nf2 * 2 + 1][1] = r3;
            }
            #pragma unroll
            for (int mi = 0; mi < 4; mi++)
                #pragma unroll
                for (int ni = 0; ni < 4; ni++)
                    asm volatile("mma.sync.aligned.m16n8k16.row.col.f32.bf16.bf16.f32 "
                        "{%0,%1,%2,%3}, {%4,%5,%6,%7}, {%8,%9}, {%0,%1,%2,%3};"
                        : "+f"(acc[mi][ni][0]), "+f"(acc[mi][ni][1]), "+f"(acc[mi][ni][2]), "+f"(acc[mi][ni][3])
                        : "r"(ah[mi][0]), "r"(ah[mi][1]), "r"(ah[mi][2]), "r"(ah[mi][3]),
                          "r"(bh[ni][0]), "r"(bh[ni][1]));
            #pragma unroll
            for (int mi = 0; mi < 4; mi++)
                #pragma unroll
                for (int ni = 0; ni < 4; ni++)
                    asm volatile("mma.sync.aligned.m16n8k16.row.col.f32.bf16.bf16.f32 "
                        "{%0,%1,%2,%3}, {%4,%5,%6,%7}, {%8,%9}, {%0,%1,%2,%3};"
                        : "+f"(acc[mi][ni][0]), "+f"(acc[mi][ni][1]), "+f"(acc[mi][ni][2]), "+f"(acc[mi][ni][3])
                        : "r"(ah[mi][0]), "r"(ah[mi][1]), "r"(ah[mi][2]), "r"(ah[mi][3]),
                          "r"(bl[ni][0]), "r"(bl[ni][1]));
            #pragma unroll
            for (int mi = 0; mi < 4; mi++)
                #pragma unroll
                for (int ni = 0; ni < 4; ni++)
                    asm volatile("mma.sync.aligned.m16n8k16.row.col.f32.bf16.bf16.f32 "
                        "{%0,%1,%2,%3}, {%4,%5,%6,%7}, {%8,%9}, {%0,%1,%2,%3};"
                        : "+f"(acc[mi][ni][0]), "+f"(acc[mi][ni][1]), "+f"(acc[mi][ni][2]), "+f"(acc[mi][ni][3])
                        : "r"(al[mi][0]), "r"(al[mi][1]), "r"(al[mi][2]), "r"(al[mi][3]),
                          "r"(bh[ni][0]), "r"(bh[ni][1]));
        }
        __syncthreads();
    }

    // epilogue
    #pragma unroll
    for (int mi = 0; mi < 4; mi++) {
        #pragma unroll
        for (int ni = 0; ni < 4; ni++) {
            int gm0 = m0 + warp_m * 64 + mi * 16 + (lane >> 2);
            int gn  = n0 + warp_n * 32 + ni * 8 + (lane & 3) * 2;
            float2 bs = *(const float2*)&bias[gn];
            #pragma unroll
            for (int h = 0; h < 2; h++) {
                int gm = gm0 + h * 8;
                float2 v = make_float2(acc[mi][ni][h * 2], acc[mi][ni][h * 2 + 1]);
                v.x += bs.x; v.y += bs.y;
                if (flags & GF_GELU) {
                    v.x = 0.5f * v.x * (1.0f + erff(v.x * 0.7071067811865475f));
                    v.y = 0.5f * v.y * (1.0f + erff(v.y * 0.7071067811865475f));
                }
                if (flags & GF_RES) {
                    float2 rv = *(const float2*)&R[(size_t)gm * N + gn];
                    v.x += rv.x; v.y += rv.y;
                }
                if (flags & GF_WRF) *(float2*)&C[(size_t)gm * N + gn] = v;
                if (flags & GF_SPLIT) {
                    __nv_bfloat16 h0, l0, h1, l1;
                    split_bf16(v.x, h0, l0); split_bf16(v.y, h1, l1);
                    __nv_bfloat162 hv; hv.x = h0; hv.y = h1;
                    __nv_bfloat162 lv; lv.x = l0; lv.y = l1;
                    *(__nv_bfloat162*)&Ch[(size_t)gm * N + gn] = hv;
                    *(__nv_bfloat162*)&Cl[(size_t)gm * N + gn] = lv;
                }
            }
        }
    }
}

// ------------------------- token conv + positional embedding -----------------
__global__ void tok_conv_kernel(const float* __restrict__ xe, const float* __restrict__ w,
                                float* __restrict__ out, __nv_bfloat16* __restrict__ oh,
                                __nv_bfloat16* __restrict__ ol) {
    int t = blockIdx.x;
    __shared__ float xs[BATCH][21];
    int tid = threadIdx.x;
    for (int j = tid; j < BATCH * 21; j += 128) {
        int b = j / 21, jj = j % 21;
        int kk = jj / 7, i = jj % 7;
        int tt = t + kk - 1;
        if (tt < 0) tt += S0; else if (tt >= S0) tt -= S0;
        xs[b][kk * 7 + i] = xe[(size_t)(b * S0 + tt) * 7 + i];
    }
    __syncthreads();
    for (int o = tid; o < DMODEL; o += 128) {
        float wreg[21];
        const float* wo = w + o * 21;
        #pragma unroll
        for (int j = 0; j < 21; j++) wreg[j] = wo[j];
        int e = o & ~1;
        float dv = expf((float)e * -0.017988946038918563f);
        float ang = (float)t * dv;
        float pe = (o & 1) ? cosf(ang) : sinf(ang);
        #pragma unroll
        for (int b = 0; b < BATCH; b++) {
            float acc = pe;
            #pragma unroll
            for (int i = 0; i < 7; i++)
                #pragma unroll
                for (int kk = 0; kk < 3; kk++) acc += xs[b][kk * 7 + i] * wreg[i * 3 + kk];
            size_t oi = (size_t)(b * S0 + t) * DMODEL + o;
            out[oi] = acc;
            split_bf16(acc, oh[oi], ol[oi]);
        }
    }
}

// ------------------------- ProbSparse attention (packed qkv) -----------------
__global__ void m_kernel(const float* __restrict__ qkv, uint32_t ka, uint32_t kb,
                         float* __restrict__ Mo, int L, int U) {
    int gw = blockIdx.x * 8 + (threadIdx.x >> 5);
    int lane = threadIdx.x & 31;
    int b = gw / (NH * L);
    int h = (gw / L) % NH;
    int l = gw % L;
    int j = l * U + (lane < U ? lane : U - 1);
    uint32_t o0, o1;
    threefry2x32(ka, kb, 0u, (uint32_t)j, o0, o1);
    int kr = (int)((o0 ^ o1) & (uint32_t)(L - 1));
    const float4* qp = (const float4*)&qkv[(size_t)(b * L + l) * QS + h * HD];
    const float4* kp = (const float4*)&qkv[(size_t)(b * L + kr) * QS + DMODEL + h * HD];
    float acc = 0.f;
    #pragma unroll
    for (int jj = 0; jj < 16; jj++) {
        float4 qv = qp[jj], kv = kp[jj];
        acc += qv.x * kv.x + qv.y * kv.y + qv.z * kv.z + qv.w * kv.w;
    }
    float mx = (lane < U) ? acc : -FLT_MAX;
    float sm = (lane < U) ? acc : 0.f;
    #pragma unroll
    for (int off = 16; off; off >>= 1) {
        mx = fmaxf(mx, __shfl_xor_sync(0xffffffffu, mx, off));
        sm += __shfl_xor_sync(0xffffffffu, sm, off);
    }
    if (lane == 0) Mo[(b * NH + h) * L + l] = mx - sm / (float)L;
}

__global__ void topk_kernel(const float* __restrict__ Mi, int* __restrict__ top,
                            int L, int u) {
    int bh = blockIdx.x, tid = threadIdx.x;
    int lane = tid & 31, warp = tid >> 5;
    __shared__ float sv[S0];
    __shared__ float wv[32];
    __shared__ int   wi[32];
    const float* m = Mi + (size_t)bh * L;
    for (int i = tid; i < L; i += 1024) sv[i] = m[i];
    __syncthreads();
    for (int it = 0; it < u; it++) {
        float best = -FLT_MAX; int besti = L;
        for (int i = tid; i < L; i += 1024) {
            float v = sv[i];
            if (v > best) { best = v; besti = i; }
        }
        #pragma unroll
        for (int off = 16; off; off >>= 1) {
            float ov = __shfl_xor_sync(0xffffffffu, best, off);
            int   oi = __shfl_xor_sync(0xffffffffu, besti, off);
            if (ov > best || (ov == best && oi < besti)) { best = ov; besti = oi; }
        }
        if (lane == 0) { wv[warp] = best; wi[warp] = besti; }
        __syncthreads();
        if (warp == 0) {
            best = wv[lane]; besti = wi[lane];
            #pragma unroll
            for (int off = 16; off; off >>= 1) {
                float ov = __shfl_xor_sync(0xffffffffu, best, off);
                int   oi = __shfl_xor_sync(0xffffffffu, besti, off);
                if (ov > best || (ov == best && oi < besti)) { best = ov; besti = oi; }
            }
            if (lane == 0) { top[bh * u + it] = besti; sv[besti] = -FLT_MAX; }
        }
        __syncthreads();
    }
}

// ------------------------- split-KV flash attention + vmean ------------------
#define ATK 128
#define KSTR 68
#define ASM_FLOATS (2*ATK*KSTR + UMAX*ATK + 2*UMAX*HD + 2*UMAX + HD)
#define ASM_BYTES (ASM_FLOATS * 4)

__global__ void attn_kernel(const float* __restrict__ qkv, const int* __restrict__ top,
                            float* __restrict__ updp, float* __restrict__ mlp,
                            float* __restrict__ vsp, int L, int u) {
    extern __shared__ float sm[];
    float* Kt   = sm;
    float* Vt   = Kt + ATK * KSTR;
    float* sc   = Vt + ATK * KSTR;
    float* qs   = sc + UMAX * ATK;
    float* accs = qs + UMAX * HD;
    float* mst  = accs + UMAX * HD;
    float* lst  = mst + UMAX;
    float* vsum = lst + UMAX;
    int h = blockIdx.x, b = blockIdx.y, z = blockIdx.z;
    int bh = b * NH + h;
    int bhz = bh * ASPL + z;
    int Lc = L / ASPL;
    int tbase = z * Lc;
    int tid = threadIdx.x, lane = tid & 31, warp = tid >> 5;

    for (int i = tid; i < u * HD; i += 256) {
        int q = i >> 6, d = i & 63;
        int qrow = top[bh * u + q];
        qs[q * HD + d] = qkv[(size_t)(b * L + qrow) * QS + h * HD + d];
        accs[i] = 0.f;
    }
    if (tid < UMAX) { mst[tid] = -FLT_MAX; lst[tid] = 0.f; }
    if (tid < HD) vsum[tid] = 0.f;
    __syncthreads();

    for (int t0 = tbase; t0 < tbase + Lc; t0 += ATK) {
        for (int i = tid; i < ATK * 16; i += 256) {
            int row = i >> 4, seg = i & 15;
            const float* base = &qkv[(size_t)(b * L + t0 + row) * QS + DMODEL + h * HD + seg * 4];
            *(float4*)&Kt[row * KSTR + seg * 4] = *(const float4*)base;
            *(float4*)&Vt[row * KSTR + seg * 4] = *(const float4*)(base + DMODEL);
        }
        __syncthreads();
        if (tid < HD) {
            float s = 0.f;
            for (int k = 0; k < ATK; k++) s += Vt[k * KSTR + tid];
            vsum[tid] += s;
        }
        for (int i = tid; i < u * ATK; i += 256) {
            int q = i >> 7, k = i & (ATK - 1);
            const float* qp = &qs[q * HD];
            const float* kp = &Kt[k * KSTR];
            float acc = 0.f;
            #pragma unroll
            for (int d4 = 0; d4 < 16; d4++) {
                float4 a = *(const float4*)&qp[d4 * 4];
                float4 c = *(const float4*)&kp[d4 * 4];
                acc += a.x * c.x + a.y * c.y + a.z * c.z + a.w * c.w;
            }
            sc[q * ATK + k] = acc * 0.125f;
        }
        __syncthreads();
        #pragma unroll
        for (int qi = 0; qi < 3; qi++) {
            int q = warp * 3 + qi;
            if (q < u) {
                float s0 = sc[q * ATK + lane],      s1 = sc[q * ATK + 32 + lane];
                float s2 = sc[q * ATK + 64 + lane], s3 = sc[q * ATK + 96 + lane];
                float tm = fmaxf(fmaxf(s0, s1), fmaxf(s2, s3));
                #pragma unroll
                for (int off = 16; off; off >>= 1)
                    tm = fmaxf(tm, __shfl_xor_sync(0xffffffffu, tm, off));
                float mold = mst[q];
                float newm = fmaxf(mold, tm);
                float alpha = expf(mold - newm);
                float p0 = expf(s0 - newm), p1 = expf(s1 - newm);
                float p2 = expf(s2 - newm), p3 = expf(s3 - newm);
                sc[q * ATK + lane] = p0;      sc[q * ATK + 32 + lane] = p1;
                sc[q * ATK + 64 + lane] = p2; sc[q * ATK + 96 + lane] = p3;
                float ls = p0 + p1 + p2 + p3;
                #pragma unroll
                for (int off = 16; off; off >>= 1)
                    ls += __shfl_xor_sync(0xffffffffu, ls, off);
                if (lane == 0) { lst[q] = lst[q] * alpha + ls; mst[q] = newm; }
                __syncwarp();
                #pragma unroll
                for (int dd = 0; dd < 2; dd++) {
                    int d = lane + dd * 32;
                    float a = accs[q * HD + d] * alpha;
                    for (int k = 0; k < ATK; k++)
                        a += sc[q * ATK + k] * Vt[k * KSTR + d];
                    accs[q * HD + d] = a;
                }
            }
        }
        __syncthreads();
    }
    #pragma unroll
    for (int qi = 0; qi < 3; qi++) {
        int q = warp * 3 + qi;
        if (q < u) {
            updp[((size_t)bhz * UMAX + q) * HD + lane]      = accs[q * HD + lane];
            updp[((size_t)bhz * UMAX + q) * HD + lane + 32] = accs[q * HD + lane + 32];
            if (lane == 0) {
                mlp[bhz * 2 * UMAX + q]        = mst[q];
                mlp[bhz * 2 * UMAX + UMAX + q] = lst[q];
            }
        }
    }
    if (tid < HD) vsp[bhz * HD + tid] = vsum[tid];
}

__global__ void attn_merge_kernel(const float* __restrict__ updp, const float* __restrict__ mlp,
                                  const float* __restrict__ vsp, float* __restrict__ upd,
                                  float* __restrict__ vme, int L, int u) {
    int bh = blockIdx.x, tid = threadIdx.x;
    for (int i = tid; i < u * HD; i += 256) {
        int q = i >> 6, d = i & 63;
        float M = -FLT_MAX;
        #pragma unroll
        for (int z = 0; z < ASPL; z++)
            M = fmaxf(M, mlp[(bh * ASPL + z) * 2 * UMAX + q]);
        float lsum = 0.f, asum = 0.f;
        #pragma unroll
        for (int z = 0; z < ASPL; z++) {
            int bhz = bh * ASPL + z;
            float w = expf(mlp[bhz * 2 * UMAX + q] - M);
            lsum += mlp[bhz * 2 * UMAX + UMAX + q] * w;
            asum += updp[((size_t)bhz * UMAX + q) * HD + d] * w;
        }
        upd[((size_t)bh * u + q) * HD + d] = asum / lsum;
    }
    if (tid < HD) {
        float s = 0.f;
        #pragma unroll
        for (int z = 0; z < ASPL; z++) s += vsp[(bh * ASPL + z) * HD + tid];
        vme[bh * HD + tid] = s / (float)L;
    }
}

__global__ void assemble_ctx_kernel(const float* __restrict__ vm,
                                    __nv_bfloat16* __restrict__ ch, __nv_bfloat16* __restrict__ cl,
                                    int L) {
    int i = blockIdx.x * blockDim.x + threadIdx.x;
    int total = BATCH * L * DMODEL;
    if (i >= total) return;
    int b = i / (L * DMODEL);
    int r = i - b * L * DMODEL;
    int c = r % DMODEL;
    int h = c / HD, d = c - h * HD;
    float val = vm[(b * NH + h) * HD + d];
    split_bf16(val, ch[i], cl[i]);
}
__global__ void scatter_upd_kernel(const int* __restrict__ top, const float* __restrict__ upd,
                                   __nv_bfloat16* __restrict__ ch, __nv_bfloat16* __restrict__ cl,
                                   int L, int u) {
    int i = blockIdx.x * blockDim.x + threadIdx.x;
    if (i >= BATCH * NH * u * HD) return;
    int d = i & 63;
    int r = i >> 6;
    int q = r % u;
    int bh = r / u;
    int b = bh / NH, h = bh % NH;
    int l = top[bh * u + q];
    float val = upd[((size_t)bh * u + q) * HD + d];
    size_t o = ((size_t)(b * L + l)) * DMODEL + h * HD + d;
    __nv_bfloat16 hi, lo;
    split_bf16(val, hi, lo);
    ch[o] = hi; cl[o] = lo;
}

// ------------------------- layernorm (out may be null: split-only) ----------
__global__ void layernorm_kernel(const float* __restrict__ in, const float* __restrict__ g,
                                 const float* __restrict__ bb, float* __restrict__ out,
                                 __nv_bfloat16* __restrict__ oh, __nv_bfloat16* __restrict__ ol) {
    int row = blockIdx.x, tid = threadIdx.x;
    __shared__ float red[128];
    const float4 v = ((const float4*)(in + (size_t)row * DMODEL))[tid];
    red[tid] = v.x + v.y + v.z + v.w;
    __syncthreads();
    for (int s = 64; s > 0; s >>= 1) { if (tid < s) red[tid] += red[tid + s]; __syncthreads(); }
    float mean = red[0] / (float)DMODEL;
    __syncthreads();
    float dx = v.x - mean, dy = v.y - mean, dz = v.z - mean, dw = v.w - mean;
    red[tid] = dx * dx + dy * dy + dz * dz + dw * dw;
    __syncthreads();
    for (int s = 64; s > 0; s >>= 1) { if (tid < s) red[tid] += red[tid + s]; __syncthreads(); }
    float rstd = rsqrtf(red[0] / (float)DMODEL + 1e-5f);
    const float4 gv = ((const float4*)g)[tid];
    const float4 bv = ((const float4*)bb)[tid];
    float4 o;
    o.x = dx * rstd * gv.x + bv.x;
    o.y = dy * rstd * gv.y + bv.y;
    o.z = dz * rstd * gv.z + bv.z;
    o.w = dw * rstd * gv.w + bv.w;
    if (out) ((float4*)(out + (size_t)row * DMODEL))[tid] = o;
    if (oh) {
        size_t base = (size_t)row * DMODEL + tid * 4;
        split_bf16(o.x, oh[base],   ol[base]);
        split_bf16(o.y, oh[base+1], ol[base+1]);
        split_bf16(o.z, oh[base+2], ol[base+2]);
        split_bf16(o.w, oh[base+3], ol[base+3]);
    }
}

// ------------------------- distil helpers ------------------------------------
__global__ void bn_partial_kernel(const float* __restrict__ y, float* __restrict__ part, int rpc) {
    int chunk = blockIdx.x, c = threadIdx.x;
    float s = 0.f, ss = 0.f;
    for (int r = 0; r < rpc; r++) {
        float vv = y[(size_t)(chunk * rpc + r) * DMODEL + c];
        s += vv; ss += vv * vv;
    }
    part[(size_t)chunk * (2 * DMODEL) + c] = s;
    part[(size_t)chunk * (2 * DMODEL) + DMODEL + c] = ss;
}
__global__ void bn_final_kernel(const float* __restrict__ part, float* __restrict__ stat,
                                int Mtot) {
    int c = threadIdx.x;
    float s = 0.f, ss = 0.f;
    #pragma unroll 8
    for (int ch = 0; ch < 64; ch++) {
        s  += part[(size_t)ch * (2 * DMODEL) + c];
        ss += part[(size_t)ch * (2 * DMODEL) + DMODEL + c];
    }
    float mu = s / (float)Mtot;
    stat[c] = mu;
    stat[DMODEL + c] = ss / (float)Mtot - mu * mu;
}
__global__ void bn_elu_maxpool_kernel(const float* __restrict__ y, const float* __restrict__ stat,
                                      const float* __restrict__ g, const float* __restrict__ bb,
                                      float* __restrict__ out,
                                      __nv_bfloat16* __restrict__ oh, __nv_bfloat16* __restrict__ ol,
                                      int L) {
    int Lo = L / 2;
    int i = blockIdx.x * blockDim.x + threadIdx.x;
    int total = BATCH * Lo * DMODEL;
    if (i >= total) return;
    int b = i / (Lo * DMODEL);
    int r = i - b * Lo * DMODEL;
    int t = r / DMODEL;
    int c = r - t * DMODEL;
    float mu = stat[c];
    float rstd = rsqrtf(stat[DMODEL + c] + 1e-5f);
    float gc = g[c], bc = bb[c];
    float m = -FLT_MAX;
    #pragma unroll
    for (int dt = -1; dt <= 1; dt++) {
        int tt = 2 * t + dt;
        if (tt >= 0 && tt < L) {
            float z = (y[(size_t)(b * L + tt) * DMODEL + c] - mu) * rstd * gc + bc;
            z = z > 0.f ? z : expm1f(z);
            m = fmaxf(m, z);
        }
    }
    out[i] = m;
    split_bf16(m, oh[i], ol[i]);
}

// ------------------------- head ----------------------------------------------
__global__ void head_kernel(const float* __restrict__ x, const float* __restrict__ w,
                            const float* __restrict__ eb, float* __restrict__ out, int rows) {
    int i = blockIdx.x * blockDim.x + threadIdx.x;
    if (i >= rows * NCOUT) return;
    int row = i / NCOUT, c = i - row * NCOUT;
    const float* xr = x + (size_t)row * DMODEL;
    const float* wr = w + (size_t)c * DMODEL;
    float acc = eb[c];
    for (int d = 0; d < DMODEL; d++) acc += xr[d] * wr[d];
    out[i] = acc;
}

// ------------------------- host orchestration --------------------------------
static inline void run_gemm(const __nv_bfloat16* Ah, const __nv_bfloat16* Al,
                            const __nv_bfloat16* Bh, const __nv_bfloat16* Bl,
                            const float* bias, const float* R,
                            float* C, __nv_bfloat16* Ch, __nv_bfloat16* Cl,
                            int M, int N, int K, int flags, int ntaps = 1, int Lb = 1) {
    dim3 grid(N / BN, M / BM);
    mma_gemm<<<grid, 256, GSMEM>>>(Ah, Al, Bh, Bl, bias, R, C, Ch, Cl, M, N, K, flags, ntaps, Lb);
}

extern "C" void kernel_launch(void* const* d_in, const int* in_sizes, int n_in,
                              void* d_out, int out_size) {
    (void)in_sizes; (void)n_in; (void)out_size;
    const float* x_enc   = (const float*)d_in[0];
    const float* tok_w   = (const float*)d_in[1];
    const float* Wq      = (const float*)d_in[2];
    const float* bq      = (const float*)d_in[3];
    const float* Wk      = (const float*)d_in[4];
    const float* bk      = (const float*)d_in[5];
    const float* Wv      = (const float*)d_in[6];
    const float* bv      = (const float*)d_in[7];
    const float* Wo      = (const float*)d_in[8];
    const float* bo      = (const float*)d_in[9];
    const float* conv1_w = (const float*)d_in[10];
    const float* conv1_b = (const float*)d_in[11];
    const float* conv2_w = (const float*)d_in[12];
    const float* conv2_b = (const float*)d_in[13];
    const float* ln1_g   = (const float*)d_in[14];
    const float* ln1_b   = (const float*)d_in[15];
    const float* ln2_g   = (const float*)d_in[16];
    const float* ln2_b   = (const float*)d_in[17];
    const float* dconv_w = (const float*)d_in[18];
    const float* dconv_b = (const float*)d_in[19];
    const float* bn_g    = (const float*)d_in[20];
    const float* bn_b    = (const float*)d_in[21];
    const float* lnf_g   = (const float*)d_in[22];
    const float* lnf_b   = (const float*)d_in[23];
    const float* end_w   = (const float*)d_in[24];
    const float* end_b   = (const float*)d_in[25];
    float* out = (float*)d_out;

    cudaFuncSetAttribute(mma_gemm, cudaFuncAttributeMaxDynamicSharedMemorySize, GSMEM);
    cudaFuncSetAttribute(attn_kernel, cudaFuncAttributeMaxDynamicSharedMemorySize, ASM_BYTES);

    void *p;
    cudaGetSymbolAddress(&p, g_x);    float* x    = (float*)p;
    cudaGetSymbolAddress(&p, g_t2);   float* t2   = (float*)p;
    cudaGetSymbolAddress(&p, g_qkv);  float* qkv  = (float*)p;
    cudaGetSymbolAddress(&p, g_M);    float* Mb   = (float*)p;
    cudaGetSymbolAddress(&p, g_top);  int*   top  = (int*)p;
    cudaGetSymbolAddress(&p, g_vme);  float* vme  = (float*)p;
    cudaGetSymbolAddress(&p, g_upd);  float* upd  = (float*)p;
    cudaGetSymbolAddress(&p, g_updp); float* updp = (float*)p;
    cudaGetSymbolAddress(&p, g_mlp);  float* mlp  = (float*)p;
    cudaGetSymbolAddress(&p, g_vsp);  float* vsp  = (float*)p;
    cudaGetSymbolAddress(&p, g_bnp);  float* bnp  = (float*)p;
    cudaGetSymbolAddress(&p, g_bns);  float* bns  = (float*)p;
    cudaGetSymbolAddress(&p, g_bqkv); float* bqkv = (float*)p;
    cudaGetSymbolAddress(&p, g_xh);   __nv_bfloat16* xh  = (__nv_bfloat16*)p;
    cudaGetSymbolAddress(&p, g_xl);   __nv_bfloat16* xl  = (__nv_bfloat16*)p;
    cudaGetSymbolAddress(&p, g_ch);   __nv_bfloat16* ch  = (__nv_bfloat16*)p;
    cudaGetSymbolAddress(&p, g_cl);   __nv_bfloat16* cl  = (__nv_bfloat16*)p;
    cudaGetSymbolAddress(&p, g_ffh);  __nv_bfloat16* ffh = (__nv_bfloat16*)p;
    cudaGetSymbolAddress(&p, g_ffl);  __nv_bfloat16* ffl = (__nv_bfloat16*)p;
    cudaGetSymbolAddress(&p, g_wh);   __nv_bfloat16* wh  = (__nv_bfloat16*)p;
    cudaGetSymbolAddress(&p, g_wl);   __nv_bfloat16* wl  = (__nv_bfloat16*)p;

    tok_conv_kernel<<<S0, 128>>>(x_enc, tok_w, x, xh, xl);

    int L = S0;
    for (int l = 0; l < ELAY; l++) {
        int U = (l == 0) ? 24 : 21;
        int u = U;
        int Mrows = BATCH * L;
        const float* Wq_l = Wq + (size_t)l * DMODEL * DMODEL;
        const float* Wk_l = Wk + (size_t)l * DMODEL * DMODEL;
        const float* Wv_l = Wv + (size_t)l * DMODEL * DMODEL;
        const float* Wo_l = Wo + (size_t)l * DMODEL * DMODEL;
        const float* w1_l = conv1_w + (size_t)l * DFF * DMODEL;
        const float* w2_l = conv2_w + (size_t)l * DMODEL * DFF;

        // fused QKV projection (N = 1536); weight split + bias concat fused
        cvt_qkv<<<(3 * DMODEL * DMODEL + 255) / 256, 256>>>(
            Wq_l, Wk_l, Wv_l, wh, wl,
            bq + l * DMODEL, bk + l * DMODEL, bv + l * DMODEL, bqkv);
        run_gemm(xh, xl, wh, wl, bqkv, 0, qkv, 0, 0, Mrows, QS, DMODEL, GF_WRF);

        // threefry key derivation (host)
        uint32_t ka, kb; threefry2x32(0u, 42u, 0u, (uint32_t)l, ka, kb);
        uint32_t k2a, k2b;
        threefry2x32(ka, kb, 0u, 1u, k2a, k2b);

        m_kernel<<<BATCH * NH * L / 8, 256>>>(qkv, k2a, k2b, Mb, L, U);
        topk_kernel<<<BATCH * NH, 1024>>>(Mb, top, L, u);
        attn_kernel<<<dim3(NH, BATCH, ASPL), 256, ASM_BYTES>>>(qkv, top, updp, mlp, vsp, L, u);
        attn_merge_kernel<<<BATCH * NH, 256>>>(updp, mlp, vsp, upd, vme, L, u);
        assemble_ctx_kernel<<<(BATCH * L * DMODEL + 255) / 256, 256>>>(vme, ch, cl, L);
        scatter_upd_kernel<<<(BATCH * NH * u * HD + 255) / 256, 256>>>(top, upd, ch, cl, L, u);

        // O projection + residual, LN1 (fp32 x needed by FFN2 residual)
        cvt_split<<<(DMODEL * DMODEL + 255) / 256, 256>>>(Wo_l, wh, wl, DMODEL * DMODEL);
        run_gemm(ch, cl, wh, wl, bo + l * DMODEL, x, t2, 0, 0, Mrows, DMODEL, DMODEL, GF_RES | GF_WRF);
        layernorm_kernel<<<Mrows, 128>>>(t2, ln1_g + l * DMODEL, ln1_b + l * DMODEL, x, xh, xl);

        // FFN
        cvt_split<<<(DFF * DMODEL + 255) / 256, 256>>>(w1_l, wh, wl, DFF * DMODEL);
        run_gemm(xh, xl, wh, wl, conv1_b + l * DFF, 0, 0, ffh, ffl, Mrows, DFF, DMODEL, GF_GELU | GF_SPLIT);
        cvt_split<<<(DMODEL * DFF + 255) / 256, 256>>>(w2_l, wh, wl, DMODEL * DFF);
        run_gemm(ffh, ffl, wh, wl, conv2_b + l * DMODEL, x, t2, 0, 0, Mrows, DMODEL, DFF, GF_RES | GF_WRF);
        // LN2: fp32 output dead for l < ELAY-1 (dconv uses split; bn reads t2; maxpool overwrites x)
        layernorm_kernel<<<Mrows, 128>>>(t2, ln2_g + l * DMODEL, ln2_b + l * DMODEL,
                                         (l == ELAY - 1) ? x : (float*)0, xh, xl);

        // distillation
        if (l < ELAY - 1) {
            const float* dw = dconv_w + (size_t)l * DMODEL * DMODEL * 3;
            cvt_dconv<<<(3 * DMODEL * DMODEL + 255) / 256, 256>>>(dw, wh, wl);
            run_gemm(xh, xl, wh, wl, dconv_b + l * DMODEL, 0, t2, 0, 0,
                     Mrows, DMODEL, DMODEL, GF_CIRC | GF_WRF, 3, L);
            bn_partial_kernel<<<64, DMODEL>>>(t2, bnp, Mrows / 64);
            bn_final_kernel<<<1, DMODEL>>>(bnp, bns, Mrows);
            bn_elu_maxpool_kernel<<<(BATCH * (L / 2) * DMODEL + 255) / 256, 256>>>(
                t2, bns, bn_g + l * DMODEL, bn_b + l * DMODEL, x, xh, xl, L);
            L /= 2;
        }
    }

    layernorm_kernel<<<BATCH * L, 128>>>(x, lnf_g, lnf_b, t2, 0, 0);
    head_kernel<<<(BATCH * L * NCOUT + 255) / 256, 256>>>(t2, end_w, end_b, out, BATCH * L);
}

// round 13
// speedup vs baseline: 1.5504x; 1.5504x over previous
#include <cuda_runtime.h>
#include <cuda_bf16.h>
#include <math.h>
#include <stdint.h>
#include <float.h>

#define BATCH 8
#define S0    2048
#define DMODEL 512
#define NH    8
#define HD    64
#define DFF   2048
#define ELAY  3
#define NCOUT 7
#define UMAX  24
#define QS    1536   // packed qkv row stride
#define ASPL  4      // attention KV splits

// ------------------------- scratch (device globals) --------------------------
__device__ float g_x  [BATCH*S0*DMODEL];
__device__ float g_t2 [BATCH*S0*DMODEL];
__device__ float g_qkv[BATCH*S0*QS];
__device__ float g_M  [BATCH*NH*S0];
__device__ int   g_top[BATCH*NH*UMAX];
__device__ int   g_sel[BATCH*NH*S0];
__device__ float g_vme[BATCH*NH*HD];
__device__ float g_upd[BATCH*NH*UMAX*HD];
__device__ float g_updp[BATCH*NH*ASPL*UMAX*HD];
__device__ float g_mlp [BATCH*NH*ASPL*2*UMAX];
__device__ float g_vsp [BATCH*NH*ASPL*HD];
__device__ float g_bnp[64*DMODEL*2];
__device__ float g_bns[DMODEL*2];
__device__ float g_bqkv[QS];
__device__ __nv_bfloat16 g_xh [BATCH*S0*DMODEL];
__device__ __nv_bfloat16 g_xl [BATCH*S0*DMODEL];
__device__ __nv_bfloat16 g_ch [BATCH*S0*DMODEL];
__device__ __nv_bfloat16 g_cl [BATCH*S0*DMODEL];
__device__ __nv_bfloat16 g_ffh[BATCH*S0*DFF];
__device__ __nv_bfloat16 g_ffl[BATCH*S0*DFF];
__device__ __nv_bfloat16 g_wh [DFF*DMODEL];
__device__ __nv_bfloat16 g_wl [DFF*DMODEL];

// ------------------------- threefry2x32 --------------------------------------
__host__ __device__ __forceinline__ void tf_round(uint32_t& x0, uint32_t& x1, int r) {
    x0 += x1; x1 = (x1 << r) | (x1 >> (32 - r)); x1 ^= x0;
}
__host__ __device__ inline void threefry2x32(uint32_t k0, uint32_t k1,
                                             uint32_t c0, uint32_t c1,
                                             uint32_t& o0, uint32_t& o1) {
    uint32_t ks2 = k0 ^ k1 ^ 0x1BD11BDAu;
    uint32_t x0 = c0 + k0, x1 = c1 + k1;
    tf_round(x0,x1,13); tf_round(x0,x1,15); tf_round(x0,x1,26); tf_round(x0,x1,6);
    x0 += k1;  x1 += ks2 + 1u;
    tf_round(x0,x1,17); tf_round(x0,x1,29); tf_round(x0,x1,16); tf_round(x0,x1,24);
    x0 += ks2; x1 += k0 + 2u;
    tf_round(x0,x1,13); tf_round(x0,x1,15); tf_round(x0,x1,26); tf_round(x0,x1,6);
    x0 += k0;  x1 += k1 + 3u;
    tf_round(x0,x1,17); tf_round(x0,x1,29); tf_round(x0,x1,16); tf_round(x0,x1,24);
    x0 += k1;  x1 += ks2 + 4u;
    tf_round(x0,x1,13); tf_round(x0,x1,15); tf_round(x0,x1,26); tf_round(x0,x1,6);
    x0 += ks2; x1 += k0 + 5u;
    o0 = x0; o1 = x1;
}

// ------------------------- split helpers -------------------------------------
__device__ __forceinline__ void split_bf16(float v, __nv_bfloat16& h, __nv_bfloat16& l) {
    h = __float2bfloat16(v);
    l = __float2bfloat16(v - __bfloat162float(h));
}
__global__ void cvt_split(const float* __restrict__ x, __nv_bfloat16* __restrict__ h,
                          __nv_bfloat16* __restrict__ l, int n) {
    int i = blockIdx.x * 256 + threadIdx.x;
    if (i >= n) return;
    split_bf16(x[i], h[i], l[i]);
}
__global__ void cvt_qkv(const float* __restrict__ Wq, const float* __restrict__ Wk,
                        const float* __restrict__ Wv, __nv_bfloat16* __restrict__ h,
                        __nv_bfloat16* __restrict__ l) {
    int i = blockIdx.x * 256 + threadIdx.x;
    if (i >= 3 * DMODEL * DMODEL) return;
    int r = i / DMODEL, c = i - r * DMODEL;
    const float* W = (r < DMODEL) ? Wq : (r < 2 * DMODEL) ? Wk : Wv;
    int rr = r & (DMODEL - 1);
    split_bf16(W[rr * DMODEL + c], h[i], l[i]);
}
__global__ void concat_bias(const float* __restrict__ bq, const float* __restrict__ bk,
                            const float* __restrict__ bv, float* __restrict__ dst) {
    int i = blockIdx.x * 256 + threadIdx.x;
    if (i >= QS) return;
    dst[i] = (i < DMODEL) ? bq[i] : (i < 2 * DMODEL) ? bk[i - DMODEL] : bv[i - 2 * DMODEL];
}
__global__ void cvt_dconv(const float* __restrict__ w, __nv_bfloat16* __restrict__ h,
                          __nv_bfloat16* __restrict__ l) {
    int i = blockIdx.x * 256 + threadIdx.x;
    if (i >= 3 * DMODEL * DMODEL) return;
    int tap = i / (DMODEL * DMODEL);
    int r = i - tap * DMODEL * DMODEL;
    split_bf16(w[(size_t)r * 3 + tap], h[i], l[i]);
}

// ------------------------- mma.sync GEMM (merged sections) -------------------
#define GF_GELU   1
#define GF_RES    2
#define GF_CIRC   8
#define GF_WRF    32
#define GF_SPLIT  64

#define BM 128
#define BN 128
#define BK 32
#define SSTRIDE 40
#define TSZ (128 * SSTRIDE * 2)
#define STAGE_BYTES (4 * TSZ)
#define GSMEM (2 * STAGE_BYTES)

__device__ __forceinline__ void load_chunk2(
    const __nv_bfloat16* __restrict__ Ah, const __nv_bfloat16* __restrict__ Al,
    const __nv_bfloat16* __restrict__ Bh, const __nv_bfloat16* __restrict__ Bl,
    char* dynsm, int buf, int c, int nkc, int K, int N,
    int m0, int n0, int flags, int Lb, int tid)
{
    int tap = c / nkc;
    int kc = c - tap * nkc;
    int k0 = kc * BK;
    int shift = (flags & GF_CIRC) ? (tap - 1) : 0;
    char* st = dynsm + buf * STAGE_BYTES;
    const __nv_bfloat16* Bht = Bh + (size_t)tap * N * K;
    const __nv_bfloat16* Blt = Bl + (size_t)tap * N * K;
    #pragma unroll 2
    for (int i = tid; i < 512; i += 256) {
        int row = i >> 2, seg = i & 3;
        int gm = m0 + row, arow = gm;
        if (flags & GF_CIRC) {
            int b = gm / Lb, t = gm - b * Lb + shift;
            if (t < 0) t += Lb; else if (t >= Lb) t -= Lb;
            arow = b * Lb + t;
        }
        size_t so = (size_t)arow * K + k0 + seg * 8;
        uint32_t d = (uint32_t)__cvta_generic_to_shared(st + row * (SSTRIDE * 2) + seg * 16);
        asm volatile("cp.async.cg.shared.global [%0], [%1], 16;" :: "r"(d), "l"(Ah + so));
        asm volatile("cp.async.cg.shared.global [%0], [%1], 16;" :: "r"(d + TSZ), "l"(Al + so));
    }
    #pragma unroll 2
    for (int i = tid; i < 512; i += 256) {
        int row = i >> 2, seg = i & 3;
        size_t so = (size_t)(n0 + row) * K + k0 + seg * 8;
        uint32_t d = (uint32_t)__cvta_generic_to_shared(st + 2 * TSZ + row * (SSTRIDE * 2) + seg * 16);
        asm volatile("cp.async.cg.shared.global [%0], [%1], 16;" :: "r"(d), "l"(Bht + so));
        asm volatile("cp.async.cg.shared.global [%0], [%1], 16;" :: "r"(d + TSZ), "l"(Blt + so));
    }
    asm volatile("cp.async.commit_group;");
}

__global__ __launch_bounds__(256)
void mma_gemm(const __nv_bfloat16* __restrict__ Ah, const __nv_bfloat16* __restrict__ Al,
              const __nv_bfloat16* __restrict__ Bh, const __nv_bfloat16* __restrict__ Bl,
              const float* __restrict__ bias, const float* __restrict__ R,
              float* __restrict__ C, __nv_bfloat16* __restrict__ Ch, __nv_bfloat16* __restrict__ Cl,
              int M, int N, int K, int flags, int ntaps, int Lb)
{
    extern __shared__ __align__(16) char dynsm[];
    int tid = threadIdx.x, lane = tid & 31, wid = tid >> 5;
    int warp_m = wid & 1, warp_n = wid >> 1;
    int m0 = blockIdx.y * BM, n0 = blockIdx.x * BN;

    float acc[4][4][4];
    #pragma unroll
    for (int mi = 0; mi < 4; mi++)
        #pragma unroll
        for (int ni = 0; ni < 4; ni++)
            #pragma unroll
            for (int e = 0; e < 4; e++) acc[mi][ni][e] = 0.f;

    const int nkc = K / BK;
    const int nch = nkc * ntaps;

    load_chunk2(Ah, Al, Bh, Bl, dynsm, 0, 0, nkc, K, N, m0, n0, flags, Lb, tid);

    uint32_t smb = (uint32_t)__cvta_generic_to_shared(dynsm);
    int a_row = warp_m * 64 + (lane & 15);
    int a_col = (lane >> 4) * 8;
    int b_row = warp_n * 32 + (lane & 7) + ((lane >> 4) * 8);
    int b_col = ((lane >> 3) & 1) * 8;

    for (int c = 0; c < nch; c++) {
        if (c + 1 < nch) {
            load_chunk2(Ah, Al, Bh, Bl, dynsm, (c + 1) & 1, c + 1, nkc, K, N, m0, n0, flags, Lb, tid);
            asm volatile("cp.async.wait_group 1;");
        } else {
            asm volatile("cp.async.wait_group 0;");
        }
        __syncthreads();
        uint32_t ab = smb + (c & 1) * STAGE_BYTES;
        #pragma unroll
        for (int ks = 0; ks < 2; ks++) {
            uint32_t ah[4][4], al[4][4];
            #pragma unroll
            for (int mi = 0; mi < 4; mi++) {
                uint32_t addr = ab + ((a_row + mi * 16) * SSTRIDE + ks * 16 + a_col) * 2;
                asm volatile("ldmatrix.sync.aligned.m8n8.x4.shared.b16 {%0,%1,%2,%3}, [%4];"
                    : "=r"(ah[mi][0]), "=r"(ah[mi][1]), "=r"(ah[mi][2]), "=r"(ah[mi][3]) : "r"(addr));
                asm volatile("ldmatrix.sync.aligned.m8n8.x4.shared.b16 {%0,%1,%2,%3}, [%4];"
                    : "=r"(al[mi][0]), "=r"(al[mi][1]), "=r"(al[mi][2]), "=r"(al[mi][3]) : "r"(addr + TSZ));
            }
            uint32_t bh[4][2], bl[4][2];
            #pragma unroll
            for (int nf2 = 0; nf2 < 2; nf2++) {
                uint32_t r0, r1, r2, r3;
                uint32_t addr = ab + 2 * TSZ + ((b_row + nf2 * 16) * SSTRIDE + ks * 16 + b_col) * 2;
                asm volatile("ldmatrix.sync.aligned.m8n8.x4.shared.b16 {%0,%1,%2,%3}, [%4];"
                    : "=r"(r0), "=r"(r1), "=r"(r2), "=r"(r3) : "r"(addr));
                bh[nf2 * 2][0] = r0;     bh[nf2 * 2][1] = r1;
                bh[nf2 * 2 + 1][0] = r2; bh[nf2 * 2 + 1][1] = r3;
                asm volatile("ldmatrix.sync.aligned.m8n8.x4.shared.b16 {%0,%1,%2,%3}, [%4];"
                    : "=r"(r0), "=r"(r1), "=r"(r2), "=r"(r3) : "r"(addr + TSZ));
                bl[nf2 * 2][0] = r0;     bl[nf2 * 2][1] = r1;
                bl[nf2 * 2 + 1][0] = r2; bl[nf2 * 2 + 1][1] = r3;
            }
            #pragma unroll
            for (int mi = 0; mi < 4; mi++)
                #pragma unroll
                for (int ni = 0; ni < 4; ni++)
                    asm volatile("mma.sync.aligned.m16n8k16.row.col.f32.bf16.bf16.f32 "
                        "{%0,%1,%2,%3}, {%4,%5,%6,%7}, {%8,%9}, {%0,%1,%2,%3};"
                        : "+f"(acc[mi][ni][0]), "+f"(acc[mi][ni][1]), "+f"(acc[mi][ni][2]), "+f"(acc[mi][ni][3])
                        : "r"(ah[mi][0]), "r"(ah[mi][1]), "r"(ah[mi][2]), "r"(ah[mi][3]),
                          "r"(bh[ni][0]), "r"(bh[ni][1]));
            #pragma unroll
            for (int mi = 0; mi < 4; mi++)
                #pragma unroll
                for (int ni = 0; ni < 4; ni++)
                    asm volatile("mma.sync.aligned.m16n8k16.row.col.f32.bf16.bf16.f32 "
                        "{%0,%1,%2,%3}, {%4,%5,%6,%7}, {%8,%9}, {%0,%1,%2,%3};"
                        : "+f"(acc[mi][ni][0]), "+f"(acc[mi][ni][1]), "+f"(acc[mi][ni][2]), "+f"(acc[mi][ni][3])
                        : "r"(ah[mi][0]), "r"(ah[mi][1]), "r"(ah[mi][2]), "r"(ah[mi][3]),
                          "r"(bl[ni][0]), "r"(bl[ni][1]));
            #pragma unroll
            for (int mi = 0; mi < 4; mi++)
                #pragma unroll
                for (int ni = 0; ni < 4; ni++)
                    asm volatile("mma.sync.aligned.m16n8k16.row.col.f32.bf16.bf16.f32 "
                        "{%0,%1,%2,%3}, {%4,%5,%6,%7}, {%8,%9}, {%0,%1,%2,%3};"
                        : "+f"(acc[mi][ni][0]), "+f"(acc[mi][ni][1]), "+f"(acc[mi][ni][2]), "+f"(acc[mi][ni][3])
                        : "r"(al[mi][0]), "r"(al[mi][1]), "r"(al[mi][2]), "r"(al[mi][3]),
                          "r"(bh[ni][0]), "r"(bh[ni][1]));
        }
        __syncthreads();
    }

    // epilogue
    #pragma unroll
    for (int mi = 0; mi < 4; mi++) {
        #pragma unroll
        for (int ni = 0; ni < 4; ni++) {
            int gm0 = m0 + warp_m * 64 + mi * 16 + (lane >> 2);
            int gn  = n0 + warp_n * 32 + ni * 8 + (lane & 3) * 2;
            float2 bs = *(const float2*)&bias[gn];
            #pragma unroll
            for (int h = 0; h < 2; h++) {
                int gm = gm0 + h * 8;
                float2 v = make_float2(acc[mi][ni][h * 2], acc[mi][ni][h * 2 + 1]);
                v.x += bs.x; v.y += bs.y;
                if (flags & GF_GELU) {
                    v.x = 0.5f * v.x * (1.0f + erff(v.x * 0.7071067811865475f));
                    v.y = 0.5f * v.y * (1.0f + erff(v.y * 0.7071067811865475f));
                }
                if (flags & GF_RES) {
                    float2 rv = *(const float2*)&R[(size_t)gm * N + gn];
                    v.x += rv.x; v.y += rv.y;
                }
                if (flags & GF_WRF) *(float2*)&C[(size_t)gm * N + gn] = v;
                if (flags & GF_SPLIT) {
                    __nv_bfloat16 h0, l0, h1, l1;
                    split_bf16(v.x, h0, l0); split_bf16(v.y, h1, l1);
                    __nv_bfloat162 hv; hv.x = h0; hv.y = h1;
                    __nv_bfloat162 lv; lv.x = l0; lv.y = l1;
                    *(__nv_bfloat162*)&Ch[(size_t)gm * N + gn] = hv;
                    *(__nv_bfloat162*)&Cl[(size_t)gm * N + gn] = lv;
                }
            }
        }
    }
}

// ------------------------- token conv + positional embedding -----------------
__global__ void tok_conv_kernel(const float* __restrict__ xe, const float* __restrict__ w,
                                float* __restrict__ out, __nv_bfloat16* __restrict__ oh,
                                __nv_bfloat16* __restrict__ ol) {
    int t = blockIdx.x;
    __shared__ float xs[BATCH][21];
    int tid = threadIdx.x;
    for (int j = tid; j < BATCH * 21; j += 128) {
        int b = j / 21, jj = j % 21;
        int kk = jj / 7, i = jj % 7;
        int tt = t + kk - 1;
        if (tt < 0) tt += S0; else if (tt >= S0) tt -= S0;
        xs[b][kk * 7 + i] = xe[(size_t)(b * S0 + tt) * 7 + i];
    }
    __syncthreads();
    for (int o = tid; o < DMODEL; o += 128) {
        float wreg[21];
        const float* wo = w + o * 21;
        #pragma unroll
        for (int j = 0; j < 21; j++) wreg[j] = wo[j];
        int e = o & ~1;
        float dv = expf((float)e * -0.017988946038918563f);
        float ang = (float)t * dv;
        float pe = (o & 1) ? cosf(ang) : sinf(ang);
        #pragma unroll
        for (int b = 0; b < BATCH; b++) {
            float acc = pe;
            #pragma unroll
            for (int i = 0; i < 7; i++)
                #pragma unroll
                for (int kk = 0; kk < 3; kk++) acc += xs[b][kk * 7 + i] * wreg[i * 3 + kk];
            size_t oi = (size_t)(b * S0 + t) * DMODEL + o;
            out[oi] = acc;
            split_bf16(acc, oh[oi], ol[oi]);
        }
    }
}

// ------------------------- ProbSparse attention (packed qkv) -----------------
__global__ void m_kernel(const float* __restrict__ qkv, uint32_t ka, uint32_t kb,
                         float* __restrict__ Mo, int L, int U) {
    int gw = blockIdx.x * 8 + (threadIdx.x >> 5);
    int lane = threadIdx.x & 31;
    int b = gw / (NH * L);
    int h = (gw / L) % NH;
    int l = gw % L;
    int j = l * U + (lane < U ? lane : U - 1);
    uint32_t o0, o1;
    threefry2x32(ka, kb, 0u, (uint32_t)j, o0, o1);
    int kr = (int)((o0 ^ o1) & (uint32_t)(L - 1));
    const float4* qp = (const float4*)&qkv[(size_t)(b * L + l) * QS + h * HD];
    const float4* kp = (const float4*)&qkv[(size_t)(b * L + kr) * QS + DMODEL + h * HD];
    float acc = 0.f;
    #pragma unroll
    for (int jj = 0; jj < 16; jj++) {
        float4 qv = qp[jj], kv = kp[jj];
        acc += qv.x * kv.x + qv.y * kv.y + qv.z * kv.z + qv.w * kv.w;
    }
    float mx = (lane < U) ? acc : -FLT_MAX;
    float sm = (lane < U) ? acc : 0.f;
    #pragma unroll
    for (int off = 16; off; off >>= 1) {
        mx = fmaxf(mx, __shfl_xor_sync(0xffffffffu, mx, off));
        sm += __shfl_xor_sync(0xffffffffu, sm, off);
    }
    if (lane == 0) Mo[(b * NH + h) * L + l] = mx - sm / (float)L;
}

__global__ void topk_kernel(const float* __restrict__ Mi, int* __restrict__ top,
                            int L, int u) {
    int bh = blockIdx.x, tid = threadIdx.x;
    int lane = tid & 31, warp = tid >> 5;
    __shared__ float sv[S0];
    __shared__ float wv[32];
    __shared__ int   wi[32];
    const float* m = Mi + (size_t)bh * L;
    for (int i = tid; i < L; i += 1024) sv[i] = m[i];
    __syncthreads();
    for (int it = 0; it < u; it++) {
        float best = -FLT_MAX; int besti = L;
        for (int i = tid; i < L; i += 1024) {
            float v = sv[i];
            if (v > best) { best = v; besti = i; }
        }
        #pragma unroll
        for (int off = 16; off; off >>= 1) {
            float ov = __shfl_xor_sync(0xffffffffu, best, off);
            int   oi = __shfl_xor_sync(0xffffffffu, besti, off);
            if (ov > best || (ov == best && oi < besti)) { best = ov; besti = oi; }
        }
        if (lane == 0) { wv[warp] = best; wi[warp] = besti; }
        __syncthreads();
        if (warp == 0) {
            best = wv[lane]; besti = wi[lane];
            #pragma unroll
            for (int off = 16; off; off >>= 1) {
                float ov = __shfl_xor_sync(0xffffffffu, best, off);
                int   oi = __shfl_xor_sync(0xffffffffu, besti, off);
                if (ov > best || (ov == best && oi < besti)) { best = ov; besti = oi; }
            }
            if (lane == 0) { top[bh * u + it] = besti; sv[besti] = -FLT_MAX; }
        }
        __syncthreads();
    }
}

__global__ void clear_sel_kernel(int* __restrict__ sel, int n) {
    int i = blockIdx.x * blockDim.x + threadIdx.x;
    if (i < n) sel[i] = 0;
}
__global__ void scatter_sel_kernel(const int* __restrict__ top, int* __restrict__ sel,
                                   int L, int u) {
    int i = blockIdx.x * blockDim.x + threadIdx.x;
    if (i >= BATCH * NH * u) return;
    int bh = i / u, ui = i % u;
    sel[(size_t)bh * L + top[bh * u + ui]] = ui + 1;
}

// ------------------------- split-KV flash attention + vmean ------------------
#define ATK 128
#define KSTR 68
#define ASM_FLOATS (2*ATK*KSTR + UMAX*ATK + 2*UMAX*HD + 2*UMAX + HD)
#define ASM_BYTES (ASM_FLOATS * 4)

__global__ void attn_kernel(const float* __restrict__ qkv, const int* __restrict__ top,
                            float* __restrict__ updp, float* __restrict__ mlp,
                            float* __restrict__ vsp, int L, int u) {
    extern __shared__ float sm[];
    float* Kt   = sm;
    float* Vt   = Kt + ATK * KSTR;
    float* sc   = Vt + ATK * KSTR;
    float* qs   = sc + UMAX * ATK;
    float* accs = qs + UMAX * HD;
    float* mst  = accs + UMAX * HD;
    float* lst  = mst + UMAX;
    float* vsum = lst + UMAX;
    int h = blockIdx.x, b = blockIdx.y, z = blockIdx.z;
    int bh = b * NH + h;
    int bhz = bh * ASPL + z;
    int Lc = L / ASPL;
    int tbase = z * Lc;
    int tid = threadIdx.x, lane = tid & 31, warp = tid >> 5;

    for (int i = tid; i < u * HD; i += 256) {
        int q = i >> 6, d = i & 63;
        int qrow = top[bh * u + q];
        qs[q * HD + d] = qkv[(size_t)(b * L + qrow) * QS + h * HD + d];
        accs[i] = 0.f;
    }
    if (tid < UMAX) { mst[tid] = -FLT_MAX; lst[tid] = 0.f; }
    if (tid < HD) vsum[tid] = 0.f;
    __syncthreads();

    for (int t0 = tbase; t0 < tbase + Lc; t0 += ATK) {
        for (int i = tid; i < ATK * 16; i += 256) {
            int row = i >> 4, seg = i & 15;
            const float* base = &qkv[(size_t)(b * L + t0 + row) * QS + DMODEL + h * HD + seg * 4];
            *(float4*)&Kt[row * KSTR + seg * 4] = *(const float4*)base;
            *(float4*)&Vt[row * KSTR + seg * 4] = *(const float4*)(base + DMODEL);
        }
        __syncthreads();
        if (tid < HD) {
            float s = 0.f;
            for (int k = 0; k < ATK; k++) s += Vt[k * KSTR + tid];
            vsum[tid] += s;
        }
        for (int i = tid; i < u * ATK; i += 256) {
            int q = i >> 7, k = i & (ATK - 1);
            const float* qp = &qs[q * HD];
            const float* kp = &Kt[k * KSTR];
            float acc = 0.f;
            #pragma unroll
            for (int d4 = 0; d4 < 16; d4++) {
                float4 a = *(const float4*)&qp[d4 * 4];
                float4 c = *(const float4*)&kp[d4 * 4];
                acc += a.x * c.x + a.y * c.y + a.z * c.z + a.w * c.w;
            }
            sc[q * ATK + k] = acc * 0.125f;
        }
        __syncthreads();
        #pragma unroll
        for (int qi = 0; qi < 3; qi++) {
            int q = warp * 3 + qi;
            if (q < u) {
                float s0 = sc[q * ATK + lane],      s1 = sc[q * ATK + 32 + lane];
                float s2 = sc[q * ATK + 64 + lane], s3 = sc[q * ATK + 96 + lane];
                float tm = fmaxf(fmaxf(s0, s1), fmaxf(s2, s3));
                #pragma unroll
                for (int off = 16; off; off >>= 1)
                    tm = fmaxf(tm, __shfl_xor_sync(0xffffffffu, tm, off));
                float mold = mst[q];
                float newm = fmaxf(mold, tm);
                float alpha = expf(mold - newm);
                float p0 = expf(s0 - newm), p1 = expf(s1 - newm);
                float p2 = expf(s2 - newm), p3 = expf(s3 - newm);
                sc[q * ATK + lane] = p0;      sc[q * ATK + 32 + lane] = p1;
                sc[q * ATK + 64 + lane] = p2; sc[q * ATK + 96 + lane] = p3;
                float ls = p0 + p1 + p2 + p3;
                #pragma unroll
                for (int off = 16; off; off >>= 1)
                    ls += __shfl_xor_sync(0xffffffffu, ls, off);
                if (lane == 0) { lst[q] = lst[q] * alpha + ls; mst[q] = newm; }
                __syncwarp();
                #pragma unroll
                for (int dd = 0; dd < 2; dd++) {
                    int d = lane + dd * 32;
                    float a = accs[q * HD + d] * alpha;
                    for (int k = 0; k < ATK; k++)
                        a += sc[q * ATK + k] * Vt[k * KSTR + d];
                    accs[q * HD + d] = a;
                }
            }
        }
        __syncthreads();
    }
    #pragma unroll
    for (int qi = 0; qi < 3; qi++) {
        int q = warp * 3 + qi;
        if (q < u) {
            updp[((size_t)bhz * UMAX + q) * HD + lane]      = accs[q * HD + lane];
            updp[((size_t)bhz * UMAX + q) * HD + lane + 32] = accs[q * HD + lane + 32];
            if (lane == 0) {
                mlp[bhz * 2 * UMAX + q]        = mst[q];
                mlp[bhz * 2 * UMAX + UMAX + q] = lst[q];
            }
        }
    }
    if (tid < HD) vsp[bhz * HD + tid] = vsum[tid];
}

__global__ void attn_merge_kernel(const float* __restrict__ updp, const float* __restrict__ mlp,
                                  const float* __restrict__ vsp, float* __restrict__ upd,
                                  float* __restrict__ vme, int L, int u) {
    int bh = blockIdx.x, tid = threadIdx.x;
    for (int i = tid; i < u * HD; i += 256) {
        int q = i >> 6, d = i & 63;
        float M = -FLT_MAX;
        #pragma unroll
        for (int z = 0; z < ASPL; z++)
            M = fmaxf(M, mlp[(bh * ASPL + z) * 2 * UMAX + q]);
        float lsum = 0.f, asum = 0.f;
        #pragma unroll
        for (int z = 0; z < ASPL; z++) {
            int bhz = bh * ASPL + z;
            float w = expf(mlp[bhz * 2 * UMAX + q] - M);
            lsum += mlp[bhz * 2 * UMAX + UMAX + q] * w;
            asum += updp[((size_t)bhz * UMAX + q) * HD + d] * w;
        }
        upd[((size_t)bh * u + q) * HD + d] = asum / lsum;
    }
    if (tid < HD) {
        float s = 0.f;
        #pragma unroll
        for (int z = 0; z < ASPL; z++) s += vsp[(bh * ASPL + z) * HD + tid];
        vme[bh * HD + tid] = s / (float)L;
    }
}

__global__ void assemble_ctx_kernel(const int* __restrict__ sel, const float* __restrict__ upd,
                                    const float* __restrict__ vm,
                                    __nv_bfloat16* __restrict__ ch, __nv_bfloat16* __restrict__ cl,
                                    int L, int u) {
    int i = blockIdx.x * blockDim.x + threadIdx.x;
    int total = BATCH * L * DMODEL;
    if (i >= total) return;
    int b = i / (L * DMODEL);
    int r = i - b * L * DMODEL;
    int l = r / DMODEL;
    int c = r - l * DMODEL;
    int h = c / HD, d = c - h * HD;
    int bh = b * NH + h;
    int s = sel[(size_t)bh * L + l];
    float val = s ? upd[((size_t)bh * u + (s - 1)) * HD + d] : vm[bh * HD + d];
    split_bf16(val, ch[i], cl[i]);
}

// ------------------------- layernorm -----------------------------------------
__global__ void layernorm_kernel(const float* __restrict__ in, const float* __restrict__ g,
                                 const float* __restrict__ bb, float* __restrict__ out,
                                 __nv_bfloat16* __restrict__ oh, __nv_bfloat16* __restrict__ ol) {
    int row = blockIdx.x, tid = threadIdx.x;
    __shared__ float red[128];
    const float4 v = ((const float4*)(in + (size_t)row * DMODEL))[tid];
    red[tid] = v.x + v.y + v.z + v.w;
    __syncthreads();
    for (int s = 64; s > 0; s >>= 1) { if (tid < s) red[tid] += red[tid + s]; __syncthreads(); }
    float mean = red[0] / (float)DMODEL;
    __syncthreads();
    float dx = v.x - mean, dy = v.y - mean, dz = v.z - mean, dw = v.w - mean;
    red[tid] = dx * dx + dy * dy + dz * dz + dw * dw;
    __syncthreads();
    for (int s = 64; s > 0; s >>= 1) { if (tid < s) red[tid] += red[tid + s]; __syncthreads(); }
    float rstd = rsqrtf(red[0] / (float)DMODEL + 1e-5f);
    const float4 gv = ((const float4*)g)[tid];
    const float4 bv = ((const float4*)bb)[tid];
    float4 o;
    o.x = dx * rstd * gv.x + bv.x;
    o.y = dy * rstd * gv.y + bv.y;
    o.z = dz * rstd * gv.z + bv.z;
    o.w = dw * rstd * gv.w + bv.w;
    ((float4*)(out + (size_t)row * DMODEL))[tid] = o;
    if (oh) {
        size_t base = (size_t)row * DMODEL + tid * 4;
        split_bf16(o.x, oh[base],   ol[base]);
        split_bf16(o.y, oh[base+1], ol[base+1]);
        split_bf16(o.z, oh[base+2], ol[base+2]);
        split_bf16(o.w, oh[base+3], ol[base+3]);
    }
}

// ------------------------- distil helpers ------------------------------------
__global__ void bn_partial_kernel(const float* __restrict__ y, float* __restrict__ part, int rpc) {
    int chunk = blockIdx.x, c = threadIdx.x;
    float s = 0.f, ss = 0.f;
    for (int r = 0; r < rpc; r++) {
        float vv = y[(size_t)(chunk * rpc + r) * DMODEL + c];
        s += vv; ss += vv * vv;
    }
    part[(size_t)chunk * (2 * DMODEL) + c] = s;
    part[(size_t)chunk * (2 * DMODEL) + DMODEL + c] = ss;
}
__global__ void bn_final_kernel(const float* __restrict__ part, float* __restrict__ stat,
                                int Mtot) {
    int c = threadIdx.x;
    float s = 0.f, ss = 0.f;
    #pragma unroll 8
    for (int ch = 0; ch < 64; ch++) {
        s  += part[(size_t)ch * (2 * DMODEL) + c];
        ss += part[(size_t)ch * (2 * DMODEL) + DMODEL + c];
    }
    float mu = s / (float)Mtot;
    stat[c] = mu;
    stat[DMODEL + c] = ss / (float)Mtot - mu * mu;
}
__global__ void bn_elu_maxpool_kernel(const float* __restrict__ y, const float* __restrict__ stat,
                                      const float* __restrict__ g, const float* __restrict__ bb,
                                      float* __restrict__ out,
                                      __nv_bfloat16* __restrict__ oh, __nv_bfloat16* __restrict__ ol,
                                      int L) {
    int Lo = L / 2;
    int i = blockIdx.x * blockDim.x + threadIdx.x;
    int total = BATCH * Lo * DMODEL;
    if (i >= total) return;
    int b = i / (Lo * DMODEL);
    int r = i - b * Lo * DMODEL;
    int t = r / DMODEL;
    int c = r - t * DMODEL;
    float mu = stat[c];
    float rstd = rsqrtf(stat[DMODEL + c] + 1e-5f);
    float gc = g[c], bc = bb[c];
    float m = -FLT_MAX;
    #pragma unroll
    for (int dt = -1; dt <= 1; dt++) {
        int tt = 2 * t + dt;
        if (tt >= 0 && tt < L) {
            float z = (y[(size_t)(b * L + tt) * DMODEL + c] - mu) * rstd * gc + bc;
            z = z > 0.f ? z : expm1f(z);
            m = fmaxf(m, z);
        }
    }
    out[i] = m;
    split_bf16(m, oh[i], ol[i]);
}

// ------------------------- head ----------------------------------------------
__global__ void head_kernel(const float* __restrict__ x, const float* __restrict__ w,
                            const float* __restrict__ eb, float* __restrict__ out, int rows) {
    int i = blockIdx.x * blockDim.x + threadIdx.x;
    if (i >= rows * NCOUT) return;
    int row = i / NCOUT, c = i - row * NCOUT;
    const float* xr = x + (size_t)row * DMODEL;
    const float* wr = w + (size_t)c * DMODEL;
    float acc = eb[c];
    for (int d = 0; d < DMODEL; d++) acc += xr[d] * wr[d];
    out[i] = acc;
}

// ------------------------- host orchestration --------------------------------
static inline void run_gemm(const __nv_bfloat16* Ah, const __nv_bfloat16* Al,
                            const __nv_bfloat16* Bh, const __nv_bfloat16* Bl,
                            const float* bias, const float* R,
                            float* C, __nv_bfloat16* Ch, __nv_bfloat16* Cl,
                            int M, int N, int K, int flags, int ntaps = 1, int Lb = 1) {
    dim3 grid(N / BN, M / BM);
    mma_gemm<<<grid, 256, GSMEM>>>(Ah, Al, Bh, Bl, bias, R, C, Ch, Cl, M, N, K, flags, ntaps, Lb);
}

extern "C" void kernel_launch(void* const* d_in, const int* in_sizes, int n_in,
                              void* d_out, int out_size) {
    (void)in_sizes; (void)n_in; (void)out_size;
    const float* x_enc   = (const float*)d_in[0];
    const float* tok_w   = (const float*)d_in[1];
    const float* Wq      = (const float*)d_in[2];
    const float* bq      = (const float*)d_in[3];
    const float* Wk      = (const float*)d_in[4];
    const float* bk      = (const float*)d_in[5];
    const float* Wv      = (const float*)d_in[6];
    const float* bv      = (const float*)d_in[7];
    const float* Wo      = (const float*)d_in[8];
    const float* bo      = (const float*)d_in[9];
    const float* conv1_w = (const float*)d_in[10];
    const float* conv1_b = (const float*)d_in[11];
    const float* conv2_w = (const float*)d_in[12];
    const float* conv2_b = (const float*)d_in[13];
    const float* ln1_g   = (const float*)d_in[14];
    const float* ln1_b   = (const float*)d_in[15];
    const float* ln2_g   = (const float*)d_in[16];
    const float* ln2_b   = (const float*)d_in[17];
    const float* dconv_w = (const float*)d_in[18];
    const float* dconv_b = (const float*)d_in[19];
    const float* bn_g    = (const float*)d_in[20];
    const float* bn_b    = (const float*)d_in[21];
    const float* lnf_g   = (const float*)d_in[22];
    const float* lnf_b   = (const float*)d_in[23];
    const float* end_w   = (const float*)d_in[24];
    const float* end_b   = (const float*)d_in[25];
    float* out = (float*)d_out;

    cudaFuncSetAttribute(mma_gemm, cudaFuncAttributeMaxDynamicSharedMemorySize, GSMEM);
    cudaFuncSetAttribute(attn_kernel, cudaFuncAttributeMaxDynamicSharedMemorySize, ASM_BYTES);

    void *p;
    cudaGetSymbolAddress(&p, g_x);    float* x    = (float*)p;
    cudaGetSymbolAddress(&p, g_t2);   float* t2   = (float*)p;
    cudaGetSymbolAddress(&p, g_qkv);  float* qkv  = (float*)p;
    cudaGetSymbolAddress(&p, g_M);    float* Mb   = (float*)p;
    cudaGetSymbolAddress(&p, g_top);  int*   top  = (int*)p;
    cudaGetSymbolAddress(&p, g_sel);  int*   sel  = (int*)p;
    cudaGetSymbolAddress(&p, g_vme);  float* vme  = (float*)p;
    cudaGetSymbolAddress(&p, g_upd);  float* upd  = (float*)p;
    cudaGetSymbolAddress(&p, g_updp); float* updp = (float*)p;
    cudaGetSymbolAddress(&p, g_mlp);  float* mlp  = (float*)p;
    cudaGetSymbolAddress(&p, g_vsp);  float* vsp  = (float*)p;
    cudaGetSymbolAddress(&p, g_bnp);  float* bnp  = (float*)p;
    cudaGetSymbolAddress(&p, g_bns);  float* bns  = (float*)p;
    cudaGetSymbolAddress(&p, g_bqkv); float* bqkv = (float*)p;
    cudaGetSymbolAddress(&p, g_xh);   __nv_bfloat16* xh  = (__nv_bfloat16*)p;
    cudaGetSymbolAddress(&p, g_xl);   __nv_bfloat16* xl  = (__nv_bfloat16*)p;
    cudaGetSymbolAddress(&p, g_ch);   __nv_bfloat16* ch  = (__nv_bfloat16*)p;
    cudaGetSymbolAddress(&p, g_cl);   __nv_bfloat16* cl  = (__nv_bfloat16*)p;
    cudaGetSymbolAddress(&p, g_ffh);  __nv_bfloat16* ffh = (__nv_bfloat16*)p;
    cudaGetSymbolAddress(&p, g_ffl);  __nv_bfloat16* ffl = (__nv_bfloat16*)p;
    cudaGetSymbolAddress(&p, g_wh);   __nv_bfloat16* wh  = (__nv_bfloat16*)p;
    cudaGetSymbolAddress(&p, g_wl);   __nv_bfloat16* wl  = (__nv_bfloat16*)p;

    tok_conv_kernel<<<S0, 128>>>(x_enc, tok_w, x, xh, xl);

    int L = S0;
    for (int l = 0; l < ELAY; l++) {
        int U = (l == 0) ? 24 : 21;
        int u = U;
        int Mrows = BATCH * L;
        const float* Wq_l = Wq + (size_t)l * DMODEL * DMODEL;
        const float* Wk_l = Wk + (size_t)l * DMODEL * DMODEL;
        const float* Wv_l = Wv + (size_t)l * DMODEL * DMODEL;
        const float* Wo_l = Wo + (size_t)l * DMODEL * DMODEL;
        const float* w1_l = conv1_w + (size_t)l * DFF * DMODEL;
        const float* w2_l = conv2_w + (size_t)l * DMODEL * DFF;

        // fused QKV projection (N = 1536)
        concat_bias<<<6, 256>>>(bq + l * DMODEL, bk + l * DMODEL, bv + l * DMODEL, bqkv);
        cvt_qkv<<<(3 * DMODEL * DMODEL + 255) / 256, 256>>>(Wq_l, Wk_l, Wv_l, wh, wl);
        run_gemm(xh, xl, wh, wl, bqkv, 0, qkv, 0, 0, Mrows, QS, DMODEL, GF_WRF);

        // threefry key derivation (host)
        uint32_t ka, kb; threefry2x32(0u, 42u, 0u, (uint32_t)l, ka, kb);
        uint32_t k2a, k2b;
        threefry2x32(ka, kb, 0u, 1u, k2a, k2b);

        m_kernel<<<BATCH * NH * L / 8, 256>>>(qkv, k2a, k2b, Mb, L, U);
        topk_kernel<<<BATCH * NH, 1024>>>(Mb, top, L, u);
        clear_sel_kernel<<<(BATCH * NH * L + 255) / 256, 256>>>(sel, BATCH * NH * L);
        scatter_sel_kernel<<<(BATCH * NH * u + 255) / 256, 256>>>(top, sel, L, u);
        attn_kernel<<<dim3(NH, BATCH, ASPL), 256, ASM_BYTES>>>(qkv, top, updp, mlp, vsp, L, u);
        attn_merge_kernel<<<BATCH * NH, 256>>>(updp, mlp, vsp, upd, vme, L, u);
        assemble_ctx_kernel<<<(BATCH * L * DMODEL + 255) / 256, 256>>>(sel, upd, vme, ch, cl, L, u);

        // O projection + residual, LN1
        cvt_split<<<(DMODEL * DMODEL + 255) / 256, 256>>>(Wo_l, wh, wl, DMODEL * DMODEL);
        run_gemm(ch, cl, wh, wl, bo + l * DMODEL, x, t2, 0, 0, Mrows, DMODEL, DMODEL, GF_RES | GF_WRF);
        layernorm_kernel<<<Mrows, 128>>>(t2, ln1_g + l * DMODEL, ln1_b + l * DMODEL, x, xh, xl);

        // FFN
        cvt_split<<<(DFF * DMODEL + 255) / 256, 256>>>(w1_l, wh, wl, DFF * DMODEL);
        run_gemm(xh, xl, wh, wl, conv1_b + l * DFF, 0, 0, ffh, ffl, Mrows, DFF, DMODEL, GF_GELU | GF_SPLIT);
        cvt_split<<<(DMODEL * DFF + 255) / 256, 256>>>(w2_l, wh, wl, DMODEL * DFF);
        run_gemm(ffh, ffl, wh, wl, conv2_b + l * DMODEL, x, t2, 0, 0, Mrows, DMODEL, DFF, GF_RES | GF_WRF);
        layernorm_kernel<<<Mrows, 128>>>(t2, ln2_g + l * DMODEL, ln2_b + l * DMODEL, x, xh, xl);

        // distillation
        if (l < ELAY - 1) {
            const float* dw = dconv_w + (size_t)l * DMODEL * DMODEL * 3;
            cvt_dconv<<<(3 * DMODEL * DMODEL + 255) / 256, 256>>>(dw, wh, wl);
            run_gemm(xh, xl, wh, wl, dconv_b + l * DMODEL, 0, t2, 0, 0,
                     Mrows, DMODEL, DMODEL, GF_CIRC | GF_WRF, 3, L);
            bn_partial_kernel<<<64, DMODEL>>>(t2, bnp, Mrows / 64);
            bn_final_kernel<<<1, DMODEL>>>(bnp, bns, Mrows);
            bn_elu_maxpool_kernel<<<(BATCH * (L / 2) * DMODEL + 255) / 256, 256>>>(
                t2, bns, bn_g + l * DMODEL, bn_b + l * DMODEL, x, xh, xl, L);
            L /= 2;
        }
    }

    layernorm_kernel<<<BATCH * L, 128>>>(x, lnf_g, lnf_b, t2, 0, 0);
    head_kernel<<<(BATCH * L * NCOUT + 255) / 256, 256>>>(t2, end_w, end_b, out, BATCH * L);
}

// round 14
// speedup vs baseline: 1.6084x; 1.0374x over previous
#include <cuda_runtime.h>
#include <cuda_bf16.h>
#include <math.h>
#include <stdint.h>
#include <float.h>

#define BATCH 8
#define S0    2048
#define DMODEL 512
#define NH    8
#define HD    64
#define DFF   2048
#define ELAY  3
#define NCOUT 7
#define UMAX  24
#define QS    1536   // packed qkv row stride
#define ASPL  4      // attention KV splits

// ------------------------- scratch (device globals) --------------------------
__device__ float g_x  [BATCH*S0*DMODEL];
__device__ float g_t2 [BATCH*S0*DMODEL];
__device__ float g_qkv[BATCH*S0*QS];
__device__ float g_M  [BATCH*NH*S0];
__device__ int   g_top[BATCH*NH*UMAX];
__device__ int   g_sel[BATCH*NH*S0];
__device__ float g_vme[BATCH*NH*HD];
__device__ float g_upd[BATCH*NH*UMAX*HD];
__device__ float g_updp[BATCH*NH*ASPL*UMAX*HD];
__device__ float g_mlp [BATCH*NH*ASPL*2*UMAX];
__device__ float g_vsp [BATCH*NH*ASPL*HD];
__device__ float g_bnp[64*DMODEL*2];
__device__ float g_bns[DMODEL*2];
__device__ float g_bqkv[QS];
__device__ __nv_bfloat16 g_xh [BATCH*S0*DMODEL];
__device__ __nv_bfloat16 g_xl [BATCH*S0*DMODEL];
__device__ __nv_bfloat16 g_ch [BATCH*S0*DMODEL];
__device__ __nv_bfloat16 g_cl [BATCH*S0*DMODEL];
__device__ __nv_bfloat16 g_ffh[BATCH*S0*DFF];
__device__ __nv_bfloat16 g_ffl[BATCH*S0*DFF];
__device__ __nv_bfloat16 g_wh [DFF*DMODEL];
__device__ __nv_bfloat16 g_wl [DFF*DMODEL];

// ------------------------- threefry2x32 --------------------------------------
__host__ __device__ __forceinline__ void tf_round(uint32_t& x0, uint32_t& x1, int r) {
    x0 += x1; x1 = (x1 << r) | (x1 >> (32 - r)); x1 ^= x0;
}
__host__ __device__ inline void threefry2x32(uint32_t k0, uint32_t k1,
                                             uint32_t c0, uint32_t c1,
                                             uint32_t& o0, uint32_t& o1) {
    uint32_t ks2 = k0 ^ k1 ^ 0x1BD11BDAu;
    uint32_t x0 = c0 + k0, x1 = c1 + k1;
    tf_round(x0,x1,13); tf_round(x0,x1,15); tf_round(x0,x1,26); tf_round(x0,x1,6);
    x0 += k1;  x1 += ks2 + 1u;
    tf_round(x0,x1,17); tf_round(x0,x1,29); tf_round(x0,x1,16); tf_round(x0,x1,24);
    x0 += ks2; x1 += k0 + 2u;
    tf_round(x0,x1,13); tf_round(x0,x1,15); tf_round(x0,x1,26); tf_round(x0,x1,6);
    x0 += k0;  x1 += k1 + 3u;
    tf_round(x0,x1,17); tf_round(x0,x1,29); tf_round(x0,x1,16); tf_round(x0,x1,24);
    x0 += k1;  x1 += ks2 + 4u;
    tf_round(x0,x1,13); tf_round(x0,x1,15); tf_round(x0,x1,26); tf_round(x0,x1,6);
    x0 += ks2; x1 += k0 + 5u;
    o0 = x0; o1 = x1;
}

// ------------------------- split helpers -------------------------------------
__device__ __forceinline__ void split_bf16(float v, __nv_bfloat16& h, __nv_bfloat16& l) {
    h = __float2bfloat16(v);
    l = __float2bfloat16(v - __bfloat162float(h));
}
__global__ void cvt_split(const float* __restrict__ x, __nv_bfloat16* __restrict__ h,
                          __nv_bfloat16* __restrict__ l, int n) {
    int i = blockIdx.x * 256 + threadIdx.x;
    if (i >= n) return;
    split_bf16(x[i], h[i], l[i]);
}
__global__ void cvt_qkv(const float* __restrict__ Wq, const float* __restrict__ Wk,
                        const float* __restrict__ Wv, __nv_bfloat16* __restrict__ h,
                        __nv_bfloat16* __restrict__ l) {
    int i = blockIdx.x * 256 + threadIdx.x;
    if (i >= 3 * DMODEL * DMODEL) return;
    int r = i / DMODEL, c = i - r * DMODEL;
    const float* W = (r < DMODEL) ? Wq : (r < 2 * DMODEL) ? Wk : Wv;
    int rr = r & (DMODEL - 1);
    split_bf16(W[rr * DMODEL + c], h[i], l[i]);
}
__global__ void concat_bias(const float* __restrict__ bq, const float* __restrict__ bk,
                            const float* __restrict__ bv, float* __restrict__ dst) {
    int i = blockIdx.x * 256 + threadIdx.x;
    if (i >= QS) return;
    dst[i] = (i < DMODEL) ? bq[i] : (i < 2 * DMODEL) ? bk[i - DMODEL] : bv[i - 2 * DMODEL];
}
__global__ void cvt_dconv(const float* __restrict__ w, __nv_bfloat16* __restrict__ h,
                          __nv_bfloat16* __restrict__ l) {
    int i = blockIdx.x * 256 + threadIdx.x;
    if (i >= 3 * DMODEL * DMODEL) return;
    int tap = i / (DMODEL * DMODEL);
    int r = i - tap * DMODEL * DMODEL;
    split_bf16(w[(size_t)r * 3 + tap], h[i], l[i]);
}

// ------------------------- mma.sync GEMM (frozen) ----------------------------
#define GF_GELU   1
#define GF_RES    2
#define GF_CIRC   8
#define GF_WRF    32
#define GF_SPLIT  64

#define BM 128
#define BN 128
#define BK 32
#define SSTRIDE 40
#define TSZ (128 * SSTRIDE * 2)
#define STAGE_BYTES (4 * TSZ)
#define GSMEM (2 * STAGE_BYTES)

__device__ __forceinline__ void load_chunk2(
    const __nv_bfloat16* __restrict__ Ah, const __nv_bfloat16* __restrict__ Al,
    const __nv_bfloat16* __restrict__ Bh, const __nv_bfloat16* __restrict__ Bl,
    char* dynsm, int buf, int c, int nkc, int K, int N,
    int m0, int n0, int flags, int Lb, int tid)
{
    int tap = c / nkc;
    int kc = c - tap * nkc;
    int k0 = kc * BK;
    int shift = (flags & GF_CIRC) ? (tap - 1) : 0;
    char* st = dynsm + buf * STAGE_BYTES;
    const __nv_bfloat16* Bht = Bh + (size_t)tap * N * K;
    const __nv_bfloat16* Blt = Bl + (size_t)tap * N * K;
    #pragma unroll 2
    for (int i = tid; i < 512; i += 256) {
        int row = i >> 2, seg = i & 3;
        int gm = m0 + row, arow = gm;
        if (flags & GF_CIRC) {
            int b = gm / Lb, t = gm - b * Lb + shift;
            if (t < 0) t += Lb; else if (t >= Lb) t -= Lb;
            arow = b * Lb + t;
        }
        size_t so = (size_t)arow * K + k0 + seg * 8;
        uint32_t d = (uint32_t)__cvta_generic_to_shared(st + row * (SSTRIDE * 2) + seg * 16);
        asm volatile("cp.async.cg.shared.global [%0], [%1], 16;" :: "r"(d), "l"(Ah + so));
        asm volatile("cp.async.cg.shared.global [%0], [%1], 16;" :: "r"(d + TSZ), "l"(Al + so));
    }
    #pragma unroll 2
    for (int i = tid; i < 512; i += 256) {
        int row = i >> 2, seg = i & 3;
        size_t so = (size_t)(n0 + row) * K + k0 + seg * 8;
        uint32_t d = (uint32_t)__cvta_generic_to_shared(st + 2 * TSZ + row * (SSTRIDE * 2) + seg * 16);
        asm volatile("cp.async.cg.shared.global [%0], [%1], 16;" :: "r"(d), "l"(Bht + so));
        asm volatile("cp.async.cg.shared.global [%0], [%1], 16;" :: "r"(d + TSZ), "l"(Blt + so));
    }
    asm volatile("cp.async.commit_group;");
}

__global__ __launch_bounds__(256)
void mma_gemm(const __nv_bfloat16* __restrict__ Ah, const __nv_bfloat16* __restrict__ Al,
              const __nv_bfloat16* __restrict__ Bh, const __nv_bfloat16* __restrict__ Bl,
              const float* __restrict__ bias, const float* __restrict__ R,
              float* __restrict__ C, __nv_bfloat16* __restrict__ Ch, __nv_bfloat16* __restrict__ Cl,
              int M, int N, int K, int flags, int ntaps, int Lb)
{
    extern __shared__ __align__(16) char dynsm[];
    int tid = threadIdx.x, lane = tid & 31, wid = tid >> 5;
    int warp_m = wid & 1, warp_n = wid >> 1;
    int m0 = blockIdx.y * BM, n0 = blockIdx.x * BN;

    float acc[4][4][4];
    #pragma unroll
    for (int mi = 0; mi < 4; mi++)
        #pragma unroll
        for (int ni = 0; ni < 4; ni++)
            #pragma unroll
            for (int e = 0; e < 4; e++) acc[mi][ni][e] = 0.f;

    const int nkc = K / BK;
    const int nch = nkc * ntaps;

    load_chunk2(Ah, Al, Bh, Bl, dynsm, 0, 0, nkc, K, N, m0, n0, flags, Lb, tid);

    uint32_t smb = (uint32_t)__cvta_generic_to_shared(dynsm);
    int a_row = warp_m * 64 + (lane & 15);
    int a_col = (lane >> 4) * 8;
    int b_row = warp_n * 32 + (lane & 7) + ((lane >> 4) * 8);
    int b_col = ((lane >> 3) & 1) * 8;

    for (int c = 0; c < nch; c++) {
        if (c + 1 < nch) {
            load_chunk2(Ah, Al, Bh, Bl, dynsm, (c + 1) & 1, c + 1, nkc, K, N, m0, n0, flags, Lb, tid);
            asm volatile("cp.async.wait_group 1;");
        } else {
            asm volatile("cp.async.wait_group 0;");
        }
        __syncthreads();
        uint32_t ab = smb + (c & 1) * STAGE_BYTES;
        #pragma unroll
        for (int ks = 0; ks < 2; ks++) {
            uint32_t ah[4][4], al[4][4];
            #pragma unroll
            for (int mi = 0; mi < 4; mi++) {
                uint32_t addr = ab + ((a_row + mi * 16) * SSTRIDE + ks * 16 + a_col) * 2;
                asm volatile("ldmatrix.sync.aligned.m8n8.x4.shared.b16 {%0,%1,%2,%3}, [%4];"
                    : "=r"(ah[mi][0]), "=r"(ah[mi][1]), "=r"(ah[mi][2]), "=r"(ah[mi][3]) : "r"(addr));
                asm volatile("ldmatrix.sync.aligned.m8n8.x4.shared.b16 {%0,%1,%2,%3}, [%4];"
                    : "=r"(al[mi][0]), "=r"(al[mi][1]), "=r"(al[mi][2]), "=r"(al[mi][3]) : "r"(addr + TSZ));
            }
            uint32_t bh[4][2], bl[4][2];
            #pragma unroll
            for (int nf2 = 0; nf2 < 2; nf2++) {
                uint32_t r0, r1, r2, r3;
                uint32_t addr = ab + 2 * TSZ + ((b_row + nf2 * 16) * SSTRIDE + ks * 16 + b_col) * 2;
                asm volatile("ldmatrix.sync.aligned.m8n8.x4.shared.b16 {%0,%1,%2,%3}, [%4];"
                    : "=r"(r0), "=r"(r1), "=r"(r2), "=r"(r3) : "r"(addr));
                bh[nf2 * 2][0] = r0;     bh[nf2 * 2][1] = r1;
                bh[nf2 * 2 + 1][0] = r2; bh[nf2 * 2 + 1][1] = r3;
                asm volatile("ldmatrix.sync.aligned.m8n8.x4.shared.b16 {%0,%1,%2,%3}, [%4];"
                    : "=r"(r0), "=r"(r1), "=r"(r2), "=r"(r3) : "r"(addr + TSZ));
                bl[nf2 * 2][0] = r0;     bl[nf2 * 2][1] = r1;
                bl[nf2 * 2 + 1][0] = r2; bl[nf2 * 2 + 1][1] = r3;
            }
            #pragma unroll
            for (int mi = 0; mi < 4; mi++)
                #pragma unroll
                for (int ni = 0; ni < 4; ni++)
                    asm volatile("mma.sync.aligned.m16n8k16.row.col.f32.bf16.bf16.f32 "
                        "{%0,%1,%2,%3}, {%4,%5,%6,%7}, {%8,%9}, {%0,%1,%2,%3};"
                        : "+f"(acc[mi][ni][0]), "+f"(acc[mi][ni][1]), "+f"(acc[mi][ni][2]), "+f"(acc[mi][ni][3])
                        : "r"(ah[mi][0]), "r"(ah[mi][1]), "r"(ah[mi][2]), "r"(ah[mi][3]),
                          "r"(bh[ni][0]), "r"(bh[ni][1]));
            #pragma unroll
            for (int mi = 0; mi < 4; mi++)
                #pragma unroll
                for (int ni = 0; ni < 4; ni++)
                    asm volatile("mma.sync.aligned.m16n8k16.row.col.f32.bf16.bf16.f32 "
                        "{%0,%1,%2,%3}, {%4,%5,%6,%7}, {%8,%9}, {%0,%1,%2,%3};"
                        : "+f"(acc[mi][ni][0]), "+f"(acc[mi][ni][1]), "+f"(acc[mi][ni][2]), "+f"(acc[mi][ni][3])
                        : "r"(ah[mi][0]), "r"(ah[mi][1]), "r"(ah[mi][2]), "r"(ah[mi][3]),
                          "r"(bl[ni][0]), "r"(bl[ni][1]));
            #pragma unroll
            for (int mi = 0; mi < 4; mi++)
                #pragma unroll
                for (int ni = 0; ni < 4; ni++)
                    asm volatile("mma.sync.aligned.m16n8k16.row.col.f32.bf16.bf16.f32 "
                        "{%0,%1,%2,%3}, {%4,%5,%6,%7}, {%8,%9}, {%0,%1,%2,%3};"
                        : "+f"(acc[mi][ni][0]), "+f"(acc[mi][ni][1]), "+f"(acc[mi][ni][2]), "+f"(acc[mi][ni][3])
                        : "r"(al[mi][0]), "r"(al[mi][1]), "r"(al[mi][2]), "r"(al[mi][3]),
                          "r"(bh[ni][0]), "r"(bh[ni][1]));
        }
        __syncthreads();
    }

    // epilogue
    #pragma unroll
    for (int mi = 0; mi < 4; mi++) {
        #pragma unroll
        for (int ni = 0; ni < 4; ni++) {
            int gm0 = m0 + warp_m * 64 + mi * 16 + (lane >> 2);
            int gn  = n0 + warp_n * 32 + ni * 8 + (lane & 3) * 2;
            float2 bs = *(const float2*)&bias[gn];
            #pragma unroll
            for (int h = 0; h < 2; h++) {
                int gm = gm0 + h * 8;
                float2 v = make_float2(acc[mi][ni][h * 2], acc[mi][ni][h * 2 + 1]);
                v.x += bs.x; v.y += bs.y;
                if (flags & GF_GELU) {
                    v.x = 0.5f * v.x * (1.0f + erff(v.x * 0.7071067811865475f));
                    v.y = 0.5f * v.y * (1.0f + erff(v.y * 0.7071067811865475f));
                }
                if (flags & GF_RES) {
                    float2 rv = *(const float2*)&R[(size_t)gm * N + gn];
                    v.x += rv.x; v.y += rv.y;
                }
                if (flags & GF_WRF) *(float2*)&C[(size_t)gm * N + gn] = v;
                if (flags & GF_SPLIT) {
                    __nv_bfloat16 h0, l0, h1, l1;
                    split_bf16(v.x, h0, l0); split_bf16(v.y, h1, l1);
                    __nv_bfloat162 hv; hv.x = h0; hv.y = h1;
                    __nv_bfloat162 lv; lv.x = l0; lv.y = l1;
                    *(__nv_bfloat162*)&Ch[(size_t)gm * N + gn] = hv;
                    *(__nv_bfloat162*)&Cl[(size_t)gm * N + gn] = lv;
                }
            }
        }
    }
}

// ------------------------- token conv + positional embedding -----------------
__global__ void tok_conv_kernel(const float* __restrict__ xe, const float* __restrict__ w,
                                float* __restrict__ out, __nv_bfloat16* __restrict__ oh,
                                __nv_bfloat16* __restrict__ ol) {
    int t = blockIdx.x;
    __shared__ float xs[BATCH][21];
    int tid = threadIdx.x;
    for (int j = tid; j < BATCH * 21; j += 128) {
        int b = j / 21, jj = j % 21;
        int kk = jj / 7, i = jj % 7;
        int tt = t + kk - 1;
        if (tt < 0) tt += S0; else if (tt >= S0) tt -= S0;
        xs[b][kk * 7 + i] = xe[(size_t)(b * S0 + tt) * 7 + i];
    }
    __syncthreads();
    for (int o = tid; o < DMODEL; o += 128) {
        float wreg[21];
        const float* wo = w + o * 21;
        #pragma unroll
        for (int j = 0; j < 21; j++) wreg[j] = wo[j];
        int e = o & ~1;
        float dv = expf((float)e * -0.017988946038918563f);
        float ang = (float)t * dv;
        float pe = (o & 1) ? cosf(ang) : sinf(ang);
        #pragma unroll
        for (int b = 0; b < BATCH; b++) {
            float acc = pe;
            #pragma unroll
            for (int i = 0; i < 7; i++)
                #pragma unroll
                for (int kk = 0; kk < 3; kk++) acc += xs[b][kk * 7 + i] * wreg[i * 3 + kk];
            size_t oi = (size_t)(b * S0 + t) * DMODEL + o;
            out[oi] = acc;
            split_bf16(acc, oh[oi], ol[oi]);
        }
    }
}

// ------------------------- ProbSparse M: head-shared K rows ------------------
// One warp per (b, l): sampled K rows are IDENTICAL across heads, so each
// sampled row is loaded once (coalesced, warp-cooperative into smem) and all
// NH head dot-products are computed from the staged row. 8x less gmem traffic.
__global__ void m2_kernel(const float* __restrict__ qkv, uint32_t ka, uint32_t kb,
                          float* __restrict__ Mo, int L, int U) {
    __shared__ float krow[8][136];   // 8 warps; 128 floats + pad
    __shared__ float qrow[8][136];
    int wid = threadIdx.x >> 5, lane = threadIdx.x & 31;
    int gw = blockIdx.x * 8 + wid;
    int b = gw / L;
    int l = gw - b * L;
    // stage this l's full Q row (512 floats = 16 float4, lane-coalesced)
    {
        const float4* src = (const float4*)&qkv[(size_t)(b * L + l) * QS];
        float4 v0 = src[lane];          // floats [0,128)
        float4 v1 = src[lane + 32];     // floats [128,256)
        float4 v2 = src[lane + 64];
        float4 v3 = src[lane + 96];
        *(float4*)&qrow[wid][0]   = v0;  // placeholder; real store below
        // store all four segments at lane*4 offsets across 512: use four banks
        // qrow only holds 136 floats; we instead keep Q in registers per lane:
        // each lane owns floats [lane*4, lane*4+4) of each 128-float head pair.
        // Simpler: recompute per-sample from gmem Q row (L2-resident, reused U times).
        (void)v0; (void)v1; (void)v2; (void)v3;
    }
    float mx[NH], sm[NH];
    #pragma unroll
    for (int h = 0; h < NH; h++) { mx[h] = -FLT_MAX; sm[h] = 0.f; }
    const float* qbase = &qkv[(size_t)(b * L + l) * QS];
    for (int s = 0; s < U; s++) {
        int j = l * U + s;
        uint32_t o0, o1;
        threefry2x32(ka, kb, 0u, (uint32_t)j, o0, o1);
        int kr = (int)((o0 ^ o1) & (uint32_t)(L - 1));
        // warp-cooperative load of K row (512 floats): lane loads 4 float4 = 16 floats
        const float4* ksrc = (const float4*)&qkv[(size_t)(b * L + kr) * QS + DMODEL];
        // each lane computes partial dot per head over its 16 floats (4 per head-quarter)
        // layout: head h owns floats [h*64, (h+1)*64). lane covers floats
        // [lane*4, lane*4+4) + [128+lane*4, ...) + [256+...] + [384+...]
        // i.e. lane hits heads lane/16*... — do it generically:
        float part[NH];
        #pragma unroll
        for (int h = 0; h < NH; h++) part[h] = 0.f;
        #pragma unroll
        for (int seg = 0; seg < 4; seg++) {
            int f0 = seg * 128 + lane * 4;      // float offset in [0,512)
            float4 kv = ksrc[seg * 32 + lane];
            const float4 qv = *(const float4*)&qbase[f0];
            int h = f0 >> 6;                    // head index (f0/64)
            part[h] += qv.x * kv.x + qv.y * kv.y + qv.z * kv.z + qv.w * kv.w;
        }
        // reduce each head's partial across the 16 lanes that touched it:
        // head h spans lanes [h*16 mod 32 ...] — floats [h*64,(h+1)*64) =
        // lanes (h*64/4)%32 .. : each head covered by 16 consecutive lane-slots
        // within one seg pair. Butterfly over full warp sums all parts per head:
        #pragma unroll
        for (int h = 0; h < NH; h++) {
            float v = part[h];
            #pragma unroll
            for (int off = 16; off; off >>= 1)
                v += __shfl_xor_sync(0xffffffffu, v, off);
            if (v == v) {   // keep
                mx[h] = fmaxf(mx[h], v);
                sm[h] += v;
            }
        }
    }
    if (lane == 0) {
        #pragma unroll
        for (int h = 0; h < NH; h++)
            Mo[(b * NH + h) * L + l] = mx[h] - sm[h] / (float)L;
    }
}

__global__ void topk_kernel(const float* __restrict__ Mi, int* __restrict__ top,
                            int L, int u) {
    int bh = blockIdx.x, tid = threadIdx.x;
    int lane = tid & 31, warp = tid >> 5;
    __shared__ float sv[S0];
    __shared__ float wv[32];
    __shared__ int   wi[32];
    const float* m = Mi + (size_t)bh * L;
    for (int i = tid; i < L; i += 1024) sv[i] = m[i];
    __syncthreads();
    for (int it = 0; it < u; it++) {
        float best = -FLT_MAX; int besti = L;
        for (int i = tid; i < L; i += 1024) {
            float v = sv[i];
            if (v > best) { best = v; besti = i; }
        }
        #pragma unroll
        for (int off = 16; off; off >>= 1) {
            float ov = __shfl_xor_sync(0xffffffffu, best, off);
            int   oi = __shfl_xor_sync(0xffffffffu, besti, off);
            if (ov > best || (ov == best && oi < besti)) { best = ov; besti = oi; }
        }
        if (lane == 0) { wv[warp] = best; wi[warp] = besti; }
        __syncthreads();
        if (warp == 0) {
            best = wv[lane]; besti = wi[lane];
            #pragma unroll
            for (int off = 16; off; off >>= 1) {
                float ov = __shfl_xor_sync(0xffffffffu, best, off);
                int   oi = __shfl_xor_sync(0xffffffffu, besti, off);
                if (ov > best || (ov == best && oi < besti)) { best = ov; besti = oi; }
            }
            if (lane == 0) { top[bh * u + it] = besti; sv[besti] = -FLT_MAX; }
        }
        __syncthreads();
    }
}

__global__ void clear_sel_kernel(int* __restrict__ sel, int n) {
    int i = blockIdx.x * blockDim.x + threadIdx.x;
    if (i < n) sel[i] = 0;
}
__global__ void scatter_sel_kernel(const int* __restrict__ top, int* __restrict__ sel,
                                   int L, int u) {
    int i = blockIdx.x * blockDim.x + threadIdx.x;
    if (i >= BATCH * NH * u) return;
    int bh = i / u, ui = i % u;
    sel[(size_t)bh * L + top[bh * u + ui]] = ui + 1;
}

// ------------------------- split-KV flash attention + vmean ------------------
#define ATK 128
#define KSTR 68
#define ASM_FLOATS (2*ATK*KSTR + UMAX*ATK + 2*UMAX*HD + 2*UMAX + HD)
#define ASM_BYTES (ASM_FLOATS * 4)

__global__ void attn_kernel(const float* __restrict__ qkv, const int* __restrict__ top,
                            float* __restrict__ updp, float* __restrict__ mlp,
                            float* __restrict__ vsp, int L, int u) {
    extern __shared__ float sm[];
    float* Kt   = sm;
    float* Vt   = Kt + ATK * KSTR;
    float* sc   = Vt + ATK * KSTR;
    float* qs   = sc + UMAX * ATK;
    float* accs = qs + UMAX * HD;
    float* mst  = accs + UMAX * HD;
    float* lst  = mst + UMAX;
    float* vsum = lst + UMAX;
    int h = blockIdx.x, b = blockIdx.y, z = blockIdx.z;
    int bh = b * NH + h;
    int bhz = bh * ASPL + z;
    int Lc = L / ASPL;
    int tbase = z * Lc;
    int tid = threadIdx.x, lane = tid & 31, warp = tid >> 5;

    for (int i = tid; i < u * HD; i += 256) {
        int q = i >> 6, d = i & 63;
        int qrow = top[bh * u + q];
        qs[q * HD + d] = qkv[(size_t)(b * L + qrow) * QS + h * HD + d];
        accs[i] = 0.f;
    }
    if (tid < UMAX) { mst[tid] = -FLT_MAX; lst[tid] = 0.f; }
    if (tid < HD) vsum[tid] = 0.f;
    __syncthreads();

    for (int t0 = tbase; t0 < tbase + Lc; t0 += ATK) {
        for (int i = tid; i < ATK * 16; i += 256) {
            int row = i >> 4, seg = i & 15;
            const float* base = &qkv[(size_t)(b * L + t0 + row) * QS + DMODEL + h * HD + seg * 4];
            *(float4*)&Kt[row * KSTR + seg * 4] = *(const float4*)base;
            *(float4*)&Vt[row * KSTR + seg * 4] = *(const float4*)(base + DMODEL);
        }
        __syncthreads();
        if (tid < HD) {
            float s = 0.f;
            for (int k = 0; k < ATK; k++) s += Vt[k * KSTR + tid];
            vsum[tid] += s;
        }
        for (int i = tid; i < u * ATK; i += 256) {
            int q = i >> 7, k = i & (ATK - 1);
            const float* qp = &qs[q * HD];
            const float* kp = &Kt[k * KSTR];
            float acc = 0.f;
            #pragma unroll
            for (int d4 = 0; d4 < 16; d4++) {
                float4 a = *(const float4*)&qp[d4 * 4];
                float4 c = *(const float4*)&kp[d4 * 4];
                acc += a.x * c.x + a.y * c.y + a.z * c.z + a.w * c.w;
            }
            sc[q * ATK + k] = acc * 0.125f;
        }
        __syncthreads();
        #pragma unroll
        for (int qi = 0; qi < 3; qi++) {
            int q = warp * 3 + qi;
            if (q < u) {
                float s0 = sc[q * ATK + lane],      s1 = sc[q * ATK + 32 + lane];
                float s2 = sc[q * ATK + 64 + lane], s3 = sc[q * ATK + 96 + lane];
                float tm = fmaxf(fmaxf(s0, s1), fmaxf(s2, s3));
                #pragma unroll
                for (int off = 16; off; off >>= 1)
                    tm = fmaxf(tm, __shfl_xor_sync(0xffffffffu, tm, off));
                float mold = mst[q];
                float newm = fmaxf(mold, tm);
                float alpha = expf(mold - newm);
                float p0 = expf(s0 - newm), p1 = expf(s1 - newm);
                float p2 = expf(s2 - newm), p3 = expf(s3 - newm);
                sc[q * ATK + lane] = p0;      sc[q * ATK + 32 + lane] = p1;
                sc[q * ATK + 64 + lane] = p2; sc[q * ATK + 96 + lane] = p3;
                float ls = p0 + p1 + p2 + p3;
                #pragma unroll
                for (int off = 16; off; off >>= 1)
                    ls += __shfl_xor_sync(0xffffffffu, ls, off);
                if (lane == 0) { lst[q] = lst[q] * alpha + ls; mst[q] = newm; }
                __syncwarp();
                #pragma unroll
                for (int dd = 0; dd < 2; dd++) {
                    int d = lane + dd * 32;
                    float a = accs[q * HD + d] * alpha;
                    for (int k = 0; k < ATK; k++)
                        a += sc[q * ATK + k] * Vt[k * KSTR + d];
                    accs[q * HD + d] = a;
                }
            }
        }
        __syncthreads();
    }
    #pragma unroll
    for (int qi = 0; qi < 3; qi++) {
        int q = warp * 3 + qi;
        if (q < u) {
            updp[((size_t)bhz * UMAX + q) * HD + lane]      = accs[q * HD + lane];
            updp[((size_t)bhz * UMAX + q) * HD + lane + 32] = accs[q * HD + lane + 32];
            if (lane == 0) {
                mlp[bhz * 2 * UMAX + q]        = mst[q];
                mlp[bhz * 2 * UMAX + UMAX + q] = lst[q];
            }
        }
    }
    if (tid < HD) vsp[bhz * HD + tid] = vsum[tid];
}

__global__ void attn_merge_kernel(const float* __restrict__ updp, const float* __restrict__ mlp,
                                  const float* __restrict__ vsp, float* __restrict__ upd,
                                  float* __restrict__ vme, int L, int u) {
    int bh = blockIdx.x, tid = threadIdx.x;
    for (int i = tid; i < u * HD; i += 256) {
        int q = i >> 6, d = i & 63;
        float M = -FLT_MAX;
        #pragma unroll
        for (int z = 0; z < ASPL; z++)
            M = fmaxf(M, mlp[(bh * ASPL + z) * 2 * UMAX + q]);
        float lsum = 0.f, asum = 0.f;
        #pragma unroll
        for (int z = 0; z < ASPL; z++) {
            int bhz = bh * ASPL + z;
            float w = expf(mlp[bhz * 2 * UMAX + q] - M);
            lsum += mlp[bhz * 2 * UMAX + UMAX + q] * w;
            asum += updp[((size_t)bhz * UMAX + q) * HD + d] * w;
        }
        upd[((size_t)bh * u + q) * HD + d] = asum / lsum;
    }
    if (tid < HD) {
        float s = 0.f;
        #pragma unroll
        for (int z = 0; z < ASPL; z++) s += vsp[(bh * ASPL + z) * HD + tid];
        vme[bh * HD + tid] = s / (float)L;
    }
}

__global__ void assemble_ctx_kernel(const int* __restrict__ sel, const float* __restrict__ upd,
                                    const float* __restrict__ vm,
                                    __nv_bfloat16* __restrict__ ch, __nv_bfloat16* __restrict__ cl,
                                    int L, int u) {
    int i = blockIdx.x * blockDim.x + threadIdx.x;
    int total = BATCH * L * DMODEL;
    if (i >= total) return;
    int b = i / (L * DMODEL);
    int r = i - b * L * DMODEL;
    int l = r / DMODEL;
    int c = r - l * DMODEL;
    int h = c / HD, d = c - h * HD;
    int bh = b * NH + h;
    int s = sel[(size_t)bh * L + l];
    float val = s ? upd[((size_t)bh * u + (s - 1)) * HD + d] : vm[bh * HD + d];
    split_bf16(val, ch[i], cl[i]);
}

// ------------------------- layernorm -----------------------------------------
__global__ void layernorm_kernel(const float* __restrict__ in, const float* __restrict__ g,
                                 const float* __restrict__ bb, float* __restrict__ out,
                                 __nv_bfloat16* __restrict__ oh, __nv_bfloat16* __restrict__ ol) {
    int row = blockIdx.x, tid = threadIdx.x;
    __shared__ float red[128];
    const float4 v = ((const float4*)(in + (size_t)row * DMODEL))[tid];
    red[tid] = v.x + v.y + v.z + v.w;
    __syncthreads();
    for (int s = 64; s > 0; s >>= 1) { if (tid < s) red[tid] += red[tid + s]; __syncthreads(); }
    float mean = red[0] / (float)DMODEL;
    __syncthreads();
    float dx = v.x - mean, dy = v.y - mean, dz = v.z - mean, dw = v.w - mean;
    red[tid] = dx * dx + dy * dy + dz * dz + dw * dw;
    __syncthreads();
    for (int s = 64; s > 0; s >>= 1) { if (tid < s) red[tid] += red[tid + s]; __syncthreads(); }
    float rstd = rsqrtf(red[0] / (float)DMODEL + 1e-5f);
    const float4 gv = ((const float4*)g)[tid];
    const float4 bv = ((const float4*)bb)[tid];
    float4 o;
    o.x = dx * rstd * gv.x + bv.x;
    o.y = dy * rstd * gv.y + bv.y;
    o.z = dz * rstd * gv.z + bv.z;
    o.w = dw * rstd * gv.w + bv.w;
    ((float4*)(out + (size_t)row * DMODEL))[tid] = o;
    if (oh) {
        size_t base = (size_t)row * DMODEL + tid * 4;
        split_bf16(o.x, oh[base],   ol[base]);
        split_bf16(o.y, oh[base+1], ol[base+1]);
        split_bf16(o.z, oh[base+2], ol[base+2]);
        split_bf16(o.w, oh[base+3], ol[base+3]);
    }
}

// ------------------------- distil helpers ------------------------------------
__global__ void bn_partial_kernel(const float* __restrict__ y, float* __restrict__ part, int rpc) {
    int chunk = blockIdx.x, c = threadIdx.x;
    float s = 0.f, ss = 0.f;
    for (int r = 0; r < rpc; r++) {
        float vv = y[(size_t)(chunk * rpc + r) * DMODEL + c];
        s += vv; ss += vv * vv;
    }
    part[(size_t)chunk * (2 * DMODEL) + c] = s;
    part[(size_t)chunk * (2 * DMODEL) + DMODEL + c] = ss;
}
__global__ void bn_final_kernel(const float* __restrict__ part, float* __restrict__ stat,
                                int Mtot) {
    int c = threadIdx.x;
    float s = 0.f, ss = 0.f;
    #pragma unroll 8
    for (int ch = 0; ch < 64; ch++) {
        s  += part[(size_t)ch * (2 * DMODEL) + c];
        ss += part[(size_t)ch * (2 * DMODEL) + DMODEL + c];
    }
    float mu = s / (float)Mtot;
    stat[c] = mu;
    stat[DMODEL + c] = ss / (float)Mtot - mu * mu;
}
__global__ void bn_elu_maxpool_kernel(const float* __restrict__ y, const float* __restrict__ stat,
                                      const float* __restrict__ g, const float* __restrict__ bb,
                                      float* __restrict__ out,
                                      __nv_bfloat16* __restrict__ oh, __nv_bfloat16* __restrict__ ol,
                                      int L) {
    int Lo = L / 2;
    int i = blockIdx.x * blockDim.x + threadIdx.x;
    int total = BATCH * Lo * DMODEL;
    if (i >= total) return;
    int b = i / (Lo * DMODEL);
    int r = i - b * Lo * DMODEL;
    int t = r / DMODEL;
    int c = r - t * DMODEL;
    float mu = stat[c];
    float rstd = rsqrtf(stat[DMODEL + c] + 1e-5f);
    float gc = g[c], bc = bb[c];
    float m = -FLT_MAX;
    #pragma unroll
    for (int dt = -1; dt <= 1; dt++) {
        int tt = 2 * t + dt;
        if (tt >= 0 && tt < L) {
            float z = (y[(size_t)(b * L + tt) * DMODEL + c] - mu) * rstd * gc + bc;
            z = z > 0.f ? z : expm1f(z);
            m = fmaxf(m, z);
        }
    }
    out[i] = m;
    split_bf16(m, oh[i], ol[i]);
}

// ------------------------- head ----------------------------------------------
__global__ void head_kernel(const float* __restrict__ x, const float* __restrict__ w,
                            const float* __restrict__ eb, float* __restrict__ out, int rows) {
    int i = blockIdx.x * blockDim.x + threadIdx.x;
    if (i >= rows * NCOUT) return;
    int row = i / NCOUT, c = i - row * NCOUT;
    const float* xr = x + (size_t)row * DMODEL;
    const float* wr = w + (size_t)c * DMODEL;
    float acc = eb[c];
    for (int d = 0; d < DMODEL; d++) acc += xr[d] * wr[d];
    out[i] = acc;
}

// ------------------------- host orchestration --------------------------------
static inline void run_gemm(const __nv_bfloat16* Ah, const __nv_bfloat16* Al,
                            const __nv_bfloat16* Bh, const __nv_bfloat16* Bl,
                            const float* bias, const float* R,
                            float* C, __nv_bfloat16* Ch, __nv_bfloat16* Cl,
                            int M, int N, int K, int flags, int ntaps = 1, int Lb = 1) {
    dim3 grid(N / BN, M / BM);
    mma_gemm<<<grid, 256, GSMEM>>>(Ah, Al, Bh, Bl, bias, R, C, Ch, Cl, M, N, K, flags, ntaps, Lb);
}

extern "C" void kernel_launch(void* const* d_in, const int* in_sizes, int n_in,
                              void* d_out, int out_size) {
    (void)in_sizes; (void)n_in; (void)out_size;
    const float* x_enc   = (const float*)d_in[0];
    const float* tok_w   = (const float*)d_in[1];
    const float* Wq      = (const float*)d_in[2];
    const float* bq      = (const float*)d_in[3];
    const float* Wk      = (const float*)d_in[4];
    const float* bk      = (const float*)d_in[5];
    const float* Wv      = (const float*)d_in[6];
    const float* bv      = (const float*)d_in[7];
    const float* Wo      = (const float*)d_in[8];
    const float* bo      = (const float*)d_in[9];
    const float* conv1_w = (const float*)d_in[10];
    const float* conv1_b = (const float*)d_in[11];
    const float* conv2_w = (const float*)d_in[12];
    const float* conv2_b = (const float*)d_in[13];
    const float* ln1_g   = (const float*)d_in[14];
    const float* ln1_b   = (const float*)d_in[15];
    const float* ln2_g   = (const float*)d_in[16];
    const float* ln2_b   = (const float*)d_in[17];
    const float* dconv_w = (const float*)d_in[18];
    const float* dconv_b = (const float*)d_in[19];
    const float* bn_g    = (const float*)d_in[20];
    const float* bn_b    = (const float*)d_in[21];
    const float* lnf_g   = (const float*)d_in[22];
    const float* lnf_b   = (const float*)d_in[23];
    const float* end_w   = (const float*)d_in[24];
    const float* end_b   = (const float*)d_in[25];
    float* out = (float*)d_out;

    cudaFuncSetAttribute(mma_gemm, cudaFuncAttributeMaxDynamicSharedMemorySize, GSMEM);
    cudaFuncSetAttribute(attn_kernel, cudaFuncAttributeMaxDynamicSharedMemorySize, ASM_BYTES);

    void *p;
    cudaGetSymbolAddress(&p, g_x);    float* x    = (float*)p;
    cudaGetSymbolAddress(&p, g_t2);   float* t2   = (float*)p;
    cudaGetSymbolAddress(&p, g_qkv);  float* qkv  = (float*)p;
    cudaGetSymbolAddress(&p, g_M);    float* Mb   = (float*)p;
    cudaGetSymbolAddress(&p, g_top);  int*   top  = (int*)p;
    cudaGetSymbolAddress(&p, g_sel);  int*   sel  = (int*)p;
    cudaGetSymbolAddress(&p, g_vme);  float* vme  = (float*)p;
    cudaGetSymbolAddress(&p, g_upd);  float* upd  = (float*)p;
    cudaGetSymbolAddress(&p, g_updp); float* updp = (float*)p;
    cudaGetSymbolAddress(&p, g_mlp);  float* mlp  = (float*)p;
    cudaGetSymbolAddress(&p, g_vsp);  float* vsp  = (float*)p;
    cudaGetSymbolAddress(&p, g_bnp);  float* bnp  = (float*)p;
    cudaGetSymbolAddress(&p, g_bns);  float* bns  = (float*)p;
    cudaGetSymbolAddress(&p, g_bqkv); float* bqkv = (float*)p;
    cudaGetSymbolAddress(&p, g_xh);   __nv_bfloat16* xh  = (__nv_bfloat16*)p;
    cudaGetSymbolAddress(&p, g_xl);   __nv_bfloat16* xl  = (__nv_bfloat16*)p;
    cudaGetSymbolAddress(&p, g_ch);   __nv_bfloat16* ch  = (__nv_bfloat16*)p;
    cudaGetSymbolAddress(&p, g_cl);   __nv_bfloat16* cl  = (__nv_bfloat16*)p;
    cudaGetSymbolAddress(&p, g_ffh);  __nv_bfloat16* ffh = (__nv_bfloat16*)p;
    cudaGetSymbolAddress(&p, g_ffl);  __nv_bfloat16* ffl = (__nv_bfloat16*)p;
    cudaGetSymbolAddress(&p, g_wh);   __nv_bfloat16* wh  = (__nv_bfloat16*)p;
    cudaGetSymbolAddress(&p, g_wl);   __nv_bfloat16* wl  = (__nv_bfloat16*)p;

    tok_conv_kernel<<<S0, 128>>>(x_enc, tok_w, x, xh, xl);

    int L = S0;
    for (int l = 0; l < ELAY; l++) {
        int U = (l == 0) ? 24 : 21;
        int u = U;
        int Mrows = BATCH * L;
        const float* Wq_l = Wq + (size_t)l * DMODEL * DMODEL;
        const float* Wk_l = Wk + (size_t)l * DMODEL * DMODEL;
        const float* Wv_l = Wv + (size_t)l * DMODEL * DMODEL;
        const float* Wo_l = Wo + (size_t)l * DMODEL * DMODEL;
        const float* w1_l = conv1_w + (size_t)l * DFF * DMODEL;
        const float* w2_l = conv2_w + (size_t)l * DMODEL * DFF;

        // fused QKV projection (N = 1536)
        concat_bias<<<6, 256>>>(bq + l * DMODEL, bk + l * DMODEL, bv + l * DMODEL, bqkv);
        cvt_qkv<<<(3 * DMODEL * DMODEL + 255) / 256, 256>>>(Wq_l, Wk_l, Wv_l, wh, wl);
        run_gemm(xh, xl, wh, wl, bqkv, 0, qkv, 0, 0, Mrows, QS, DMODEL, GF_WRF);

        // threefry key derivation (host)
        uint32_t ka, kb; threefry2x32(0u, 42u, 0u, (uint32_t)l, ka, kb);
        uint32_t k2a, k2b;
        threefry2x32(ka, kb, 0u, 1u, k2a, k2b);

        m2_kernel<<<BATCH * L / 8, 256>>>(qkv, k2a, k2b, Mb, L, U);
        topk_kernel<<<BATCH * NH, 1024>>>(Mb, top, L, u);
        clear_sel_kernel<<<(BATCH * NH * L + 255) / 256, 256>>>(sel, BATCH * NH * L);
        scatter_sel_kernel<<<(BATCH * NH * u + 255) / 256, 256>>>(top, sel, L, u);
        attn_kernel<<<dim3(NH, BATCH, ASPL), 256, ASM_BYTES>>>(qkv, top, updp, mlp, vsp, L, u);
        attn_merge_kernel<<<BATCH * NH, 256>>>(updp, mlp, vsp, upd, vme, L, u);
        assemble_ctx_kernel<<<(BATCH * L * DMODEL + 255) / 256, 256>>>(sel, upd, vme, ch, cl, L, u);

        // O projection + residual, LN1
        cvt_split<<<(DMODEL * DMODEL + 255) / 256, 256>>>(Wo_l, wh, wl, DMODEL * DMODEL);
        run_gemm(ch, cl, wh, wl, bo + l * DMODEL, x, t2, 0, 0, Mrows, DMODEL, DMODEL, GF_RES | GF_WRF);
        layernorm_kernel<<<Mrows, 128>>>(t2, ln1_g + l * DMODEL, ln1_b + l * DMODEL, x, xh, xl);

        // FFN
        cvt_split<<<(DFF * DMODEL + 255) / 256, 256>>>(w1_l, wh, wl, DFF * DMODEL);
        run_gemm(xh, xl, wh, wl, conv1_b + l * DFF, 0, 0, ffh, ffl, Mrows, DFF, DMODEL, GF_GELU | GF_SPLIT);
        cvt_split<<<(DMODEL * DFF + 255) / 256, 256>>>(w2_l, wh, wl, DMODEL * DFF);
        run_gemm(ffh, ffl, wh, wl, conv2_b + l * DMODEL, x, t2, 0, 0, Mrows, DMODEL, DFF, GF_RES | GF_WRF);
        layernorm_kernel<<<Mrows, 128>>>(t2, ln2_g + l * DMODEL, ln2_b + l * DMODEL, x, xh, xl);

        // distillation
        if (l < ELAY - 1) {
            const float* dw = dconv_w + (size_t)l * DMODEL * DMODEL * 3;
            cvt_dconv<<<(3 * DMODEL * DMODEL + 255) / 256, 256>>>(dw, wh, wl);
            run_gemm(xh, xl, wh, wl, dconv_b + l * DMODEL, 0, t2, 0, 0,
                     Mrows, DMODEL, DMODEL, GF_CIRC | GF_WRF, 3, L);
            bn_partial_kernel<<<64, DMODEL>>>(t2, bnp, Mrows / 64);
            bn_final_kernel<<<1, DMODEL>>>(bnp, bns, Mrows);
            bn_elu_maxpool_kernel<<<(BATCH * (L / 2) * DMODEL + 255) / 256, 256>>>(
                t2, bns, bn_g + l * DMODEL, bn_b + l * DMODEL, x, xh, xl, L);
            L /= 2;
        }
    }

    layernorm_kernel<<<BATCH * L, 128>>>(x, lnf_g, lnf_b, t2, 0, 0);
    head_kernel<<<(BATCH * L * NCOUT + 255) / 256, 256>>>(t2, end_w, end_b, out, BATCH * L);
}

// round 15
// speedup vs baseline: 1.6598x; 1.0319x over previous
#include <cuda_runtime.h>
#include <cuda_bf16.h>
#include <math.h>
#include <stdint.h>
#include <float.h>

#define BATCH 8
#define S0    2048
#define DMODEL 512
#define NH    8
#define HD    64
#define DFF   2048
#define ELAY  3
#define NCOUT 7
#define UMAX  24
#define QS    1536   // packed qkv row stride
#define ASPL  4      // attention KV splits

// ------------------------- scratch (device globals) --------------------------
__device__ float g_x  [BATCH*S0*DMODEL];
__device__ float g_t2 [BATCH*S0*DMODEL];
__device__ float g_qkv[BATCH*S0*QS];
__device__ float g_M  [BATCH*NH*S0];
__device__ int   g_top[BATCH*NH*UMAX];
__device__ int   g_sel[BATCH*NH*S0];
__device__ float g_vme[BATCH*NH*HD];
__device__ float g_upd[BATCH*NH*UMAX*HD];
__device__ float g_updp[BATCH*NH*ASPL*UMAX*HD];
__device__ float g_mlp [BATCH*NH*ASPL*2*UMAX];
__device__ float g_vsp [BATCH*NH*ASPL*HD];
__device__ float g_bnp[64*DMODEL*2];
__device__ float g_bns[DMODEL*2];
__device__ float g_bqkv[QS];
__device__ __nv_bfloat16 g_xh [BATCH*S0*DMODEL];
__device__ __nv_bfloat16 g_xl [BATCH*S0*DMODEL];
__device__ __nv_bfloat16 g_ch [BATCH*S0*DMODEL];
__device__ __nv_bfloat16 g_cl [BATCH*S0*DMODEL];
__device__ __nv_bfloat16 g_ffh[BATCH*S0*DFF];
__device__ __nv_bfloat16 g_ffl[BATCH*S0*DFF];
__device__ __nv_bfloat16 g_wh [DFF*DMODEL];
__device__ __nv_bfloat16 g_wl [DFF*DMODEL];

// ------------------------- threefry2x32 --------------------------------------
__host__ __device__ __forceinline__ void tf_round(uint32_t& x0, uint32_t& x1, int r) {
    x0 += x1; x1 = (x1 << r) | (x1 >> (32 - r)); x1 ^= x0;
}
__host__ __device__ inline void threefry2x32(uint32_t k0, uint32_t k1,
                                             uint32_t c0, uint32_t c1,
                                             uint32_t& o0, uint32_t& o1) {
    uint32_t ks2 = k0 ^ k1 ^ 0x1BD11BDAu;
    uint32_t x0 = c0 + k0, x1 = c1 + k1;
    tf_round(x0,x1,13); tf_round(x0,x1,15); tf_round(x0,x1,26); tf_round(x0,x1,6);
    x0 += k1;  x1 += ks2 + 1u;
    tf_round(x0,x1,17); tf_round(x0,x1,29); tf_round(x0,x1,16); tf_round(x0,x1,24);
    x0 += ks2; x1 += k0 + 2u;
    tf_round(x0,x1,13); tf_round(x0,x1,15); tf_round(x0,x1,26); tf_round(x0,x1,6);
    x0 += k0;  x1 += k1 + 3u;
    tf_round(x0,x1,17); tf_round(x0,x1,29); tf_round(x0,x1,16); tf_round(x0,x1,24);
    x0 += k1;  x1 += ks2 + 4u;
    tf_round(x0,x1,13); tf_round(x0,x1,15); tf_round(x0,x1,26); tf_round(x0,x1,6);
    x0 += ks2; x1 += k0 + 5u;
    o0 = x0; o1 = x1;
}

// ------------------------- split helpers -------------------------------------
__device__ __forceinline__ void split_bf16(float v, __nv_bfloat16& h, __nv_bfloat16& l) {
    h = __float2bfloat16(v);
    l = __float2bfloat16(v - __bfloat162float(h));
}
__global__ void cvt_split(const float* __restrict__ x, __nv_bfloat16* __restrict__ h,
                          __nv_bfloat16* __restrict__ l, int n) {
    int i = blockIdx.x * 256 + threadIdx.x;
    if (i >= n) return;
    split_bf16(x[i], h[i], l[i]);
}
__global__ void cvt_qkv(const float* __restrict__ Wq, const float* __restrict__ Wk,
                        const float* __restrict__ Wv, __nv_bfloat16* __restrict__ h,
                        __nv_bfloat16* __restrict__ l) {
    int i = blockIdx.x * 256 + threadIdx.x;
    if (i >= 3 * DMODEL * DMODEL) return;
    int r = i / DMODEL, c = i - r * DMODEL;
    const float* W = (r < DMODEL) ? Wq : (r < 2 * DMODEL) ? Wk : Wv;
    int rr = r & (DMODEL - 1);
    split_bf16(W[rr * DMODEL + c], h[i], l[i]);
}
__global__ void concat_bias(const float* __restrict__ bq, const float* __restrict__ bk,
                            const float* __restrict__ bv, float* __restrict__ dst) {
    int i = blockIdx.x * 256 + threadIdx.x;
    if (i >= QS) return;
    dst[i] = (i < DMODEL) ? bq[i] : (i < 2 * DMODEL) ? bk[i - DMODEL] : bv[i - 2 * DMODEL];
}
__global__ void cvt_dconv(const float* __restrict__ w, __nv_bfloat16* __restrict__ h,
                          __nv_bfloat16* __restrict__ l) {
    int i = blockIdx.x * 256 + threadIdx.x;
    if (i >= 3 * DMODEL * DMODEL) return;
    int tap = i / (DMODEL * DMODEL);
    int r = i - tap * DMODEL * DMODEL;
    split_bf16(w[(size_t)r * 3 + tap], h[i], l[i]);
}

// ------------------------- mma.sync GEMM (frozen) ----------------------------
#define GF_GELU   1
#define GF_RES    2
#define GF_CIRC   8
#define GF_WRF    32
#define GF_SPLIT  64

#define BM 128
#define BN 128
#define BK 32
#define SSTRIDE 40
#define TSZ (128 * SSTRIDE * 2)
#define STAGE_BYTES (4 * TSZ)
#define GSMEM (2 * STAGE_BYTES)

__device__ __forceinline__ void load_chunk2(
    const __nv_bfloat16* __restrict__ Ah, const __nv_bfloat16* __restrict__ Al,
    const __nv_bfloat16* __restrict__ Bh, const __nv_bfloat16* __restrict__ Bl,
    char* dynsm, int buf, int c, int nkc, int K, int N,
    int m0, int n0, int flags, int Lb, int tid)
{
    int tap = c / nkc;
    int kc = c - tap * nkc;
    int k0 = kc * BK;
    int shift = (flags & GF_CIRC) ? (tap - 1) : 0;
    char* st = dynsm + buf * STAGE_BYTES;
    const __nv_bfloat16* Bht = Bh + (size_t)tap * N * K;
    const __nv_bfloat16* Blt = Bl + (size_t)tap * N * K;
    #pragma unroll 2
    for (int i = tid; i < 512; i += 256) {
        int row = i >> 2, seg = i & 3;
        int gm = m0 + row, arow = gm;
        if (flags & GF_CIRC) {
            int b = gm / Lb, t = gm - b * Lb + shift;
            if (t < 0) t += Lb; else if (t >= Lb) t -= Lb;
            arow = b * Lb + t;
        }
        size_t so = (size_t)arow * K + k0 + seg * 8;
        uint32_t d = (uint32_t)__cvta_generic_to_shared(st + row * (SSTRIDE * 2) + seg * 16);
        asm volatile("cp.async.cg.shared.global [%0], [%1], 16;" :: "r"(d), "l"(Ah + so));
        asm volatile("cp.async.cg.shared.global [%0], [%1], 16;" :: "r"(d + TSZ), "l"(Al + so));
    }
    #pragma unroll 2
    for (int i = tid; i < 512; i += 256) {
        int row = i >> 2, seg = i & 3;
        size_t so = (size_t)(n0 + row) * K + k0 + seg * 8;
        uint32_t d = (uint32_t)__cvta_generic_to_shared(st + 2 * TSZ + row * (SSTRIDE * 2) + seg * 16);
        asm volatile("cp.async.cg.shared.global [%0], [%1], 16;" :: "r"(d), "l"(Bht + so));
        asm volatile("cp.async.cg.shared.global [%0], [%1], 16;" :: "r"(d + TSZ), "l"(Blt + so));
    }
    asm volatile("cp.async.commit_group;");
}

__global__ __launch_bounds__(256)
void mma_gemm(const __nv_bfloat16* __restrict__ Ah, const __nv_bfloat16* __restrict__ Al,
              const __nv_bfloat16* __restrict__ Bh, const __nv_bfloat16* __restrict__ Bl,
              const float* __restrict__ bias, const float* __restrict__ R,
              float* __restrict__ C, __nv_bfloat16* __restrict__ Ch, __nv_bfloat16* __restrict__ Cl,
              int M, int N, int K, int flags, int ntaps, int Lb)
{
    extern __shared__ __align__(16) char dynsm[];
    int tid = threadIdx.x, lane = tid & 31, wid = tid >> 5;
    int warp_m = wid & 1, warp_n = wid >> 1;
    int m0 = blockIdx.y * BM, n0 = blockIdx.x * BN;

    float acc[4][4][4];
    #pragma unroll
    for (int mi = 0; mi < 4; mi++)
        #pragma unroll
        for (int ni = 0; ni < 4; ni++)
            #pragma unroll
            for (int e = 0; e < 4; e++) acc[mi][ni][e] = 0.f;

    const int nkc = K / BK;
    const int nch = nkc * ntaps;

    load_chunk2(Ah, Al, Bh, Bl, dynsm, 0, 0, nkc, K, N, m0, n0, flags, Lb, tid);

    uint32_t smb = (uint32_t)__cvta_generic_to_shared(dynsm);
    int a_row = warp_m * 64 + (lane & 15);
    int a_col = (lane >> 4) * 8;
    int b_row = warp_n * 32 + (lane & 7) + ((lane >> 4) * 8);
    int b_col = ((lane >> 3) & 1) * 8;

    for (int c = 0; c < nch; c++) {
        if (c + 1 < nch) {
            load_chunk2(Ah, Al, Bh, Bl, dynsm, (c + 1) & 1, c + 1, nkc, K, N, m0, n0, flags, Lb, tid);
            asm volatile("cp.async.wait_group 1;");
        } else {
            asm volatile("cp.async.wait_group 0;");
        }
        __syncthreads();
        uint32_t ab = smb + (c & 1) * STAGE_BYTES;
        #pragma unroll
        for (int ks = 0; ks < 2; ks++) {
            uint32_t ah[4][4], al[4][4];
            #pragma unroll
            for (int mi = 0; mi < 4; mi++) {
                uint32_t addr = ab + ((a_row + mi * 16) * SSTRIDE + ks * 16 + a_col) * 2;
                asm volatile("ldmatrix.sync.aligned.m8n8.x4.shared.b16 {%0,%1,%2,%3}, [%4];"
                    : "=r"(ah[mi][0]), "=r"(ah[mi][1]), "=r"(ah[mi][2]), "=r"(ah[mi][3]) : "r"(addr));
                asm volatile("ldmatrix.sync.aligned.m8n8.x4.shared.b16 {%0,%1,%2,%3}, [%4];"
                    : "=r"(al[mi][0]), "=r"(al[mi][1]), "=r"(al[mi][2]), "=r"(al[mi][3]) : "r"(addr + TSZ));
            }
            uint32_t bh[4][2], bl[4][2];
            #pragma unroll
            for (int nf2 = 0; nf2 < 2; nf2++) {
                uint32_t r0, r1, r2, r3;
                uint32_t addr = ab + 2 * TSZ + ((b_row + nf2 * 16) * SSTRIDE + ks * 16 + b_col) * 2;
                asm volatile("ldmatrix.sync.aligned.m8n8.x4.shared.b16 {%0,%1,%2,%3}, [%4];"
                    : "=r"(r0), "=r"(r1), "=r"(r2), "=r"(r3) : "r"(addr));
                bh[nf2 * 2][0] = r0;     bh[nf2 * 2][1] = r1;
                bh[nf2 * 2 + 1][0] = r2; bh[nf2 * 2 + 1][1] = r3;
                asm volatile("ldmatrix.sync.aligned.m8n8.x4.shared.b16 {%0,%1,%2,%3}, [%4];"
                    : "=r"(r0), "=r"(r1), "=r"(r2), "=r"(r3) : "r"(addr + TSZ));
                bl[nf2 * 2][0] = r0;     bl[nf2 * 2][1] = r1;
                bl[nf2 * 2 + 1][0] = r2; bl[nf2 * 2 + 1][1] = r3;
            }
            #pragma unroll
            for (int mi = 0; mi < 4; mi++)
                #pragma unroll
                for (int ni = 0; ni < 4; ni++)
                    asm volatile("mma.sync.aligned.m16n8k16.row.col.f32.bf16.bf16.f32 "
                        "{%0,%1,%2,%3}, {%4,%5,%6,%7}, {%8,%9}, {%0,%1,%2,%3};"
                        : "+f"(acc[mi][ni][0]), "+f"(acc[mi][ni][1]), "+f"(acc[mi][ni][2]), "+f"(acc[mi][ni][3])
                        : "r"(ah[mi][0]), "r"(ah[mi][1]), "r"(ah[mi][2]), "r"(ah[mi][3]),
                          "r"(bh[ni][0]), "r"(bh[ni][1]));
            #pragma unroll
            for (int mi = 0; mi < 4; mi++)
                #pragma unroll
                for (int ni = 0; ni < 4; ni++)
                    asm volatile("mma.sync.aligned.m16n8k16.row.col.f32.bf16.bf16.f32 "
                        "{%0,%1,%2,%3}, {%4,%5,%6,%7}, {%8,%9}, {%0,%1,%2,%3};"
                        : "+f"(acc[mi][ni][0]), "+f"(acc[mi][ni][1]), "+f"(acc[mi][ni][2]), "+f"(acc[mi][ni][3])
                        : "r"(ah[mi][0]), "r"(ah[mi][1]), "r"(ah[mi][2]), "r"(ah[mi][3]),
                          "r"(bl[ni][0]), "r"(bl[ni][1]));
            #pragma unroll
            for (int mi = 0; mi < 4; mi++)
                #pragma unroll
                for (int ni = 0; ni < 4; ni++)
                    asm volatile("mma.sync.aligned.m16n8k16.row.col.f32.bf16.bf16.f32 "
                        "{%0,%1,%2,%3}, {%4,%5,%6,%7}, {%8,%9}, {%0,%1,%2,%3};"
                        : "+f"(acc[mi][ni][0]), "+f"(acc[mi][ni][1]), "+f"(acc[mi][ni][2]), "+f"(acc[mi][ni][3])
                        : "r"(al[mi][0]), "r"(al[mi][1]), "r"(al[mi][2]), "r"(al[mi][3]),
                          "r"(bh[ni][0]), "r"(bh[ni][1]));
        }
        __syncthreads();
    }

    // epilogue
    #pragma unroll
    for (int mi = 0; mi < 4; mi++) {
        #pragma unroll
        for (int ni = 0; ni < 4; ni++) {
            int gm0 = m0 + warp_m * 64 + mi * 16 + (lane >> 2);
            int gn  = n0 + warp_n * 32 + ni * 8 + (lane & 3) * 2;
            float2 bs = *(const float2*)&bias[gn];
            #pragma unroll
            for (int h = 0; h < 2; h++) {
                int gm = gm0 + h * 8;
                float2 v = make_float2(acc[mi][ni][h * 2], acc[mi][ni][h * 2 + 1]);
                v.x += bs.x; v.y += bs.y;
                if (flags & GF_GELU) {
                    v.x = 0.5f * v.x * (1.0f + erff(v.x * 0.7071067811865475f));
                    v.y = 0.5f * v.y * (1.0f + erff(v.y * 0.7071067811865475f));
                }
                if (flags & GF_RES) {
                    float2 rv = *(const float2*)&R[(size_t)gm * N + gn];
                    v.x += rv.x; v.y += rv.y;
                }
                if (flags & GF_WRF) *(float2*)&C[(size_t)gm * N + gn] = v;
                if (flags & GF_SPLIT) {
                    __nv_bfloat16 h0, l0, h1, l1;
                    split_bf16(v.x, h0, l0); split_bf16(v.y, h1, l1);
                    __nv_bfloat162 hv; hv.x = h0; hv.y = h1;
                    __nv_bfloat162 lv; lv.x = l0; lv.y = l1;
                    *(__nv_bfloat162*)&Ch[(size_t)gm * N + gn] = hv;
                    *(__nv_bfloat162*)&Cl[(size_t)gm * N + gn] = lv;
                }
            }
        }
    }
}

// ------------------------- token conv + positional embedding -----------------
__global__ void tok_conv_kernel(const float* __restrict__ xe, const float* __restrict__ w,
                                float* __restrict__ out, __nv_bfloat16* __restrict__ oh,
                                __nv_bfloat16* __restrict__ ol) {
    int t = blockIdx.x;
    __shared__ float xs[BATCH][21];
    int tid = threadIdx.x;
    for (int j = tid; j < BATCH * 21; j += 128) {
        int b = j / 21, jj = j % 21;
        int kk = jj / 7, i = jj % 7;
        int tt = t + kk - 1;
        if (tt < 0) tt += S0; else if (tt >= S0) tt -= S0;
        xs[b][kk * 7 + i] = xe[(size_t)(b * S0 + tt) * 7 + i];
    }
    __syncthreads();
    for (int o = tid; o < DMODEL; o += 128) {
        float wreg[21];
        const float* wo = w + o * 21;
        #pragma unroll
        for (int j = 0; j < 21; j++) wreg[j] = wo[j];
        int e = o & ~1;
        float dv = expf((float)e * -0.017988946038918563f);
        float ang = (float)t * dv;
        float pe = (o & 1) ? cosf(ang) : sinf(ang);
        #pragma unroll
        for (int b = 0; b < BATCH; b++) {
            float acc = pe;
            #pragma unroll
            for (int i = 0; i < 7; i++)
                #pragma unroll
                for (int kk = 0; kk < 3; kk++) acc += xs[b][kk * 7 + i] * wreg[i * 3 + kk];
            size_t oi = (size_t)(b * S0 + t) * DMODEL + o;
            out[oi] = acc;
            split_bf16(acc, oh[oi], ol[oi]);
        }
    }
}

// ------------------------- ProbSparse M: head-shared K rows (v2) -------------
// One warp per (b, l). Q row held in registers (loaded once). Per sample:
// coalesced warp load of the K row; 4 static per-segment partials; half-warp
// butterfly + one cross-half exchange gives every lane both head sums of each
// segment with STATIC indices (no local-memory arrays).
__global__ void m2_kernel(const float* __restrict__ qkv, uint32_t ka, uint32_t kb,
                          float* __restrict__ Mo, int L, int U) {
    int wid = threadIdx.x >> 5, lane = threadIdx.x & 31;
    int gw = blockIdx.x * 8 + wid;
    int b = gw / L;
    int l = gw - b * L;
    const float4* qsrc = (const float4*)&qkv[(size_t)(b * L + l) * QS];
    const float4 q0 = qsrc[lane];
    const float4 q1 = qsrc[32 + lane];
    const float4 q2 = qsrc[64 + lane];
    const float4 q3 = qsrc[96 + lane];
    int hiHalf = lane >> 4;   // 0: heads {0,2,4,6}; 1: heads {1,3,5,7} per segment

    float mx[NH], sm[NH];
    #pragma unroll
    for (int h = 0; h < NH; h++) { mx[h] = -FLT_MAX; sm[h] = 0.f; }

    for (int s = 0; s < U; s++) {
        int j = l * U + s;
        uint32_t o0, o1;
        threefry2x32(ka, kb, 0u, (uint32_t)j, o0, o1);
        int kr = (int)((o0 ^ o1) & (uint32_t)(L - 1));
        const float4* ksrc = (const float4*)&qkv[(size_t)(b * L + kr) * QS + DMODEL];
        float4 k0 = ksrc[lane];
        float4 k1 = ksrc[32 + lane];
        float4 k2 = ksrc[64 + lane];
        float4 k3 = ksrc[96 + lane];
        float p0 = q0.x * k0.x + q0.y * k0.y + q0.z * k0.z + q0.w * k0.w;
        float p1 = q1.x * k1.x + q1.y * k1.y + q1.z * k1.z + q1.w * k1.w;
        float p2 = q2.x * k2.x + q2.y * k2.y + q2.z * k2.z + q2.w * k2.w;
        float p3 = q3.x * k3.x + q3.y * k3.y + q3.z * k3.z + q3.w * k3.w;
        // reduce within each 16-lane half (segment seg: lanes 0-15 -> head 2*seg,
        // lanes 16-31 -> head 2*seg+1)
        #pragma unroll
        for (int off = 8; off; off >>= 1) {
            p0 += __shfl_xor_sync(0xffffffffu, p0, off);
            p1 += __shfl_xor_sync(0xffffffffu, p1, off);
            p2 += __shfl_xor_sync(0xffffffffu, p2, off);
            p3 += __shfl_xor_sync(0xffffffffu, p3, off);
        }
        // exchange across halves: every lane gets both head sums per segment
        float o0f = __shfl_xor_sync(0xffffffffu, p0, 16);
        float o1f = __shfl_xor_sync(0xffffffffu, p1, 16);
        float o2f = __shfl_xor_sync(0xffffffffu, p2, 16);
        float o3f = __shfl_xor_sync(0xffffffffu, p3, 16);
        float he0 = hiHalf ? o0f : p0;   // head 0
        float ho0 = hiHalf ? p0 : o0f;   // head 1
        float he1 = hiHalf ? o1f : p1;   // head 2
        float ho1 = hiHalf ? p1 : o1f;   // head 3
        float he2 = hiHalf ? o2f : p2;   // head 4
        float ho2 = hiHalf ? p2 : o2f;   // head 5
        float he3 = hiHalf ? o3f : p3;   // head 6
        float ho3 = hiHalf ? p3 : o3f;   // head 7
        mx[0] = fmaxf(mx[0], he0); sm[0] += he0;
        mx[1] = fmaxf(mx[1], ho0); sm[1] += ho0;
        mx[2] = fmaxf(mx[2], he1); sm[2] += he1;
        mx[3] = fmaxf(mx[3], ho1); sm[3] += ho1;
        mx[4] = fmaxf(mx[4], he2); sm[4] += he2;
        mx[5] = fmaxf(mx[5], ho2); sm[5] += ho2;
        mx[6] = fmaxf(mx[6], he3); sm[6] += he3;
        mx[7] = fmaxf(mx[7], ho3); sm[7] += ho3;
    }
    if (lane == 0) {
        #pragma unroll
        for (int h = 0; h < NH; h++)
            Mo[(b * NH + h) * L + l] = mx[h] - sm[h] / (float)L;
    }
}

__global__ void topk_kernel(const float* __restrict__ Mi, int* __restrict__ top,
                            int L, int u) {
    int bh = blockIdx.x, tid = threadIdx.x;
    int lane = tid & 31, warp = tid >> 5;
    __shared__ float sv[S0];
    __shared__ float wv[32];
    __shared__ int   wi[32];
    const float* m = Mi + (size_t)bh * L;
    for (int i = tid; i < L; i += 1024) sv[i] = m[i];
    __syncthreads();
    for (int it = 0; it < u; it++) {
        float best = -FLT_MAX; int besti = L;
        for (int i = tid; i < L; i += 1024) {
            float v = sv[i];
            if (v > best) { best = v; besti = i; }
        }
        #pragma unroll
        for (int off = 16; off; off >>= 1) {
            float ov = __shfl_xor_sync(0xffffffffu, best, off);
            int   oi = __shfl_xor_sync(0xffffffffu, besti, off);
            if (ov > best || (ov == best && oi < besti)) { best = ov; besti = oi; }
        }
        if (lane == 0) { wv[warp] = best; wi[warp] = besti; }
        __syncthreads();
        if (warp == 0) {
            best = wv[lane]; besti = wi[lane];
            #pragma unroll
            for (int off = 16; off; off >>= 1) {
                float ov = __shfl_xor_sync(0xffffffffu, best, off);
                int   oi = __shfl_xor_sync(0xffffffffu, besti, off);
                if (ov > best || (ov == best && oi < besti)) { best = ov; besti = oi; }
            }
            if (lane == 0) { top[bh * u + it] = besti; sv[besti] = -FLT_MAX; }
        }
        __syncthreads();
    }
}

__global__ void clear_sel_kernel(int* __restrict__ sel, int n) {
    int i = blockIdx.x * blockDim.x + threadIdx.x;
    if (i < n) sel[i] = 0;
}
__global__ void scatter_sel_kernel(const int* __restrict__ top, int* __restrict__ sel,
                                   int L, int u) {
    int i = blockIdx.x * blockDim.x + threadIdx.x;
    if (i >= BATCH * NH * u) return;
    int bh = i / u, ui = i % u;
    sel[(size_t)bh * L + top[bh * u + ui]] = ui + 1;
}

// ------------------------- split-KV flash attention + vmean ------------------
#define ATK 128
#define KSTR 68
#define ASM_FLOATS (2*ATK*KSTR + UMAX*ATK + 2*UMAX*HD + 2*UMAX + HD)
#define ASM_BYTES (ASM_FLOATS * 4)

__global__ void attn_kernel(const float* __restrict__ qkv, const int* __restrict__ top,
                            float* __restrict__ updp, float* __restrict__ mlp,
                            float* __restrict__ vsp, int L, int u) {
    extern __shared__ float sm[];
    float* Kt   = sm;
    float* Vt   = Kt + ATK * KSTR;
    float* sc   = Vt + ATK * KSTR;
    float* qs   = sc + UMAX * ATK;
    float* accs = qs + UMAX * HD;
    float* mst  = accs + UMAX * HD;
    float* lst  = mst + UMAX;
    float* vsum = lst + UMAX;
    int h = blockIdx.x, b = blockIdx.y, z = blockIdx.z;
    int bh = b * NH + h;
    int bhz = bh * ASPL + z;
    int Lc = L / ASPL;
    int tbase = z * Lc;
    int tid = threadIdx.x, lane = tid & 31, warp = tid >> 5;

    for (int i = tid; i < u * HD; i += 256) {
        int q = i >> 6, d = i & 63;
        int qrow = top[bh * u + q];
        qs[q * HD + d] = qkv[(size_t)(b * L + qrow) * QS + h * HD + d];
        accs[i] = 0.f;
    }
    if (tid < UMAX) { mst[tid] = -FLT_MAX; lst[tid] = 0.f; }
    if (tid < HD) vsum[tid] = 0.f;
    __syncthreads();

    for (int t0 = tbase; t0 < tbase + Lc; t0 += ATK) {
        for (int i = tid; i < ATK * 16; i += 256) {
            int row = i >> 4, seg = i & 15;
            const float* base = &qkv[(size_t)(b * L + t0 + row) * QS + DMODEL + h * HD + seg * 4];
            *(float4*)&Kt[row * KSTR + seg * 4] = *(const float4*)base;
            *(float4*)&Vt[row * KSTR + seg * 4] = *(const float4*)(base + DMODEL);
        }
        __syncthreads();
        if (tid < HD) {
            float s = 0.f;
            for (int k = 0; k < ATK; k++) s += Vt[k * KSTR + tid];
            vsum[tid] += s;
        }
        for (int i = tid; i < u * ATK; i += 256) {
            int q = i >> 7, k = i & (ATK - 1);
            const float* qp = &qs[q * HD];
            const float* kp = &Kt[k * KSTR];
            float acc = 0.f;
            #pragma unroll
            for (int d4 = 0; d4 < 16; d4++) {
                float4 a = *(const float4*)&qp[d4 * 4];
                float4 c = *(const float4*)&kp[d4 * 4];
                acc += a.x * c.x + a.y * c.y + a.z * c.z + a.w * c.w;
            }
            sc[q * ATK + k] = acc * 0.125f;
        }
        __syncthreads();
        #pragma unroll
        for (int qi = 0; qi < 3; qi++) {
            int q = warp * 3 + qi;
            if (q < u) {
                float s0 = sc[q * ATK + lane],      s1 = sc[q * ATK + 32 + lane];
                float s2 = sc[q * ATK + 64 + lane], s3 = sc[q * ATK + 96 + lane];
                float tm = fmaxf(fmaxf(s0, s1), fmaxf(s2, s3));
                #pragma unroll
                for (int off = 16; off; off >>= 1)
                    tm = fmaxf(tm, __shfl_xor_sync(0xffffffffu, tm, off));
                float mold = mst[q];
                float newm = fmaxf(mold, tm);
                float alpha = expf(mold - newm);
                float p0 = expf(s0 - newm), p1 = expf(s1 - newm);
                float p2 = expf(s2 - newm), p3 = expf(s3 - newm);
                sc[q * ATK + lane] = p0;      sc[q * ATK + 32 + lane] = p1;
                sc[q * ATK + 64 + lane] = p2; sc[q * ATK + 96 + lane] = p3;
                float ls = p0 + p1 + p2 + p3;
                #pragma unroll
                for (int off = 16; off; off >>= 1)
                    ls += __shfl_xor_sync(0xffffffffu, ls, off);
                if (lane == 0) { lst[q] = lst[q] * alpha + ls; mst[q] = newm; }
                __syncwarp();
                #pragma unroll
                for (int dd = 0; dd < 2; dd++) {
                    int d = lane + dd * 32;
                    float a = accs[q * HD + d] * alpha;
                    for (int k = 0; k < ATK; k++)
                        a += sc[q * ATK + k] * Vt[k * KSTR + d];
                    accs[q * HD + d] = a;
                }
            }
        }
        __syncthreads();
    }
    #pragma unroll
    for (int qi = 0; qi < 3; qi++) {
        int q = warp * 3 + qi;
        if (q < u) {
            updp[((size_t)bhz * UMAX + q) * HD + lane]      = accs[q * HD + lane];
            updp[((size_t)bhz * UMAX + q) * HD + lane + 32] = accs[q * HD + lane + 32];
            if (lane == 0) {
                mlp[bhz * 2 * UMAX + q]        = mst[q];
                mlp[bhz * 2 * UMAX + UMAX + q] = lst[q];
            }
        }
    }
    if (tid < HD) vsp[bhz * HD + tid] = vsum[tid];
}

__global__ void attn_merge_kernel(const float* __restrict__ updp, const float* __restrict__ mlp,
                                  const float* __restrict__ vsp, float* __restrict__ upd,
                                  float* __restrict__ vme, int L, int u) {
    int bh = blockIdx.x, tid = threadIdx.x;
    for (int i = tid; i < u * HD; i += 256) {
        int q = i >> 6, d = i & 63;
        float M = -FLT_MAX;
        #pragma unroll
        for (int z = 0; z < ASPL; z++)
            M = fmaxf(M, mlp[(bh * ASPL + z) * 2 * UMAX + q]);
        float lsum = 0.f, asum = 0.f;
        #pragma unroll
        for (int z = 0; z < ASPL; z++) {
            int bhz = bh * ASPL + z;
            float w = expf(mlp[bhz * 2 * UMAX + q] - M);
            lsum += mlp[bhz * 2 * UMAX + UMAX + q] * w;
            asum += updp[((size_t)bhz * UMAX + q) * HD + d] * w;
        }
        upd[((size_t)bh * u + q) * HD + d] = asum / lsum;
    }
    if (tid < HD) {
        float s = 0.f;
        #pragma unroll
        for (int z = 0; z < ASPL; z++) s += vsp[(bh * ASPL + z) * HD + tid];
        vme[bh * HD + tid] = s / (float)L;
    }
}

__global__ void assemble_ctx_kernel(const int* __restrict__ sel, const float* __restrict__ upd,
                                    const float* __restrict__ vm,
                                    __nv_bfloat16* __restrict__ ch, __nv_bfloat16* __restrict__ cl,
                                    int L, int u) {
    int i = blockIdx.x * blockDim.x + threadIdx.x;
    int total = BATCH * L * DMODEL;
    if (i >= total) return;
    int b = i / (L * DMODEL);
    int r = i - b * L * DMODEL;
    int l = r / DMODEL;
    int c = r - l * DMODEL;
    int h = c / HD, d = c - h * HD;
    int bh = b * NH + h;
    int s = sel[(size_t)bh * L + l];
    float val = s ? upd[((size_t)bh * u + (s - 1)) * HD + d] : vm[bh * HD + d];
    split_bf16(val, ch[i], cl[i]);
}

// ------------------------- layernorm -----------------------------------------
__global__ void layernorm_kernel(const float* __restrict__ in, const float* __restrict__ g,
                                 const float* __restrict__ bb, float* __restrict__ out,
                                 __nv_bfloat16* __restrict__ oh, __nv_bfloat16* __restrict__ ol) {
    int row = blockIdx.x, tid = threadIdx.x;
    __shared__ float red[128];
    const float4 v = ((const float4*)(in + (size_t)row * DMODEL))[tid];
    red[tid] = v.x + v.y + v.z + v.w;
    __syncthreads();
    for (int s = 64; s > 0; s >>= 1) { if (tid < s) red[tid] += red[tid + s]; __syncthreads(); }
    float mean = red[0] / (float)DMODEL;
    __syncthreads();
    float dx = v.x - mean, dy = v.y - mean, dz = v.z - mean, dw = v.w - mean;
    red[tid] = dx * dx + dy * dy + dz * dz + dw * dw;
    __syncthreads();
    for (int s = 64; s > 0; s >>= 1) { if (tid < s) red[tid] += red[tid + s]; __syncthreads(); }
    float rstd = rsqrtf(red[0] / (float)DMODEL + 1e-5f);
    const float4 gv = ((const float4*)g)[tid];
    const float4 bv = ((const float4*)bb)[tid];
    float4 o;
    o.x = dx * rstd * gv.x + bv.x;
    o.y = dy * rstd * gv.y + bv.y;
    o.z = dz * rstd * gv.z + bv.z;
    o.w = dw * rstd * gv.w + bv.w;
    ((float4*)(out + (size_t)row * DMODEL))[tid] = o;
    if (oh) {
        size_t base = (size_t)row * DMODEL + tid * 4;
        split_bf16(o.x, oh[base],   ol[base]);
        split_bf16(o.y, oh[base+1], ol[base+1]);
        split_bf16(o.z, oh[base+2], ol[base+2]);
        split_bf16(o.w, oh[base+3], ol[base+3]);
    }
}

// ------------------------- distil helpers ------------------------------------
__global__ void bn_partial_kernel(const float* __restrict__ y, float* __restrict__ part, int rpc) {
    int chunk = blockIdx.x, c = threadIdx.x;
    float s = 0.f, ss = 0.f;
    for (int r = 0; r < rpc; r++) {
        float vv = y[(size_t)(chunk * rpc + r) * DMODEL + c];
        s += vv; ss += vv * vv;
    }
    part[(size_t)chunk * (2 * DMODEL) + c] = s;
    part[(size_t)chunk * (2 * DMODEL) + DMODEL + c] = ss;
}
__global__ void bn_final_kernel(const float* __restrict__ part, float* __restrict__ stat,
                                int Mtot) {
    int c = threadIdx.x;
    float s = 0.f, ss = 0.f;
    #pragma unroll 8
    for (int ch = 0; ch < 64; ch++) {
        s  += part[(size_t)ch * (2 * DMODEL) + c];
        ss += part[(size_t)ch * (2 * DMODEL) + DMODEL + c];
    }
    float mu = s / (float)Mtot;
    stat[c] = mu;
    stat[DMODEL + c] = ss / (float)Mtot - mu * mu;
}
__global__ void bn_elu_maxpool_kernel(const float* __restrict__ y, const float* __restrict__ stat,
                                      const float* __restrict__ g, const float* __restrict__ bb,
                                      float* __restrict__ out,
                                      __nv_bfloat16* __restrict__ oh, __nv_bfloat16* __restrict__ ol,
                                      int L) {
    int Lo = L / 2;
    int i = blockIdx.x * blockDim.x + threadIdx.x;
    int total = BATCH * Lo * DMODEL;
    if (i >= total) return;
    int b = i / (Lo * DMODEL);
    int r = i - b * Lo * DMODEL;
    int t = r / DMODEL;
    int c = r - t * DMODEL;
    float mu = stat[c];
    float rstd = rsqrtf(stat[DMODEL + c] + 1e-5f);
    float gc = g[c], bc = bb[c];
    float m = -FLT_MAX;
    #pragma unroll
    for (int dt = -1; dt <= 1; dt++) {
        int tt = 2 * t + dt;
        if (tt >= 0 && tt < L) {
            float z = (y[(size_t)(b * L + tt) * DMODEL + c] - mu) * rstd * gc + bc;
            z = z > 0.f ? z : expm1f(z);
            m = fmaxf(m, z);
        }
    }
    out[i] = m;
    split_bf16(m, oh[i], ol[i]);
}

// ------------------------- head ----------------------------------------------
__global__ void head_kernel(const float* __restrict__ x, const float* __restrict__ w,
                            const float* __restrict__ eb, float* __restrict__ out, int rows) {
    int i = blockIdx.x * blockDim.x + threadIdx.x;
    if (i >= rows * NCOUT) return;
    int row = i / NCOUT, c = i - row * NCOUT;
    const float* xr = x + (size_t)row * DMODEL;
    const float* wr = w + (size_t)c * DMODEL;
    float acc = eb[c];
    for (int d = 0; d < DMODEL; d++) acc += xr[d] * wr[d];
    out[i] = acc;
}

// ------------------------- host orchestration --------------------------------
static inline void run_gemm(const __nv_bfloat16* Ah, const __nv_bfloat16* Al,
                            const __nv_bfloat16* Bh, const __nv_bfloat16* Bl,
                            const float* bias, const float* R,
                            float* C, __nv_bfloat16* Ch, __nv_bfloat16* Cl,
                            int M, int N, int K, int flags, int ntaps = 1, int Lb = 1) {
    dim3 grid(N / BN, M / BM);
    mma_gemm<<<grid, 256, GSMEM>>>(Ah, Al, Bh, Bl, bias, R, C, Ch, Cl, M, N, K, flags, ntaps, Lb);
}

extern "C" void kernel_launch(void* const* d_in, const int* in_sizes, int n_in,
                              void* d_out, int out_size) {
    (void)in_sizes; (void)n_in; (void)out_size;
    const float* x_enc   = (const float*)d_in[0];
    const float* tok_w   = (const float*)d_in[1];
    const float* Wq      = (const float*)d_in[2];
    const float* bq      = (const float*)d_in[3];
    const float* Wk      = (const float*)d_in[4];
    const float* bk      = (const float*)d_in[5];
    const float* Wv      = (const float*)d_in[6];
    const float* bv      = (const float*)d_in[7];
    const float* Wo      = (const float*)d_in[8];
    const float* bo      = (const float*)d_in[9];
    const float* conv1_w = (const float*)d_in[10];
    const float* conv1_b = (const float*)d_in[11];
    const float* conv2_w = (const float*)d_in[12];
    const float* conv2_b = (const float*)d_in[13];
    const float* ln1_g   = (const float*)d_in[14];
    const float* ln1_b   = (const float*)d_in[15];
    const float* ln2_g   = (const float*)d_in[16];
    const float* ln2_b   = (const float*)d_in[17];
    const float* dconv_w = (const float*)d_in[18];
    const float* dconv_b = (const float*)d_in[19];
    const float* bn_g    = (const float*)d_in[20];
    const float* bn_b    = (const float*)d_in[21];
    const float* lnf_g   = (const float*)d_in[22];
    const float* lnf_b   = (const float*)d_in[23];
    const float* end_w   = (const float*)d_in[24];
    const float* end_b   = (const float*)d_in[25];
    float* out = (float*)d_out;

    cudaFuncSetAttribute(mma_gemm, cudaFuncAttributeMaxDynamicSharedMemorySize, GSMEM);
    cudaFuncSetAttribute(attn_kernel, cudaFuncAttributeMaxDynamicSharedMemorySize, ASM_BYTES);

    void *p;
    cudaGetSymbolAddress(&p, g_x);    float* x    = (float*)p;
    cudaGetSymbolAddress(&p, g_t2);   float* t2   = (float*)p;
    cudaGetSymbolAddress(&p, g_qkv);  float* qkv  = (float*)p;
    cudaGetSymbolAddress(&p, g_M);    float* Mb   = (float*)p;
    cudaGetSymbolAddress(&p, g_top);  int*   top  = (int*)p;
    cudaGetSymbolAddress(&p, g_sel);  int*   sel  = (int*)p;
    cudaGetSymbolAddress(&p, g_vme);  float* vme  = (float*)p;
    cudaGetSymbolAddress(&p, g_upd);  float* upd  = (float*)p;
    cudaGetSymbolAddress(&p, g_updp); float* updp = (float*)p;
    cudaGetSymbolAddress(&p, g_mlp);  float* mlp  = (float*)p;
    cudaGetSymbolAddress(&p, g_vsp);  float* vsp  = (float*)p;
    cudaGetSymbolAddress(&p, g_bnp);  float* bnp  = (float*)p;
    cudaGetSymbolAddress(&p, g_bns);  float* bns  = (float*)p;
    cudaGetSymbolAddress(&p, g_bqkv); float* bqkv = (float*)p;
    cudaGetSymbolAddress(&p, g_xh);   __nv_bfloat16* xh  = (__nv_bfloat16*)p;
    cudaGetSymbolAddress(&p, g_xl);   __nv_bfloat16* xl  = (__nv_bfloat16*)p;
    cudaGetSymbolAddress(&p, g_ch);   __nv_bfloat16* ch  = (__nv_bfloat16*)p;
    cudaGetSymbolAddress(&p, g_cl);   __nv_bfloat16* cl  = (__nv_bfloat16*)p;
    cudaGetSymbolAddress(&p, g_ffh);  __nv_bfloat16* ffh = (__nv_bfloat16*)p;
    cudaGetSymbolAddress(&p, g_ffl);  __nv_bfloat16* ffl = (__nv_bfloat16*)p;
    cudaGetSymbolAddress(&p, g_wh);   __nv_bfloat16* wh  = (__nv_bfloat16*)p;
    cudaGetSymbolAddress(&p, g_wl);   __nv_bfloat16* wl  = (__nv_bfloat16*)p;

    tok_conv_kernel<<<S0, 128>>>(x_enc, tok_w, x, xh, xl);

    int L = S0;
    for (int l = 0; l < ELAY; l++) {
        int U = (l == 0) ? 24 : 21;
        int u = U;
        int Mrows = BATCH * L;
        const float* Wq_l = Wq + (size_t)l * DMODEL * DMODEL;
        const float* Wk_l = Wk + (size_t)l * DMODEL * DMODEL;
        const float* Wv_l = Wv + (size_t)l * DMODEL * DMODEL;
        const float* Wo_l = Wo + (size_t)l * DMODEL * DMODEL;
        const float* w1_l = conv1_w + (size_t)l * DFF * DMODEL;
        const float* w2_l = conv2_w + (size_t)l * DMODEL * DFF;

        // fused QKV projection (N = 1536)
        concat_bias<<<6, 256>>>(bq + l * DMODEL, bk + l * DMODEL, bv + l * DMODEL, bqkv);
        cvt_qkv<<<(3 * DMODEL * DMODEL + 255) / 256, 256>>>(Wq_l, Wk_l, Wv_l, wh, wl);
        run_gemm(xh, xl, wh, wl, bqkv, 0, qkv, 0, 0, Mrows, QS, DMODEL, GF_WRF);

        // threefry key derivation (host)
        uint32_t ka, kb; threefry2x32(0u, 42u, 0u, (uint32_t)l, ka, kb);
        uint32_t k2a, k2b;
        threefry2x32(ka, kb, 0u, 1u, k2a, k2b);

        m2_kernel<<<BATCH * L / 8, 256>>>(qkv, k2a, k2b, Mb, L, U);
        topk_kernel<<<BATCH * NH, 1024>>>(Mb, top, L, u);
        clear_sel_kernel<<<(BATCH * NH * L + 255) / 256, 256>>>(sel, BATCH * NH * L);
        scatter_sel_kernel<<<(BATCH * NH * u + 255) / 256, 256>>>(top, sel, L, u);
        attn_kernel<<<dim3(NH, BATCH, ASPL), 256, ASM_BYTES>>>(qkv, top, updp, mlp, vsp, L, u);
        attn_merge_kernel<<<BATCH * NH, 256>>>(updp, mlp, vsp, upd, vme, L, u);
        assemble_ctx_kernel<<<(BATCH * L * DMODEL + 255) / 256, 256>>>(sel, upd, vme, ch, cl, L, u);

        // O projection + residual, LN1
        cvt_split<<<(DMODEL * DMODEL + 255) / 256, 256>>>(Wo_l, wh, wl, DMODEL * DMODEL);
        run_gemm(ch, cl, wh, wl, bo + l * DMODEL, x, t2, 0, 0, Mrows, DMODEL, DMODEL, GF_RES | GF_WRF);
        layernorm_kernel<<<Mrows, 128>>>(t2, ln1_g + l * DMODEL, ln1_b + l * DMODEL, x, xh, xl);

        // FFN
        cvt_split<<<(DFF * DMODEL + 255) / 256, 256>>>(w1_l, wh, wl, DFF * DMODEL);
        run_gemm(xh, xl, wh, wl, conv1_b + l * DFF, 0, 0, ffh, ffl, Mrows, DFF, DMODEL, GF_GELU | GF_SPLIT);
        cvt_split<<<(DMODEL * DFF + 255) / 256, 256>>>(w2_l, wh, wl, DMODEL * DFF);
        run_gemm(ffh, ffl, wh, wl, conv2_b + l * DMODEL, x, t2, 0, 0, Mrows, DMODEL, DFF, GF_RES | GF_WRF);
        layernorm_kernel<<<Mrows, 128>>>(t2, ln2_g + l * DMODEL, ln2_b + l * DMODEL, x, xh, xl);

        // distillation
        if (l < ELAY - 1) {
            const float* dw = dconv_w + (size_t)l * DMODEL * DMODEL * 3;
            cvt_dconv<<<(3 * DMODEL * DMODEL + 255) / 256, 256>>>(dw, wh, wl);
            run_gemm(xh, xl, wh, wl, dconv_b + l * DMODEL, 0, t2, 0, 0,
                     Mrows, DMODEL, DMODEL, GF_CIRC | GF_WRF, 3, L);
            bn_partial_kernel<<<64, DMODEL>>>(t2, bnp, Mrows / 64);
            bn_final_kernel<<<1, DMODEL>>>(bnp, bns, Mrows);
            bn_elu_maxpool_kernel<<<(BATCH * (L / 2) * DMODEL + 255) / 256, 256>>>(
                t2, bns, bn_g + l * DMODEL, bn_b + l * DMODEL, x, xh, xl, L);
            L /= 2;
        }
    }

    layernorm_kernel<<<BATCH * L, 128>>>(x, lnf_g, lnf_b, t2, 0, 0);
    head_kernel<<<(BATCH * L * NCOUT + 255) / 256, 256>>>(t2, end_w, end_b, out, BATCH * L);
}

// round 16
// speedup vs baseline: 1.6797x; 1.0120x over previous
#include <cuda_runtime.h>
#include <cuda_bf16.h>
#include <math.h>
#include <stdint.h>
#include <float.h>

#define BATCH 8
#define S0    2048
#define DMODEL 512
#define NH    8
#define HD    64
#define DFF   2048
#define ELAY  3
#define NCOUT 7
#define UMAX  24
#define QS    1536   // packed qkv row stride
#define ASPL  4      // attention KV splits

#define NQKV (3*DMODEL*DMODEL)     // 786432
#define NWO  (DMODEL*DMODEL)       // 262144
#define NW1  (DFF*DMODEL)          // 1048576
#define NW2  (DMODEL*DFF)          // 1048576
#define NDC  (3*DMODEL*DMODEL)     // 786432

// ------------------------- scratch (device globals) --------------------------
__device__ float g_x  [BATCH*S0*DMODEL];
__device__ float g_t2 [BATCH*S0*DMODEL];
__device__ float g_qkv[BATCH*S0*QS];
__device__ float g_M  [BATCH*NH*S0];
__device__ int   g_top[BATCH*NH*UMAX];
__device__ int   g_sel[BATCH*NH*S0];
__device__ float g_vme[BATCH*NH*HD];
__device__ float g_upd[BATCH*NH*UMAX*HD];
__device__ float g_updp[BATCH*NH*ASPL*UMAX*HD];
__device__ float g_mlp [BATCH*NH*ASPL*2*UMAX];
__device__ float g_vsp [BATCH*NH*ASPL*HD];
__device__ float g_bnp[64*DMODEL*2];
__device__ float g_bns[DMODEL*2];
__device__ float g_bqkv[QS];
__device__ __nv_bfloat16 g_xh [BATCH*S0*DMODEL];
__device__ __nv_bfloat16 g_xl [BATCH*S0*DMODEL];
__device__ __nv_bfloat16 g_ch [BATCH*S0*DMODEL];
__device__ __nv_bfloat16 g_cl [BATCH*S0*DMODEL];
__device__ __nv_bfloat16 g_ffh[BATCH*S0*DFF];
__device__ __nv_bfloat16 g_ffl[BATCH*S0*DFF];
__device__ __nv_bfloat16 g_qkh[NQKV], g_qkl[NQKV];
__device__ __nv_bfloat16 g_woh[NWO],  g_wol[NWO];
__device__ __nv_bfloat16 g_w1h[NW1],  g_w1l[NW1];
__device__ __nv_bfloat16 g_w2h[NW2],  g_w2l[NW2];
__device__ __nv_bfloat16 g_dch[NDC],  g_dcl[NDC];

// ------------------------- threefry2x32 --------------------------------------
__host__ __device__ __forceinline__ void tf_round(uint32_t& x0, uint32_t& x1, int r) {
    x0 += x1; x1 = (x1 << r) | (x1 >> (32 - r)); x1 ^= x0;
}
__host__ __device__ inline void threefry2x32(uint32_t k0, uint32_t k1,
                                             uint32_t c0, uint32_t c1,
                                             uint32_t& o0, uint32_t& o1) {
    uint32_t ks2 = k0 ^ k1 ^ 0x1BD11BDAu;
    uint32_t x0 = c0 + k0, x1 = c1 + k1;
    tf_round(x0,x1,13); tf_round(x0,x1,15); tf_round(x0,x1,26); tf_round(x0,x1,6);
    x0 += k1;  x1 += ks2 + 1u;
    tf_round(x0,x1,17); tf_round(x0,x1,29); tf_round(x0,x1,16); tf_round(x0,x1,24);
    x0 += ks2; x1 += k0 + 2u;
    tf_round(x0,x1,13); tf_round(x0,x1,15); tf_round(x0,x1,26); tf_round(x0,x1,6);
    x0 += k0;  x1 += k1 + 3u;
    tf_round(x0,x1,17); tf_round(x0,x1,29); tf_round(x0,x1,16); tf_round(x0,x1,24);
    x0 += k1;  x1 += ks2 + 4u;
    tf_round(x0,x1,13); tf_round(x0,x1,15); tf_round(x0,x1,26); tf_round(x0,x1,6);
    x0 += ks2; x1 += k0 + 5u;
    o0 = x0; o1 = x1;
}

// ------------------------- split helpers -------------------------------------
__device__ __forceinline__ void split_bf16(float v, __nv_bfloat16& h, __nv_bfloat16& l) {
    h = __float2bfloat16(v);
    l = __float2bfloat16(v - __bfloat162float(h));
}
// one kernel: all weight conversions for a layer (disjoint index regions)
__global__ void cvt_layer(const float* __restrict__ Wq, const float* __restrict__ Wk,
                          const float* __restrict__ Wv,
                          const float* __restrict__ bq, const float* __restrict__ bk,
                          const float* __restrict__ bv, float* __restrict__ bdst,
                          const float* __restrict__ Wo, const float* __restrict__ W1,
                          const float* __restrict__ W2, const float* __restrict__ DW,
                          __nv_bfloat16* __restrict__ qkh, __nv_bfloat16* __restrict__ qkl,
                          __nv_bfloat16* __restrict__ woh, __nv_bfloat16* __restrict__ wol,
                          __nv_bfloat16* __restrict__ w1h, __nv_bfloat16* __restrict__ w1l,
                          __nv_bfloat16* __restrict__ w2h, __nv_bfloat16* __restrict__ w2l,
                          __nv_bfloat16* __restrict__ dch, __nv_bfloat16* __restrict__ dcl,
                          int has_dc) {
    int i = blockIdx.x * 256 + threadIdx.x;
    if (i < QS)
        bdst[i] = (i < DMODEL) ? bq[i] : (i < 2 * DMODEL) ? bk[i - DMODEL] : bv[i - 2 * DMODEL];
    if (i < NQKV) {
        int r = i / DMODEL, c = i - r * DMODEL;
        const float* W = (r < DMODEL) ? Wq : (r < 2 * DMODEL) ? Wk : Wv;
        int rr = r & (DMODEL - 1);
        split_bf16(W[rr * DMODEL + c], qkh[i], qkl[i]);
        return;
    }
    int j = i - NQKV;
    if (j < NWO) { split_bf16(Wo[j], woh[j], wol[j]); return; }
    j -= NWO;
    if (j < NW1) { split_bf16(W1[j], w1h[j], w1l[j]); return; }
    j -= NW1;
    if (j < NW2) { split_bf16(W2[j], w2h[j], w2l[j]); return; }
    j -= NW2;
    if (has_dc && j < NDC) {
        int tap = j / (DMODEL * DMODEL);
        int r = j - tap * DMODEL * DMODEL;
        split_bf16(DW[(size_t)r * 3 + tap], dch[j], dcl[j]);
    }
}

// ------------------------- mma.sync GEMM (frozen) ----------------------------
#define GF_GELU   1
#define GF_RES    2
#define GF_CIRC   8
#define GF_WRF    32
#define GF_SPLIT  64

#define BM 128
#define BN 128
#define BK 32
#define SSTRIDE 40
#define TSZ (128 * SSTRIDE * 2)
#define STAGE_BYTES (4 * TSZ)
#define GSMEM (2 * STAGE_BYTES)

__device__ __forceinline__ void load_chunk2(
    const __nv_bfloat16* __restrict__ Ah, const __nv_bfloat16* __restrict__ Al,
    const __nv_bfloat16* __restrict__ Bh, const __nv_bfloat16* __restrict__ Bl,
    char* dynsm, int buf, int c, int nkc, int K, int N,
    int m0, int n0, int flags, int Lb, int tid)
{
    int tap = c / nkc;
    int kc = c - tap * nkc;
    int k0 = kc * BK;
    int shift = (flags & GF_CIRC) ? (tap - 1) : 0;
    char* st = dynsm + buf * STAGE_BYTES;
    const __nv_bfloat16* Bht = Bh + (size_t)tap * N * K;
    const __nv_bfloat16* Blt = Bl + (size_t)tap * N * K;
    #pragma unroll 2
    for (int i = tid; i < 512; i += 256) {
        int row = i >> 2, seg = i & 3;
        int gm = m0 + row, arow = gm;
        if (flags & GF_CIRC) {
            int b = gm / Lb, t = gm - b * Lb + shift;
            if (t < 0) t += Lb; else if (t >= Lb) t -= Lb;
            arow = b * Lb + t;
        }
        size_t so = (size_t)arow * K + k0 + seg * 8;
        uint32_t d = (uint32_t)__cvta_generic_to_shared(st + row * (SSTRIDE * 2) + seg * 16);
        asm volatile("cp.async.cg.shared.global [%0], [%1], 16;" :: "r"(d), "l"(Ah + so));
        asm volatile("cp.async.cg.shared.global [%0], [%1], 16;" :: "r"(d + TSZ), "l"(Al + so));
    }
    #pragma unroll 2
    for (int i = tid; i < 512; i += 256) {
        int row = i >> 2, seg = i & 3;
        size_t so = (size_t)(n0 + row) * K + k0 + seg * 8;
        uint32_t d = (uint32_t)__cvta_generic_to_shared(st + 2 * TSZ + row * (SSTRIDE * 2) + seg * 16);
        asm volatile("cp.async.cg.shared.global [%0], [%1], 16;" :: "r"(d), "l"(Bht + so));
        asm volatile("cp.async.cg.shared.global [%0], [%1], 16;" :: "r"(d + TSZ), "l"(Blt + so));
    }
    asm volatile("cp.async.commit_group;");
}

__global__ __launch_bounds__(256)
void mma_gemm(const __nv_bfloat16* __restrict__ Ah, const __nv_bfloat16* __restrict__ Al,
              const __nv_bfloat16* __restrict__ Bh, const __nv_bfloat16* __restrict__ Bl,
              const float* __restrict__ bias, const float* __restrict__ R,
              float* __restrict__ C, __nv_bfloat16* __restrict__ Ch, __nv_bfloat16* __restrict__ Cl,
              int M, int N, int K, int flags, int ntaps, int Lb)
{
    extern __shared__ __align__(16) char dynsm[];
    int tid = threadIdx.x, lane = tid & 31, wid = tid >> 5;
    int warp_m = wid & 1, warp_n = wid >> 1;
    int m0 = blockIdx.y * BM, n0 = blockIdx.x * BN;

    float acc[4][4][4];
    #pragma unroll
    for (int mi = 0; mi < 4; mi++)
        #pragma unroll
        for (int ni = 0; ni < 4; ni++)
            #pragma unroll
            for (int e = 0; e < 4; e++) acc[mi][ni][e] = 0.f;

    const int nkc = K / BK;
    const int nch = nkc * ntaps;

    load_chunk2(Ah, Al, Bh, Bl, dynsm, 0, 0, nkc, K, N, m0, n0, flags, Lb, tid);

    uint32_t smb = (uint32_t)__cvta_generic_to_shared(dynsm);
    int a_row = warp_m * 64 + (lane & 15);
    int a_col = (lane >> 4) * 8;
    int b_row = warp_n * 32 + (lane & 7) + ((lane >> 4) * 8);
    int b_col = ((lane >> 3) & 1) * 8;

    for (int c = 0; c < nch; c++) {
        if (c + 1 < nch) {
            load_chunk2(Ah, Al, Bh, Bl, dynsm, (c + 1) & 1, c + 1, nkc, K, N, m0, n0, flags, Lb, tid);
            asm volatile("cp.async.wait_group 1;");
        } else {
            asm volatile("cp.async.wait_group 0;");
        }
        __syncthreads();
        uint32_t ab = smb + (c & 1) * STAGE_BYTES;
        #pragma unroll
        for (int ks = 0; ks < 2; ks++) {
            uint32_t ah[4][4], al[4][4];
            #pragma unroll
            for (int mi = 0; mi < 4; mi++) {
                uint32_t addr = ab + ((a_row + mi * 16) * SSTRIDE + ks * 16 + a_col) * 2;
                asm volatile("ldmatrix.sync.aligned.m8n8.x4.shared.b16 {%0,%1,%2,%3}, [%4];"
                    : "=r"(ah[mi][0]), "=r"(ah[mi][1]), "=r"(ah[mi][2]), "=r"(ah[mi][3]) : "r"(addr));
                asm volatile("ldmatrix.sync.aligned.m8n8.x4.shared.b16 {%0,%1,%2,%3}, [%4];"
                    : "=r"(al[mi][0]), "=r"(al[mi][1]), "=r"(al[mi][2]), "=r"(al[mi][3]) : "r"(addr + TSZ));
            }
            uint32_t bh[4][2], bl[4][2];
            #pragma unroll
            for (int nf2 = 0; nf2 < 2; nf2++) {
                uint32_t r0, r1, r2, r3;
                uint32_t addr = ab + 2 * TSZ + ((b_row + nf2 * 16) * SSTRIDE + ks * 16 + b_col) * 2;
                asm volatile("ldmatrix.sync.aligned.m8n8.x4.shared.b16 {%0,%1,%2,%3}, [%4];"
                    : "=r"(r0), "=r"(r1), "=r"(r2), "=r"(r3) : "r"(addr));
                bh[nf2 * 2][0] = r0;     bh[nf2 * 2][1] = r1;
                bh[nf2 * 2 + 1][0] = r2; bh[nf2 * 2 + 1][1] = r3;
                asm volatile("ldmatrix.sync.aligned.m8n8.x4.shared.b16 {%0,%1,%2,%3}, [%4];"
                    : "=r"(r0), "=r"(r1), "=r"(r2), "=r"(r3) : "r"(addr + TSZ));
                bl[nf2 * 2][0] = r0;     bl[nf2 * 2][1] = r1;
                bl[nf2 * 2 + 1][0] = r2; bl[nf2 * 2 + 1][1] = r3;
            }
            #pragma unroll
            for (int mi = 0; mi < 4; mi++)
                #pragma unroll
                for (int ni = 0; ni < 4; ni++)
                    asm volatile("mma.sync.aligned.m16n8k16.row.col.f32.bf16.bf16.f32 "
                        "{%0,%1,%2,%3}, {%4,%5,%6,%7}, {%8,%9}, {%0,%1,%2,%3};"
                        : "+f"(acc[mi][ni][0]), "+f"(acc[mi][ni][1]), "+f"(acc[mi][ni][2]), "+f"(acc[mi][ni][3])
                        : "r"(ah[mi][0]), "r"(ah[mi][1]), "r"(ah[mi][2]), "r"(ah[mi][3]),
                          "r"(bh[ni][0]), "r"(bh[ni][1]));
            #pragma unroll
            for (int mi = 0; mi < 4; mi++)
                #pragma unroll
                for (int ni = 0; ni < 4; ni++)
                    asm volatile("mma.sync.aligned.m16n8k16.row.col.f32.bf16.bf16.f32 "
                        "{%0,%1,%2,%3}, {%4,%5,%6,%7}, {%8,%9}, {%0,%1,%2,%3};"
                        : "+f"(acc[mi][ni][0]), "+f"(acc[mi][ni][1]), "+f"(acc[mi][ni][2]), "+f"(acc[mi][ni][3])
                        : "r"(ah[mi][0]), "r"(ah[mi][1]), "r"(ah[mi][2]), "r"(ah[mi][3]),
                          "r"(bl[ni][0]), "r"(bl[ni][1]));
            #pragma unroll
            for (int mi = 0; mi < 4; mi++)
                #pragma unroll
                for (int ni = 0; ni < 4; ni++)
                    asm volatile("mma.sync.aligned.m16n8k16.row.col.f32.bf16.bf16.f32 "
                        "{%0,%1,%2,%3}, {%4,%5,%6,%7}, {%8,%9}, {%0,%1,%2,%3};"
                        : "+f"(acc[mi][ni][0]), "+f"(acc[mi][ni][1]), "+f"(acc[mi][ni][2]), "+f"(acc[mi][ni][3])
                        : "r"(al[mi][0]), "r"(al[mi][1]), "r"(al[mi][2]), "r"(al[mi][3]),
                          "r"(bh[ni][0]), "r"(bh[ni][1]));
        }
        __syncthreads();
    }

    // epilogue
    #pragma unroll
    for (int mi = 0; mi < 4; mi++) {
        #pragma unroll
        for (int ni = 0; ni < 4; ni++) {
            int gm0 = m0 + warp_m * 64 + mi * 16 + (lane >> 2);
            int gn  = n0 + warp_n * 32 + ni * 8 + (lane & 3) * 2;
            float2 bs = *(const float2*)&bias[gn];
            #pragma unroll
            for (int h = 0; h < 2; h++) {
                int gm = gm0 + h * 8;
                float2 v = make_float2(acc[mi][ni][h * 2], acc[mi][ni][h * 2 + 1]);
                v.x += bs.x; v.y += bs.y;
                if (flags & GF_GELU) {
                    v.x = 0.5f * v.x * (1.0f + erff(v.x * 0.7071067811865475f));
                    v.y = 0.5f * v.y * (1.0f + erff(v.y * 0.7071067811865475f));
                }
                if (flags & GF_RES) {
                    float2 rv = *(const float2*)&R[(size_t)gm * N + gn];
                    v.x += rv.x; v.y += rv.y;
                }
                if (flags & GF_WRF) *(float2*)&C[(size_t)gm * N + gn] = v;
                if (flags & GF_SPLIT) {
                    __nv_bfloat16 h0, l0, h1, l1;
                    split_bf16(v.x, h0, l0); split_bf16(v.y, h1, l1);
                    __nv_bfloat162 hv; hv.x = h0; hv.y = h1;
                    __nv_bfloat162 lv; lv.x = l0; lv.y = l1;
                    *(__nv_bfloat162*)&Ch[(size_t)gm * N + gn] = hv;
                    *(__nv_bfloat162*)&Cl[(size_t)gm * N + gn] = lv;
                }
            }
        }
    }
}

// ------------------------- token conv + positional embedding -----------------
__global__ void tok_conv_kernel(const float* __restrict__ xe, const float* __restrict__ w,
                                float* __restrict__ out, __nv_bfloat16* __restrict__ oh,
                                __nv_bfloat16* __restrict__ ol) {
    int t = blockIdx.x;
    __shared__ float xs[BATCH][21];
    int tid = threadIdx.x;
    for (int j = tid; j < BATCH * 21; j += 128) {
        int b = j / 21, jj = j % 21;
        int kk = jj / 7, i = jj % 7;
        int tt = t + kk - 1;
        if (tt < 0) tt += S0; else if (tt >= S0) tt -= S0;
        xs[b][kk * 7 + i] = xe[(size_t)(b * S0 + tt) * 7 + i];
    }
    __syncthreads();
    for (int o = tid; o < DMODEL; o += 128) {
        float wreg[21];
        const float* wo = w + o * 21;
        #pragma unroll
        for (int j = 0; j < 21; j++) wreg[j] = wo[j];
        int e = o & ~1;
        float dv = expf((float)e * -0.017988946038918563f);
        float ang = (float)t * dv;
        float pe = (o & 1) ? cosf(ang) : sinf(ang);
        #pragma unroll
        for (int b = 0; b < BATCH; b++) {
            float acc = pe;
            #pragma unroll
            for (int i = 0; i < 7; i++)
                #pragma unroll
                for (int kk = 0; kk < 3; kk++) acc += xs[b][kk * 7 + i] * wreg[i * 3 + kk];
            size_t oi = (size_t)(b * S0 + t) * DMODEL + o;
            out[oi] = acc;
            split_bf16(acc, oh[oi], ol[oi]);
        }
    }
}

// ------------------------- ProbSparse M: head-shared K rows (v2) -------------
__global__ void m2_kernel(const float* __restrict__ qkv, uint32_t ka, uint32_t kb,
                          float* __restrict__ Mo, int L, int U) {
    int wid = threadIdx.x >> 5, lane = threadIdx.x & 31;
    int gw = blockIdx.x * 8 + wid;
    int b = gw / L;
    int l = gw - b * L;
    const float4* qsrc = (const float4*)&qkv[(size_t)(b * L + l) * QS];
    const float4 q0 = qsrc[lane];
    const float4 q1 = qsrc[32 + lane];
    const float4 q2 = qsrc[64 + lane];
    const float4 q3 = qsrc[96 + lane];
    int hiHalf = lane >> 4;

    float mx[NH], sm[NH];
    #pragma unroll
    for (int h = 0; h < NH; h++) { mx[h] = -FLT_MAX; sm[h] = 0.f; }

    for (int s = 0; s < U; s++) {
        int j = l * U + s;
        uint32_t o0, o1;
        threefry2x32(ka, kb, 0u, (uint32_t)j, o0, o1);
        int kr = (int)((o0 ^ o1) & (uint32_t)(L - 1));
        const float4* ksrc = (const float4*)&qkv[(size_t)(b * L + kr) * QS + DMODEL];
        float4 k0 = ksrc[lane];
        float4 k1 = ksrc[32 + lane];
        float4 k2 = ksrc[64 + lane];
        float4 k3 = ksrc[96 + lane];
        float p0 = q0.x * k0.x + q0.y * k0.y + q0.z * k0.z + q0.w * k0.w;
        float p1 = q1.x * k1.x + q1.y * k1.y + q1.z * k1.z + q1.w * k1.w;
        float p2 = q2.x * k2.x + q2.y * k2.y + q2.z * k2.z + q2.w * k2.w;
        float p3 = q3.x * k3.x + q3.y * k3.y + q3.z * k3.z + q3.w * k3.w;
        #pragma unroll
        for (int off = 8; off; off >>= 1) {
            p0 += __shfl_xor_sync(0xffffffffu, p0, off);
            p1 += __shfl_xor_sync(0xffffffffu, p1, off);
            p2 += __shfl_xor_sync(0xffffffffu, p2, off);
            p3 += __shfl_xor_sync(0xffffffffu, p3, off);
        }
        float o0f = __shfl_xor_sync(0xffffffffu, p0, 16);
        float o1f = __shfl_xor_sync(0xffffffffu, p1, 16);
        float o2f = __shfl_xor_sync(0xffffffffu, p2, 16);
        float o3f = __shfl_xor_sync(0xffffffffu, p3, 16);
        float he0 = hiHalf ? o0f : p0;
        float ho0 = hiHalf ? p0 : o0f;
        float he1 = hiHalf ? o1f : p1;
        float ho1 = hiHalf ? p1 : o1f;
        float he2 = hiHalf ? o2f : p2;
        float ho2 = hiHalf ? p2 : o2f;
        float he3 = hiHalf ? o3f : p3;
        float ho3 = hiHalf ? p3 : o3f;
        mx[0] = fmaxf(mx[0], he0); sm[0] += he0;
        mx[1] = fmaxf(mx[1], ho0); sm[1] += ho0;
        mx[2] = fmaxf(mx[2], he1); sm[2] += he1;
        mx[3] = fmaxf(mx[3], ho1); sm[3] += ho1;
        mx[4] = fmaxf(mx[4], he2); sm[4] += he2;
        mx[5] = fmaxf(mx[5], ho2); sm[5] += ho2;
        mx[6] = fmaxf(mx[6], he3); sm[6] += he3;
        mx[7] = fmaxf(mx[7], ho3); sm[7] += ho3;
    }
    if (lane == 0) {
        #pragma unroll
        for (int h = 0; h < NH; h++)
            Mo[(b * NH + h) * L + l] = mx[h] - sm[h] / (float)L;
    }
}

__global__ void topk_kernel(const float* __restrict__ Mi, int* __restrict__ top,
                            int L, int u) {
    int bh = blockIdx.x, tid = threadIdx.x;
    int lane = tid & 31, warp = tid >> 5;
    __shared__ float sv[S0];
    __shared__ float wv[32];
    __shared__ int   wi[32];
    const float* m = Mi + (size_t)bh * L;
    for (int i = tid; i < L; i += 1024) sv[i] = m[i];
    __syncthreads();
    for (int it = 0; it < u; it++) {
        float best = -FLT_MAX; int besti = L;
        for (int i = tid; i < L; i += 1024) {
            float v = sv[i];
            if (v > best) { best = v; besti = i; }
        }
        #pragma unroll
        for (int off = 16; off; off >>= 1) {
            float ov = __shfl_xor_sync(0xffffffffu, best, off);
            int   oi = __shfl_xor_sync(0xffffffffu, besti, off);
            if (ov > best || (ov == best && oi < besti)) { best = ov; besti = oi; }
        }
        if (lane == 0) { wv[warp] = best; wi[warp] = besti; }
        __syncthreads();
        if (warp == 0) {
            best = wv[lane]; besti = wi[lane];
            #pragma unroll
            for (int off = 16; off; off >>= 1) {
                float ov = __shfl_xor_sync(0xffffffffu, best, off);
                int   oi = __shfl_xor_sync(0xffffffffu, besti, off);
                if (ov > best || (ov == best && oi < besti)) { best = ov; besti = oi; }
            }
            if (lane == 0) { top[bh * u + it] = besti; sv[besti] = -FLT_MAX; }
        }
        __syncthreads();
    }
}

__global__ void clear_sel_kernel(int* __restrict__ sel, int n) {
    int i = blockIdx.x * blockDim.x + threadIdx.x;
    if (i < n) sel[i] = 0;
}
__global__ void scatter_sel_kernel(const int* __restrict__ top, int* __restrict__ sel,
                                   int L, int u) {
    int i = blockIdx.x * blockDim.x + threadIdx.x;
    if (i >= BATCH * NH * u) return;
    int bh = i / u, ui = i % u;
    sel[(size_t)bh * L + top[bh * u + ui]] = ui + 1;
}

// ------------------------- split-KV flash attention + vmean ------------------
// PV phase uses float2 V loads: lane covers d = {2*lane, 2*lane+1}.
#define ATK 128
#define KSTR 68
#define ASM_FLOATS (2*ATK*KSTR + UMAX*ATK + 2*UMAX*HD + 2*UMAX + HD)
#define ASM_BYTES (ASM_FLOATS * 4)

__global__ void attn_kernel(const float* __restrict__ qkv, const int* __restrict__ top,
                            float* __restrict__ updp, float* __restrict__ mlp,
                            float* __restrict__ vsp, int L, int u) {
    extern __shared__ float sm[];
    float* Kt   = sm;
    float* Vt   = Kt + ATK * KSTR;
    float* sc   = Vt + ATK * KSTR;
    float* qs   = sc + UMAX * ATK;
    float* accs = qs + UMAX * HD;
    float* mst  = accs + UMAX * HD;
    float* lst  = mst + UMAX;
    float* vsum = lst + UMAX;
    int h = blockIdx.x, b = blockIdx.y, z = blockIdx.z;
    int bh = b * NH + h;
    int bhz = bh * ASPL + z;
    int Lc = L / ASPL;
    int tbase = z * Lc;
    int tid = threadIdx.x, lane = tid & 31, warp = tid >> 5;

    for (int i = tid; i < u * HD; i += 256) {
        int q = i >> 6, d = i & 63;
        int qrow = top[bh * u + q];
        qs[q * HD + d] = qkv[(size_t)(b * L + qrow) * QS + h * HD + d];
        accs[i] = 0.f;
    }
    if (tid < UMAX) { mst[tid] = -FLT_MAX; lst[tid] = 0.f; }
    if (tid < HD) vsum[tid] = 0.f;
    __syncthreads();

    for (int t0 = tbase; t0 < tbase + Lc; t0 += ATK) {
        for (int i = tid; i < ATK * 16; i += 256) {
            int row = i >> 4, seg = i & 15;
            const float* base = &qkv[(size_t)(b * L + t0 + row) * QS + DMODEL + h * HD + seg * 4];
            *(float4*)&Kt[row * KSTR + seg * 4] = *(const float4*)base;
            *(float4*)&Vt[row * KSTR + seg * 4] = *(const float4*)(base + DMODEL);
        }
        __syncthreads();
        if (tid < HD) {
            float s = 0.f;
            for (int k = 0; k < ATK; k++) s += Vt[k * KSTR + tid];
            vsum[tid] += s;
        }
        for (int i = tid; i < u * ATK; i += 256) {
            int q = i >> 7, k = i & (ATK - 1);
            const float* qp = &qs[q * HD];
            const float* kp = &Kt[k * KSTR];
            float acc = 0.f;
            #pragma unroll
            for (int d4 = 0; d4 < 16; d4++) {
                float4 a = *(const float4*)&qp[d4 * 4];
                float4 c = *(const float4*)&kp[d4 * 4];
                acc += a.x * c.x + a.y * c.y + a.z * c.z + a.w * c.w;
            }
            sc[q * ATK + k] = acc * 0.125f;
        }
        __syncthreads();
        #pragma unroll
        for (int qi = 0; qi < 3; qi++) {
            int q = warp * 3 + qi;
            if (q < u) {
                float s0 = sc[q * ATK + lane],      s1 = sc[q * ATK + 32 + lane];
                float s2 = sc[q * ATK + 64 + lane], s3 = sc[q * ATK + 96 + lane];
                float tm = fmaxf(fmaxf(s0, s1), fmaxf(s2, s3));
                #pragma unroll
                for (int off = 16; off; off >>= 1)
                    tm = fmaxf(tm, __shfl_xor_sync(0xffffffffu, tm, off));
                float mold = mst[q];
                float newm = fmaxf(mold, tm);
                float alpha = expf(mold - newm);
                float p0 = expf(s0 - newm), p1 = expf(s1 - newm);
                float p2 = expf(s2 - newm), p3 = expf(s3 - newm);
                sc[q * ATK + lane] = p0;      sc[q * ATK + 32 + lane] = p1;
                sc[q * ATK + 64 + lane] = p2; sc[q * ATK + 96 + lane] = p3;
                float ls = p0 + p1 + p2 + p3;
                #pragma unroll
                for (int off = 16; off; off >>= 1)
                    ls += __shfl_xor_sync(0xffffffffu, ls, off);
                if (lane == 0) { lst[q] = lst[q] * alpha + ls; mst[q] = newm; }
                __syncwarp();
                // PV: lane handles d = 2*lane, 2*lane+1 via one float2 V load
                int d0 = 2 * lane;
                float a0 = accs[q * HD + d0] * alpha;
                float a1 = accs[q * HD + d0 + 1] * alpha;
                for (int k = 0; k < ATK; k++) {
                    float s = sc[q * ATK + k];
                    float2 vv = *(const float2*)&Vt[k * KSTR + d0];
                    a0 += s * vv.x;
                    a1 += s * vv.y;
                }
                accs[q * HD + d0]     = a0;
                accs[q * HD + d0 + 1] = a1;
            }
        }
        __syncthreads();
    }
    #pragma unroll
    for (int qi = 0; qi < 3; qi++) {
        int q = warp * 3 + qi;
        if (q < u) {
            int d0 = 2 * lane;
            updp[((size_t)bhz * UMAX + q) * HD + d0]     = accs[q * HD + d0];
            updp[((size_t)bhz * UMAX + q) * HD + d0 + 1] = accs[q * HD + d0 + 1];
            if (lane == 0) {
                mlp[bhz * 2 * UMAX + q]        = mst[q];
                mlp[bhz * 2 * UMAX + UMAX + q] = lst[q];
            }
        }
    }
    if (tid < HD) vsp[bhz * HD + tid] = vsum[tid];
}

__global__ void attn_merge_kernel(const float* __restrict__ updp, const float* __restrict__ mlp,
                                  const float* __restrict__ vsp, float* __restrict__ upd,
                                  float* __restrict__ vme, int L, int u) {
    int bh = blockIdx.x, tid = threadIdx.x;
    for (int i = tid; i < u * HD; i += 256) {
        int q = i >> 6, d = i & 63;
        float M = -FLT_MAX;
        #pragma unroll
        for (int z = 0; z < ASPL; z++)
            M = fmaxf(M, mlp[(bh * ASPL + z) * 2 * UMAX + q]);
        float lsum = 0.f, asum = 0.f;
        #pragma unroll
        for (int z = 0; z < ASPL; z++) {
            int bhz = bh * ASPL + z;
            float w = expf(mlp[bhz * 2 * UMAX + q] - M);
            lsum += mlp[bhz * 2 * UMAX + UMAX + q] * w;
            asum += updp[((size_t)bhz * UMAX + q) * HD + d] * w;
        }
        upd[((size_t)bh * u + q) * HD + d] = asum / lsum;
    }
    if (tid < HD) {
        float s = 0.f;
        #pragma unroll
        for (int z = 0; z < ASPL; z++) s += vsp[(bh * ASPL + z) * HD + tid];
        vme[bh * HD + tid] = s / (float)L;
    }
}

__global__ void assemble_ctx_kernel(const int* __restrict__ sel, const float* __restrict__ upd,
                                    const float* __restrict__ vm,
                                    __nv_bfloat16* __restrict__ ch, __nv_bfloat16* __restrict__ cl,
                                    int L, int u) {
    int i = blockIdx.x * blockDim.x + threadIdx.x;
    int total = BATCH * L * DMODEL;
    if (i >= total) return;
    int b = i / (L * DMODEL);
    int r = i - b * L * DMODEL;
    int l = r / DMODEL;
    int c = r - l * DMODEL;
    int h = c / HD, d = c - h * HD;
    int bh = b * NH + h;
    int s = sel[(size_t)bh * L + l];
    float val = s ? upd[((size_t)bh * u + (s - 1)) * HD + d] : vm[bh * HD + d];
    split_bf16(val, ch[i], cl[i]);
}

// ------------------------- layernorm -----------------------------------------
__global__ void layernorm_kernel(const float* __restrict__ in, const float* __restrict__ g,
                                 const float* __restrict__ bb, float* __restrict__ out,
                                 __nv_bfloat16* __restrict__ oh, __nv_bfloat16* __restrict__ ol) {
    int row = blockIdx.x, tid = threadIdx.x;
    __shared__ float red[128];
    const float4 v = ((const float4*)(in + (size_t)row * DMODEL))[tid];
    red[tid] = v.x + v.y + v.z + v.w;
    __syncthreads();
    for (int s = 64; s > 0; s >>= 1) { if (tid < s) red[tid] += red[tid + s]; __syncthreads(); }
    float mean = red[0] / (float)DMODEL;
    __syncthreads();
    float dx = v.x - mean, dy = v.y - mean, dz = v.z - mean, dw = v.w - mean;
    red[tid] = dx * dx + dy * dy + dz * dz + dw * dw;
    __syncthreads();
    for (int s = 64; s > 0; s >>= 1) { if (tid < s) red[tid] += red[tid + s]; __syncthreads(); }
    float rstd = rsqrtf(red[0] / (float)DMODEL + 1e-5f);
    const float4 gv = ((const float4*)g)[tid];
    const float4 bv = ((const float4*)bb)[tid];
    float4 o;
    o.x = dx * rstd * gv.x + bv.x;
    o.y = dy * rstd * gv.y + bv.y;
    o.z = dz * rstd * gv.z + bv.z;
    o.w = dw * rstd * gv.w + bv.w;
    ((float4*)(out + (size_t)row * DMODEL))[tid] = o;
    if (oh) {
        size_t base = (size_t)row * DMODEL + tid * 4;
        split_bf16(o.x, oh[base],   ol[base]);
        split_bf16(o.y, oh[base+1], ol[base+1]);
        split_bf16(o.z, oh[base+2], ol[base+2]);
        split_bf16(o.w, oh[base+3], ol[base+3]);
    }
}

// ------------------------- distil helpers ------------------------------------
__global__ void bn_partial_kernel(const float* __restrict__ y, float* __restrict__ part, int rpc) {
    int chunk = blockIdx.x, c = threadIdx.x;
    float s = 0.f, ss = 0.f;
    for (int r = 0; r < rpc; r++) {
        float vv = y[(size_t)(chunk * rpc + r) * DMODEL + c];
        s += vv; ss += vv * vv;
    }
    part[(size_t)chunk * (2 * DMODEL) + c] = s;
    part[(size_t)chunk * (2 * DMODEL) + DMODEL + c] = ss;
}
__global__ void bn_final_kernel(const float* __restrict__ part, float* __restrict__ stat,
                                int Mtot) {
    int c = threadIdx.x;
    float s = 0.f, ss = 0.f;
    #pragma unroll 8
    for (int ch = 0; ch < 64; ch++) {
        s  += part[(size_t)ch * (2 * DMODEL) + c];
        ss += part[(size_t)ch * (2 * DMODEL) + DMODEL + c];
    }
    float mu = s / (float)Mtot;
    stat[c] = mu;
    stat[DMODEL + c] = ss / (float)Mtot - mu * mu;
}
__global__ void bn_elu_maxpool_kernel(const float* __restrict__ y, const float* __restrict__ stat,
                                      const float* __restrict__ g, const float* __restrict__ bb,
                                      float* __restrict__ out,
                                      __nv_bfloat16* __restrict__ oh, __nv_bfloat16* __restrict__ ol,
                                      int L) {
    int Lo = L / 2;
    int i = blockIdx.x * blockDim.x + threadIdx.x;
    int total = BATCH * Lo * DMODEL;
    if (i >= total) return;
    int b = i / (Lo * DMODEL);
    int r = i - b * Lo * DMODEL;
    int t = r / DMODEL;
    int c = r - t * DMODEL;
    float mu = stat[c];
    float rstd = rsqrtf(stat[DMODEL + c] + 1e-5f);
    float gc = g[c], bc = bb[c];
    float m = -FLT_MAX;
    #pragma unroll
    for (int dt = -1; dt <= 1; dt++) {
        int tt = 2 * t + dt;
        if (tt >= 0 && tt < L) {
            float z = (y[(size_t)(b * L + tt) * DMODEL + c] - mu) * rstd * gc + bc;
            z = z > 0.f ? z : expm1f(z);
            m = fmaxf(m, z);
        }
    }
    out[i] = m;
    split_bf16(m, oh[i], ol[i]);
}

// ------------------------- head ----------------------------------------------
__global__ void head_kernel(const float* __restrict__ x, const float* __restrict__ w,
                            const float* __restrict__ eb, float* __restrict__ out, int rows) {
    int i = blockIdx.x * blockDim.x + threadIdx.x;
    if (i >= rows * NCOUT) return;
    int row = i / NCOUT, c = i - row * NCOUT;
    const float* xr = x + (size_t)row * DMODEL;
    const float* wr = w + (size_t)c * DMODEL;
    float acc = eb[c];
    for (int d = 0; d < DMODEL; d++) acc += xr[d] * wr[d];
    out[i] = acc;
}

// ------------------------- host orchestration --------------------------------
static inline void run_gemm(const __nv_bfloat16* Ah, const __nv_bfloat16* Al,
                            const __nv_bfloat16* Bh, const __nv_bfloat16* Bl,
                            const float* bias, const float* R,
                            float* C, __nv_bfloat16* Ch, __nv_bfloat16* Cl,
                            int M, int N, int K, int flags, int ntaps = 1, int Lb = 1) {
    dim3 grid(N / BN, M / BM);
    mma_gemm<<<grid, 256, GSMEM>>>(Ah, Al, Bh, Bl, bias, R, C, Ch, Cl, M, N, K, flags, ntaps, Lb);
}

extern "C" void kernel_launch(void* const* d_in, const int* in_sizes, int n_in,
                              void* d_out, int out_size) {
    (void)in_sizes; (void)n_in; (void)out_size;
    const float* x_enc   = (const float*)d_in[0];
    const float* tok_w   = (const float*)d_in[1];
    const float* Wq      = (const float*)d_in[2];
    const float* bq      = (const float*)d_in[3];
    const float* Wk      = (const float*)d_in[4];
    const float* bk      = (const float*)d_in[5];
    const float* Wv      = (const float*)d_in[6];
    const float* bv      = (const float*)d_in[7];
    const float* Wo      = (const float*)d_in[8];
    const float* bo      = (const float*)d_in[9];
    const float* conv1_w = (const float*)d_in[10];
    const float* conv1_b = (const float*)d_in[11];
    const float* conv2_w = (const float*)d_in[12];
    const float* conv2_b = (const float*)d_in[13];
    const float* ln1_g   = (const float*)d_in[14];
    const float* ln1_b   = (const float*)d_in[15];
    const float* ln2_g   = (const float*)d_in[16];
    const float* ln2_b   = (const float*)d_in[17];
    const float* dconv_w = (const float*)d_in[18];
    const float* dconv_b = (const float*)d_in[19];
    const float* bn_g    = (const float*)d_in[20];
    const float* bn_b    = (const float*)d_in[21];
    const float* lnf_g   = (const float*)d_in[22];
    const float* lnf_b   = (const float*)d_in[23];
    const float* end_w   = (const float*)d_in[24];
    const float* end_b   = (const float*)d_in[25];
    float* out = (float*)d_out;

    cudaFuncSetAttribute(mma_gemm, cudaFuncAttributeMaxDynamicSharedMemorySize, GSMEM);
    cudaFuncSetAttribute(attn_kernel, cudaFuncAttributeMaxDynamicSharedMemorySize, ASM_BYTES);

    void *p;
    cudaGetSymbolAddress(&p, g_x);    float* x    = (float*)p;
    cudaGetSymbolAddress(&p, g_t2);   float* t2   = (float*)p;
    cudaGetSymbolAddress(&p, g_qkv);  float* qkv  = (float*)p;
    cudaGetSymbolAddress(&p, g_M);    float* Mb   = (float*)p;
    cudaGetSymbolAddress(&p, g_top);  int*   top  = (int*)p;
    cudaGetSymbolAddress(&p, g_sel);  int*   sel  = (int*)p;
    cudaGetSymbolAddress(&p, g_vme);  float* vme  = (float*)p;
    cudaGetSymbolAddress(&p, g_upd);  float* upd  = (float*)p;
    cudaGetSymbolAddress(&p, g_updp); float* updp = (float*)p;
    cudaGetSymbolAddress(&p, g_mlp);  float* mlp  = (float*)p;
    cudaGetSymbolAddress(&p, g_vsp);  float* vsp  = (float*)p;
    cudaGetSymbolAddress(&p, g_bnp);  float* bnp  = (float*)p;
    cudaGetSymbolAddress(&p, g_bns);  float* bns  = (float*)p;
    cudaGetSymbolAddress(&p, g_bqkv); float* bqkv = (float*)p;
    cudaGetSymbolAddress(&p, g_xh);   __nv_bfloat16* xh  = (__nv_bfloat16*)p;
    cudaGetSymbolAddress(&p, g_xl);   __nv_bfloat16* xl  = (__nv_bfloat16*)p;
    cudaGetSymbolAddress(&p, g_ch);   __nv_bfloat16* ch  = (__nv_bfloat16*)p;
    cudaGetSymbolAddress(&p, g_cl);   __nv_bfloat16* cl  = (__nv_bfloat16*)p;
    cudaGetSymbolAddress(&p, g_ffh);  __nv_bfloat16* ffh = (__nv_bfloat16*)p;
    cudaGetSymbolAddress(&p, g_ffl);  __nv_bfloat16* ffl = (__nv_bfloat16*)p;
    cudaGetSymbolAddress(&p, g_qkh);  __nv_bfloat16* qkh = (__nv_bfloat16*)p;
    cudaGetSymbolAddress(&p, g_qkl);  __nv_bfloat16* qkl = (__nv_bfloat16*)p;
    cudaGetSymbolAddress(&p, g_woh);  __nv_bfloat16* woh = (__nv_bfloat16*)p;
    cudaGetSymbolAddress(&p, g_wol);  __nv_bfloat16* wol = (__nv_bfloat16*)p;
    cudaGetSymbolAddress(&p, g_w1h);  __nv_bfloat16* w1h = (__nv_bfloat16*)p;
    cudaGetSymbolAddress(&p, g_w1l);  __nv_bfloat16* w1l = (__nv_bfloat16*)p;
    cudaGetSymbolAddress(&p, g_w2h);  __nv_bfloat16* w2h = (__nv_bfloat16*)p;
    cudaGetSymbolAddress(&p, g_w2l);  __nv_bfloat16* w2l = (__nv_bfloat16*)p;
    cudaGetSymbolAddress(&p, g_dch);  __nv_bfloat16* dch = (__nv_bfloat16*)p;
    cudaGetSymbolAddress(&p, g_dcl);  __nv_bfloat16* dcl = (__nv_bfloat16*)p;

    tok_conv_kernel<<<S0, 128>>>(x_enc, tok_w, x, xh, xl);

    int L = S0;
    for (int l = 0; l < ELAY; l++) {
        int U = (l == 0) ? 24 : 21;
        int u = U;
        int Mrows = BATCH * L;
        int has_dc = (l < ELAY - 1) ? 1 : 0;
        const float* Wq_l = Wq + (size_t)l * DMODEL * DMODEL;
        const float* Wk_l = Wk + (size_t)l * DMODEL * DMODEL;
        const float* Wv_l = Wv + (size_t)l * DMODEL * DMODEL;
        const float* Wo_l = Wo + (size_t)l * DMODEL * DMODEL;
        const float* w1_l = conv1_w + (size_t)l * DFF * DMODEL;
        const float* w2_l = conv2_w + (size_t)l * DMODEL * DFF;
        const float* dw_l = dconv_w + (size_t)l * DMODEL * DMODEL * 3;

        // all weight conversions for this layer in one launch
        int ntot = NQKV + NWO + NW1 + NW2 + (has_dc ? NDC : 0);
        cvt_layer<<<(ntot + 255) / 256, 256>>>(
            Wq_l, Wk_l, Wv_l, bq + l * DMODEL, bk + l * DMODEL, bv + l * DMODEL, bqkv,
            Wo_l, w1_l, w2_l, has_dc ? dw_l : Wo_l,
            qkh, qkl, woh, wol, w1h, w1l, w2h, w2l, dch, dcl, has_dc);

        // fused QKV projection (N = 1536)
        run_gemm(xh, xl, qkh, qkl, bqkv, 0, qkv, 0, 0, Mrows, QS, DMODEL, GF_WRF);

        // threefry key derivation (host)
        uint32_t ka, kb; threefry2x32(0u, 42u, 0u, (uint32_t)l, ka, kb);
        uint32_t k2a, k2b;
        threefry2x32(ka, kb, 0u, 1u, k2a, k2b);

        m2_kernel<<<BATCH * L / 8, 256>>>(qkv, k2a, k2b, Mb, L, U);
        topk_kernel<<<BATCH * NH, 1024>>>(Mb, top, L, u);
        clear_sel_kernel<<<(BATCH * NH * L + 255) / 256, 256>>>(sel, BATCH * NH * L);
        scatter_sel_kernel<<<(BATCH * NH * u + 255) / 256, 256>>>(top, sel, L, u);
        attn_kernel<<<dim3(NH, BATCH, ASPL), 256, ASM_BYTES>>>(qkv, top, updp, mlp, vsp, L, u);
        attn_merge_kernel<<<BATCH * NH, 256>>>(updp, mlp, vsp, upd, vme, L, u);
        assemble_ctx_kernel<<<(BATCH * L * DMODEL + 255) / 256, 256>>>(sel, upd, vme, ch, cl, L, u);

        // O projection + residual, LN1
        run_gemm(ch, cl, woh, wol, bo + l * DMODEL, x, t2, 0, 0, Mrows, DMODEL, DMODEL, GF_RES | GF_WRF);
        layernorm_kernel<<<Mrows, 128>>>(t2, ln1_g + l * DMODEL, ln1_b + l * DMODEL, x, xh, xl);

        // FFN
        run_gemm(xh, xl, w1h, w1l, conv1_b + l * DFF, 0, 0, ffh, ffl, Mrows, DFF, DMODEL, GF_GELU | GF_SPLIT);
        run_gemm(ffh, ffl, w2h, w2l, conv2_b + l * DMODEL, x, t2, 0, 0, Mrows, DMODEL, DFF, GF_RES | GF_WRF);
        layernorm_kernel<<<Mrows, 128>>>(t2, ln2_g + l * DMODEL, ln2_b + l * DMODEL, x, xh, xl);

        // distillation
        if (has_dc) {
            run_gemm(xh, xl, dch, dcl, dconv_b + l * DMODEL, 0, t2, 0, 0,
                     Mrows, DMODEL, DMODEL, GF_CIRC | GF_WRF, 3, L);
            bn_partial_kernel<<<64, DMODEL>>>(t2, bnp, Mrows / 64);
            bn_final_kernel<<<1, DMODEL>>>(bnp, bns, Mrows);
            bn_elu_maxpool_kernel<<<(BATCH * (L / 2) * DMODEL + 255) / 256, 256>>>(
                t2, bns, bn_g + l * DMODEL, bn_b + l * DMODEL, x, xh, xl, L);
            L /= 2;
        }
    }

    layernorm_kernel<<<BATCH * L, 128>>>(x, lnf_g, lnf_b, t2, 0, 0);
    head_kernel<<<(BATCH * L * NCOUT + 255) / 256, 256>>>(t2, end_w, end_b, out, BATCH * L);
}